// round 6
// baseline (speedup 1.0000x reference)
#include <cuda_runtime.h>
#include <cuda_bf16.h>
#include <math.h>
#include <stdint.h>

#define B_    4
#define S_    2048
#define DM    1024
#define NH    16
#define DK    64
#define INNER 1024

// ---------------- scratch (static device globals; no allocation) ----------------
__device__ __align__(256) float g_q[(size_t)B_ * NH * S_ * DK];
__device__ __align__(256) __nv_bfloat16 g_khi[(size_t)B_ * NH * S_ * DK];
__device__ __align__(256) __nv_bfloat16 g_klo[(size_t)B_ * NH * S_ * DK];
__device__ __align__(256) __nv_bfloat16 g_vthi[(size_t)B_ * NH * DK * S_];
__device__ __align__(256) __nv_bfloat16 g_vtlo[(size_t)B_ * NH * DK * S_];
__device__ __align__(256) __nv_bfloat16 g_ctxhi[(size_t)B_ * S_ * INNER];
__device__ __align__(256) __nv_bfloat16 g_ctxlo[(size_t)B_ * S_ * INNER];
__device__ __align__(256) __nv_bfloat16 g_hidhi[(size_t)B_ * S_ * DM];
__device__ __align__(256) __nv_bfloat16 g_hidlo[(size_t)B_ * S_ * DM];
__device__ __align__(256) __nv_bfloat16 g_wqhi[(size_t)DM * DM], g_wqlo[(size_t)DM * DM];
__device__ __align__(256) __nv_bfloat16 g_wkhi[(size_t)DM * DM], g_wklo[(size_t)DM * DM];
__device__ __align__(256) __nv_bfloat16 g_wvhi[(size_t)DM * DM], g_wvlo[(size_t)DM * DM];
__device__ __align__(256) __nv_bfloat16 g_wohi[(size_t)DM * DM], g_wolo[(size_t)DM * DM];
__device__ unsigned char g_bucket[(size_t)B_ * S_ * S_];
__device__ unsigned char g_lutb[256];

// ================= helpers =================
__device__ __forceinline__ void mma16816(float* c, const uint32_t* a, const uint32_t* b) {
    asm volatile(
        "mma.sync.aligned.m16n8k16.row.col.f32.bf16.bf16.f32 "
        "{%0,%1,%2,%3}, {%4,%5,%6,%7}, {%8,%9}, {%0,%1,%2,%3};\n"
        : "+f"(c[0]), "+f"(c[1]), "+f"(c[2]), "+f"(c[3])
        : "r"(a[0]), "r"(a[1]), "r"(a[2]), "r"(a[3]), "r"(b[0]), "r"(b[1]));
}

__device__ __forceinline__ void ldm4(uint32_t* r, uint32_t a) {
    asm volatile("ldmatrix.sync.aligned.m8n8.x4.shared.b16 {%0,%1,%2,%3}, [%4];"
                 : "=r"(r[0]), "=r"(r[1]), "=r"(r[2]), "=r"(r[3]) : "r"(a));
}

__device__ __forceinline__ void split2(float x, float y, uint32_t& hi, uint32_t& lo) {
    __nv_bfloat162 h = __floats2bfloat162_rn(x, y);
    float rx = x - __bfloat162float(h.x);
    float ry = y - __bfloat162float(h.y);
    __nv_bfloat162 l = __floats2bfloat162_rn(rx, ry);
    hi = *(uint32_t*)&h;
    lo = *(uint32_t*)&l;
}

__device__ __forceinline__ uint32_t smem_u32(const void* p) {
    uint32_t a;
    asm("{ .reg .u64 t; cvta.to.shared.u64 t, %1; cvt.u32.u64 %0, t; }" : "=r"(a) : "l"(p));
    return a;
}
__device__ __forceinline__ void cp16(uint32_t dst, const void* src) {
    asm volatile("cp.async.ca.shared.global [%0], [%1], 16;" :: "r"(dst), "l"(src) : "memory");
}
#define CP_COMMIT() asm volatile("cp.async.commit_group;" ::: "memory")
#define CP_WAIT1()  asm volatile("cp.async.wait_group 1;" ::: "memory")
#define CP_WAIT0()  asm volatile("cp.async.wait_group 0;" ::: "memory")

// ================= bucket LUT + bucket =================
__global__ void lut_kernel() {
    int rp = threadIdx.x;
    int bucket;
    if (rp < 8) {
        bucket = rp;
    } else {
        float v = logf((float)rp * 0.125f);
        v = v / 2.772588722239781f;
        v = v * 8.0f;
        bucket = 8 + (int)v;
        bucket = bucket < 15 ? bucket : 15;
    }
    g_lutb[rp] = (unsigned char)bucket;
}

__global__ void bucket_kernel(const int* __restrict__ pos) {
    int idx = blockIdx.x * blockDim.x + threadIdx.x;
    if (idx >= B_ * S_ * S_) return;
    int k = idx & (S_ - 1);
    int q = (idx >> 11) & (S_ - 1);
    int b = idx >> 22;
    int rel = pos[b * S_ + k] - pos[b * S_ + q];
    int ret = (rel > 0) ? 16 : 0;
    int rp = rel < 0 ? -rel : rel;
    int bucket = g_lutb[rp < 256 ? rp : 255];
    g_bucket[idx] = (unsigned char)(ret + bucket);
}

// ================= pre-split fp32 -> hi/lo bf16 =================
__global__ void presplit_kernel(const float4* __restrict__ src,
                                uint2* __restrict__ hi, uint2* __restrict__ lo, int n4) {
    int i = blockIdx.x * blockDim.x + threadIdx.x;
    if (i >= n4) return;
    float4 v = src[i];
    uint32_t h0, l0, h1, l1;
    split2(v.x, v.y, h0, l0);
    split2(v.z, v.w, h1, l1);
    uint2 uh = {h0, h1}, ul = {l0, l1};
    hi[i] = uh;
    lo[i] = ul;
}

// ================= bf16 double-buffered GEMM, 512 thr, ldmatrix =================
// C[M,N] = A @ B^T, block 128x128, 16 warps (4m x 4n), warp tile 32x32.
#define RS 80
#define SA_HI 0
#define SA_LO 10240
#define SB_HI 20480
#define SB_LO 30720
#define STAGE 40960
#define GDSMEM (2 * STAGE)

__device__ __forceinline__ void gemm_stage(int c, uint32_t bufo, uint32_t sb,
                                           const __nv_bfloat16* Ahi, const __nv_bfloat16* Alo,
                                           const __nv_bfloat16* Bhi, const __nv_bfloat16* Blo,
                                           int m0, int n0, int tid) {
    int k0 = c * 32;
    int row = tid >> 2, q = tid & 3;
    size_t ga = (size_t)(m0 + row) * DM + k0 + q * 8;
    size_t gb = (size_t)(n0 + row) * DM + k0 + q * 8;
    uint32_t so = sb + bufo + row * RS + q * 16;
    cp16(so + SA_HI, Ahi + ga);
    cp16(so + SA_LO, Alo + ga);
    cp16(so + SB_HI, Bhi + gb);
    cp16(so + SB_LO, Blo + gb);
    CP_COMMIT();
}

__device__ __forceinline__ void gemm_core(const __nv_bfloat16* Ahi, const __nv_bfloat16* Alo,
                                          const __nv_bfloat16* Bhi, const __nv_bfloat16* Blo,
                                          int m0, int n0, float acc[2][4][4], char* smem) {
    uint32_t sb = smem_u32(smem);
    int tid = threadIdx.x, lane = tid & 31, wid = tid >> 5;
    int wm = wid >> 2, wn = wid & 3;

    // ldmatrix per-thread offsets
    // A (16x16): row = wm*32 + mt*16 + (lane&15), colb = (lane>>4)*16
    uint32_t aoff = (uint32_t)(wm * 32 + (lane & 15)) * RS + (lane >> 4) * 16;
    // B pair p (nt=2p,2p+1): row = wn*32 + p*16 + ((lane>>4)&1)*8 + (lane&7), colb = ((lane>>3)&1)*16
    uint32_t boff = (uint32_t)(wn * 32 + ((lane >> 4) & 1) * 8 + (lane & 7)) * RS + ((lane >> 3) & 1) * 16;

    gemm_stage(0, 0, sb, Ahi, Alo, Bhi, Blo, m0, n0, tid);
    gemm_stage(1, STAGE, sb, Ahi, Alo, Bhi, Blo, m0, n0, tid);

    #pragma unroll 1
    for (int c = 0; c < 32; c++) {
        uint32_t bufo = (c & 1) * STAGE;
        if (c < 31) CP_WAIT1(); else CP_WAIT0();
        __syncthreads();
        uint32_t base = sb + bufo;
        #pragma unroll
        for (int kk = 0; kk < 2; kk++) {
            uint32_t ka = kk * 32;
            uint32_t bh[4][2], bl[4][2];
            {
                uint32_t r[4];
                ldm4(r, base + SB_HI + boff + ka);
                bh[0][0] = r[0]; bh[0][1] = r[1]; bh[1][0] = r[2]; bh[1][1] = r[3];
                ldm4(r, base + SB_HI + boff + 16 * RS + ka);
                bh[2][0] = r[0]; bh[2][1] = r[1]; bh[3][0] = r[2]; bh[3][1] = r[3];
                ldm4(r, base + SB_LO + boff + ka);
                bl[0][0] = r[0]; bl[0][1] = r[1]; bl[1][0] = r[2]; bl[1][1] = r[3];
                ldm4(r, base + SB_LO + boff + 16 * RS + ka);
                bl[2][0] = r[0]; bl[2][1] = r[1]; bl[3][0] = r[2]; bl[3][1] = r[3];
            }
            uint32_t ah[2][4], al[2][4];
            ldm4(ah[0], base + SA_HI + aoff + ka);
            ldm4(ah[1], base + SA_HI + aoff + 16 * RS + ka);
            ldm4(al[0], base + SA_LO + aoff + ka);
            ldm4(al[1], base + SA_LO + aoff + 16 * RS + ka);
            #pragma unroll
            for (int mt = 0; mt < 2; mt++)
                #pragma unroll
                for (int nt = 0; nt < 4; nt++) {
                    mma16816(acc[mt][nt], ah[mt], bh[nt]);
                    mma16816(acc[mt][nt], al[mt], bh[nt]);
                    mma16816(acc[mt][nt], ah[mt], bl[nt]);
                }
        }
        __syncthreads();
        if (c + 2 < 32) gemm_stage(c + 2, bufo, sb, Ahi, Alo, Bhi, Blo, m0, n0, tid);
    }
}

// QKV projection. grid (24, 64), 512 thr
__global__ __launch_bounds__(512) void proj_mma() {
    extern __shared__ char smem[];
    int bx = blockIdx.x;
    int wsel = bx >> 3;
    int n0 = (bx & 7) * 128;
    int m0 = blockIdx.y * 128;
    const __nv_bfloat16* Bh = (wsel == 0) ? g_wqhi : (wsel == 1) ? g_wkhi : g_wvhi;
    const __nv_bfloat16* Bl = (wsel == 0) ? g_wqlo : (wsel == 1) ? g_wklo : g_wvlo;

    float acc[2][4][4] = {};
    gemm_core(g_hidhi, g_hidlo, Bh, Bl, m0, n0, acc, smem);

    int lane = threadIdx.x & 31, wid = threadIdx.x >> 5;
    int wm = wid >> 2, wn = wid & 3;
    int g = lane >> 2, tg = lane & 3;
    #pragma unroll
    for (int mt = 0; mt < 2; mt++) {
        #pragma unroll
        for (int nt = 0; nt < 4; nt++) {
            int r0 = m0 + wm * 32 + mt * 16 + g;
            int r1 = r0 + 8;
            int c = n0 + wn * 32 + nt * 8 + tg * 2;
            int h = c >> 6, d = c & 63;
            int b0 = r0 >> 11, s0 = r0 & (S_ - 1);
            int b1 = r1 >> 11, s1 = r1 & (S_ - 1);
            float a0 = acc[mt][nt][0], a1 = acc[mt][nt][1];
            float a2 = acc[mt][nt][2], a3 = acc[mt][nt][3];
            if (wsel == 0) {
                float2 v0 = {a0, a1};
                *(float2*)&g_q[(((size_t)(b0 * NH + h) * S_ + s0) << 6) + d] = v0;
                float2 v1 = {a2, a3};
                *(float2*)&g_q[(((size_t)(b1 * NH + h) * S_ + s1) << 6) + d] = v1;
            } else if (wsel == 1) {
                uint32_t h0, l0, h1, l1;
                split2(a0, a1, h0, l0);
                split2(a2, a3, h1, l1);
                size_t o0 = (((size_t)(b0 * NH + h) * S_ + s0) << 6) + d;
                size_t o1 = (((size_t)(b1 * NH + h) * S_ + s1) << 6) + d;
                *(uint32_t*)&g_khi[o0] = h0; *(uint32_t*)&g_klo[o0] = l0;
                *(uint32_t*)&g_khi[o1] = h1; *(uint32_t*)&g_klo[o1] = l1;
            } else {
                size_t base0 = ((size_t)(b0 * NH + h) * DK + d) * S_;
                size_t base1 = ((size_t)(b1 * NH + h) * DK + d) * S_;
                #pragma unroll
                for (int e = 0; e < 4; e++) {
                    float x = acc[mt][nt][e];
                    __nv_bfloat16 hh = __float2bfloat16(x);
                    __nv_bfloat16 ll = __float2bfloat16(x - __bfloat162float(hh));
                    size_t o = (e < 2 ? base0 + s0 : base1 + s1) + (size_t)(e & 1) * S_;
                    g_vthi[o] = hh;
                    g_vtlo[o] = ll;
                }
            }
        }
    }
}

// output projection. grid (8, 64), 512 thr
__global__ __launch_bounds__(512) void outproj_mma(float* __restrict__ out) {
    extern __shared__ char smem[];
    int n0 = blockIdx.x * 128;
    int m0 = blockIdx.y * 128;

    float acc[2][4][4] = {};
    gemm_core(g_ctxhi, g_ctxlo, g_wohi, g_wolo, m0, n0, acc, smem);

    int lane = threadIdx.x & 31, wid = threadIdx.x >> 5;
    int wm = wid >> 2, wn = wid & 3;
    int g = lane >> 2, tg = lane & 3;
    #pragma unroll
    for (int mt = 0; mt < 2; mt++) {
        #pragma unroll
        for (int nt = 0; nt < 4; nt++) {
            int r0 = m0 + wm * 32 + mt * 16 + g;
            int c = n0 + wn * 32 + nt * 8 + tg * 2;
            float2 v0 = {acc[mt][nt][0], acc[mt][nt][1]};
            *(float2*)&out[(size_t)r0 * DM + c] = v0;
            float2 v1 = {acc[mt][nt][2], acc[mt][nt][3]};
            *(float2*)&out[(size_t)(r0 + 8) * DM + c] = v1;
        }
    }
}

// ================= tensor-core flash attention, 256 thr, q-tile 128, ldmatrix ======
#define KROWB 144
#define AT_KHI 0
#define AT_KLO 9216
#define AT_VTH 18432
#define AT_VTL 27648
#define ATSTAGE 36864
#define AT_MCL (2 * ATSTAGE)
#define AT_RBH (AT_MCL + 512)
#define AT_DSMEM (AT_RBH + 128)

__global__ __launch_bounds__(256) void attn_mma(const float* __restrict__ rel_bias,
                                                const float* __restrict__ mask) {
    extern __shared__ char sm[];
    float* rbh = (float*)(sm + AT_RBH);
    uint32_t sb = smem_u32(sm);

    int tid = threadIdx.x, lane = tid & 31, wrp = tid >> 5;
    int g = lane >> 2, tg = lane & 3;
    int q0 = blockIdx.x * 128, h = blockIdx.y, b = blockIdx.z;

    const __nv_bfloat16* khi = g_khi + (size_t)(b * NH + h) * S_ * DK;
    const __nv_bfloat16* klo = g_klo + (size_t)(b * NH + h) * S_ * DK;
    const __nv_bfloat16* vth = g_vthi + (size_t)(b * NH + h) * DK * S_;
    const __nv_bfloat16* vtl = g_vtlo + (size_t)(b * NH + h) * DK * S_;
    const float* maskp = mask + b * S_;

    if (tid < 32) rbh[tid] = rel_bias[tid * NH + h];

    auto stage = [&](int i) {
        int k0 = i * 64;
        uint32_t bufo = (i & 1) * ATSTAGE;
        #pragma unroll
        for (int j = 0; j < 2; j++) {
            int idx = tid + j * 256;
            int r = idx >> 3, q = idx & 7;
            uint32_t so = sb + bufo + r * KROWB + q * 16;
            cp16(so + AT_KHI, khi + (size_t)(k0 + r) * DK + q * 8);
            cp16(so + AT_KLO, klo + (size_t)(k0 + r) * DK + q * 8);
            cp16(so + AT_VTH, vth + (size_t)r * S_ + k0 + q * 8);
            cp16(so + AT_VTL, vtl + (size_t)r * S_ + k0 + q * 8);
        }
        if (tid < 16) cp16(sb + AT_MCL + (i & 1) * 256 + tid * 16, maskp + k0 + tid * 4);
        CP_COMMIT();
    };

    // Q fragments (hi/lo) in registers
    int r0 = q0 + wrp * 16 + g;
    const float* qp = g_q + ((size_t)(b * NH + h) * S_ + r0) * DK;
    uint32_t qh[4][4], ql[4][4];
    #pragma unroll
    for (int kc = 0; kc < 4; kc++) {
        int c = kc * 16 + 2 * tg;
        float2 v00 = *(const float2*)&qp[c];
        float2 v10 = *(const float2*)&qp[8 * DK + c];
        float2 v01 = *(const float2*)&qp[c + 8];
        float2 v11 = *(const float2*)&qp[8 * DK + c + 8];
        split2(v00.x, v00.y, qh[kc][0], ql[kc][0]);
        split2(v10.x, v10.y, qh[kc][1], ql[kc][1]);
        split2(v01.x, v01.y, qh[kc][2], ql[kc][2]);
        split2(v11.x, v11.y, qh[kc][3], ql[kc][3]);
    }

    const unsigned char* bk0 = g_bucket + ((size_t)b * S_ + r0) * S_;
    const unsigned char* bk1 = bk0 + 8 * (size_t)S_;

    // ldmatrix per-thread offset for K/V (B-operand pairs)
    uint32_t koff = (uint32_t)(((lane >> 4) & 1) * 8 + (lane & 7)) * KROWB + ((lane >> 3) & 1) * 16;

    float o[8][4] = {};
    float m0 = -1e30f, m1 = -1e30f, l0 = 0.f, l1 = 0.f;

    stage(0);
    stage(1);

    #pragma unroll 1
    for (int i = 0; i < 32; i++) {
        int k0 = i * 64;
        uint32_t bufo = (i & 1) * ATSTAGE;
        if (i < 31) CP_WAIT1(); else CP_WAIT0();
        __syncthreads();
        uint32_t base = sb + bufo;
        const float* mclf = (const float*)(sm + AT_MCL + (i & 1) * 256);

        // ---- S = Q @ K^T ----
        float s[8][4] = {};
        #pragma unroll
        for (int kc = 0; kc < 4; kc++) {
            uint32_t ka = kc * 32;
            uint32_t bh[8][2], bl[8][2];
            #pragma unroll
            for (int p = 0; p < 4; p++) {
                uint32_t r[4];
                ldm4(r, base + AT_KHI + koff + p * 16 * KROWB + ka);
                bh[2 * p][0] = r[0]; bh[2 * p][1] = r[1];
                bh[2 * p + 1][0] = r[2]; bh[2 * p + 1][1] = r[3];
                ldm4(r, base + AT_KLO + koff + p * 16 * KROWB + ka);
                bl[2 * p][0] = r[0]; bl[2 * p][1] = r[1];
                bl[2 * p + 1][0] = r[2]; bl[2 * p + 1][1] = r[3];
            }
            #pragma unroll
            for (int nt = 0; nt < 8; nt++) {
                mma16816(s[nt], qh[kc], bh[nt]);
                mma16816(s[nt], ql[kc], bh[nt]);
                mma16816(s[nt], qh[kc], bl[nt]);
            }
        }

        // ---- bias ----
        #pragma unroll
        for (int nt = 0; nt < 8; nt++) {
            int col = k0 + nt * 8 + 2 * tg;
            uchar2 u0 = *(const uchar2*)(bk0 + col);
            uchar2 u1 = *(const uchar2*)(bk1 + col);
            float mv0 = mclf[nt * 8 + 2 * tg], mv1 = mclf[nt * 8 + 2 * tg + 1];
            float mc0 = -1000.0f + 1000.0f * mv0;
            float mc1 = -1000.0f + 1000.0f * mv1;
            s[nt][0] += rbh[u0.x] + mc0;
            s[nt][1] += rbh[u0.y] + mc1;
            s[nt][2] += rbh[u1.x] + mc0;
            s[nt][3] += rbh[u1.y] + mc1;
        }

        // ---- online softmax ----
        float rm0 = -1e30f, rm1 = -1e30f;
        #pragma unroll
        for (int nt = 0; nt < 8; nt++) {
            rm0 = fmaxf(rm0, fmaxf(s[nt][0], s[nt][1]));
            rm1 = fmaxf(rm1, fmaxf(s[nt][2], s[nt][3]));
        }
        rm0 = fmaxf(rm0, __shfl_xor_sync(0xffffffffu, rm0, 1));
        rm0 = fmaxf(rm0, __shfl_xor_sync(0xffffffffu, rm0, 2));
        rm1 = fmaxf(rm1, __shfl_xor_sync(0xffffffffu, rm1, 1));
        rm1 = fmaxf(rm1, __shfl_xor_sync(0xffffffffu, rm1, 2));
        float mn0 = fmaxf(m0, rm0), mn1 = fmaxf(m1, rm1);
        float fac0 = __expf(m0 - mn0), fac1 = __expf(m1 - mn1);
        m0 = mn0; m1 = mn1;
        float rs0 = 0.f, rs1 = 0.f;
        #pragma unroll
        for (int nt = 0; nt < 8; nt++) {
            s[nt][0] = __expf(s[nt][0] - mn0);
            s[nt][1] = __expf(s[nt][1] - mn0);
            s[nt][2] = __expf(s[nt][2] - mn1);
            s[nt][3] = __expf(s[nt][3] - mn1);
            rs0 += s[nt][0] + s[nt][1];
            rs1 += s[nt][2] + s[nt][3];
        }
        rs0 += __shfl_xor_sync(0xffffffffu, rs0, 1);
        rs0 += __shfl_xor_sync(0xffffffffu, rs0, 2);
        rs1 += __shfl_xor_sync(0xffffffffu, rs1, 1);
        rs1 += __shfl_xor_sync(0xffffffffu, rs1, 2);
        l0 = l0 * fac0 + rs0;
        l1 = l1 * fac1 + rs1;
        #pragma unroll
        for (int dt = 0; dt < 8; dt++) {
            o[dt][0] *= fac0; o[dt][1] *= fac0;
            o[dt][2] *= fac1; o[dt][3] *= fac1;
        }

        // ---- O += P @ V ----
        #pragma unroll
        for (int kc = 0; kc < 4; kc++) {
            uint32_t ah[4], al[4];
            split2(s[2 * kc][0],     s[2 * kc][1],     ah[0], al[0]);
            split2(s[2 * kc][2],     s[2 * kc][3],     ah[1], al[1]);
            split2(s[2 * kc + 1][0], s[2 * kc + 1][1], ah[2], al[2]);
            split2(s[2 * kc + 1][2], s[2 * kc + 1][3], ah[3], al[3]);
            uint32_t ka = kc * 32;
            uint32_t bh[8][2], bl[8][2];
            #pragma unroll
            for (int p = 0; p < 4; p++) {
                uint32_t r[4];
                ldm4(r, base + AT_VTH + koff + p * 16 * KROWB + ka);
                bh[2 * p][0] = r[0]; bh[2 * p][1] = r[1];
                bh[2 * p + 1][0] = r[2]; bh[2 * p + 1][1] = r[3];
                ldm4(r, base + AT_VTL + koff + p * 16 * KROWB + ka);
                bl[2 * p][0] = r[0]; bl[2 * p][1] = r[1];
                bl[2 * p + 1][0] = r[2]; bl[2 * p + 1][1] = r[3];
            }
            #pragma unroll
            for (int dt = 0; dt < 8; dt++) {
                mma16816(o[dt], ah, bh[dt]);
                mma16816(o[dt], al, bh[dt]);
                mma16816(o[dt], ah, bl[dt]);
            }
        }
        __syncthreads();
        if (i + 2 < 32) stage(i + 2);
    }

    // ---- epilogue ----
    float inv0 = 1.0f / l0, inv1 = 1.0f / l1;
    size_t cb0 = ((size_t)(b * S_ + r0)) * INNER + h * DK;
    size_t cb1 = cb0 + (size_t)8 * INNER;
    #pragma unroll
    for (int dt = 0; dt < 8; dt++) {
        uint32_t hh, ll;
        split2(o[dt][0] * inv0, o[dt][1] * inv0, hh, ll);
        *(uint32_t*)&g_ctxhi[cb0 + dt * 8 + 2 * tg] = hh;
        *(uint32_t*)&g_ctxlo[cb0 + dt * 8 + 2 * tg] = ll;
        split2(o[dt][2] * inv1, o[dt][3] * inv1, hh, ll);
        *(uint32_t*)&g_ctxhi[cb1 + dt * 8 + 2 * tg] = hh;
        *(uint32_t*)&g_ctxlo[cb1 + dt * 8 + 2 * tg] = ll;
    }
}

// ---------------- launch ----------------
extern "C" void kernel_launch(void* const* d_in, const int* in_sizes, int n_in,
                              void* d_out, int out_size) {
    const float* hidden    = (const float*)d_in[0];
    const int*   positions = (const int*)d_in[1];
    const float* mask      = (const float*)d_in[2];
    const float* wq        = (const float*)d_in[3];
    const float* wk        = (const float*)d_in[4];
    const float* wv        = (const float*)d_in[5];
    const float* wo        = (const float*)d_in[6];
    const float* rel_bias  = (const float*)d_in[7];
    float* out = (float*)d_out;

    cudaFuncSetAttribute(proj_mma, cudaFuncAttributeMaxDynamicSharedMemorySize, GDSMEM);
    cudaFuncSetAttribute(outproj_mma, cudaFuncAttributeMaxDynamicSharedMemorySize, GDSMEM);
    cudaFuncSetAttribute(attn_mma, cudaFuncAttributeMaxDynamicSharedMemorySize, AT_DSMEM);

    lut_kernel<<<1, 256>>>();
    int nb = B_ * S_ * S_;
    bucket_kernel<<<(nb + 255) / 256, 256>>>(positions);

    {
        __nv_bfloat16 *hh, *hl, *qh_, *ql_, *kh, *kl, *vh, *vl, *oh, *ol;
        cudaGetSymbolAddress((void**)&hh, g_hidhi);
        cudaGetSymbolAddress((void**)&hl, g_hidlo);
        cudaGetSymbolAddress((void**)&qh_, g_wqhi);
        cudaGetSymbolAddress((void**)&ql_, g_wqlo);
        cudaGetSymbolAddress((void**)&kh, g_wkhi);
        cudaGetSymbolAddress((void**)&kl, g_wklo);
        cudaGetSymbolAddress((void**)&vh, g_wvhi);
        cudaGetSymbolAddress((void**)&vl, g_wvlo);
        cudaGetSymbolAddress((void**)&oh, g_wohi);
        cudaGetSymbolAddress((void**)&ol, g_wolo);
        int nh4 = B_ * S_ * DM / 4;
        presplit_kernel<<<(nh4 + 255) / 256, 256>>>((const float4*)hidden, (uint2*)hh, (uint2*)hl, nh4);
        int nw4 = DM * DM / 4;
        presplit_kernel<<<(nw4 + 255) / 256, 256>>>((const float4*)wq, (uint2*)qh_, (uint2*)ql_, nw4);
        presplit_kernel<<<(nw4 + 255) / 256, 256>>>((const float4*)wk, (uint2*)kh, (uint2*)kl, nw4);
        presplit_kernel<<<(nw4 + 255) / 256, 256>>>((const float4*)wv, (uint2*)vh, (uint2*)vl, nw4);
        presplit_kernel<<<(nw4 + 255) / 256, 256>>>((const float4*)wo, (uint2*)oh, (uint2*)ol, nw4);
    }

    dim3 gproj(24, 64);
    proj_mma<<<gproj, 512, GDSMEM>>>();

    dim3 gattn(S_ / 128, NH, B_);
    attn_mma<<<gattn, 256, AT_DSMEM>>>(rel_bias, mask);

    dim3 gout(8, 64);
    outproj_mma<<<gout, 512, GDSMEM>>>(out);
}

// round 7
// speedup vs baseline: 1.1029x; 1.1029x over previous
#include <cuda_runtime.h>
#include <cuda_bf16.h>
#include <math.h>
#include <stdint.h>

#define B_    4
#define S_    2048
#define DM    1024
#define NH    16
#define DK    64
#define INNER 1024

// ---------------- scratch (static device globals; no allocation) ----------------
__device__ __align__(256) float g_q[(size_t)B_ * NH * S_ * DK];
__device__ __align__(256) __nv_bfloat16 g_khi[(size_t)B_ * NH * S_ * DK];
__device__ __align__(256) __nv_bfloat16 g_klo[(size_t)B_ * NH * S_ * DK];
__device__ __align__(256) __nv_bfloat16 g_vthi[(size_t)B_ * NH * DK * S_];
__device__ __align__(256) __nv_bfloat16 g_vtlo[(size_t)B_ * NH * DK * S_];
__device__ __align__(256) __nv_bfloat16 g_ctxhi[(size_t)B_ * S_ * INNER];
__device__ __align__(256) __nv_bfloat16 g_ctxlo[(size_t)B_ * S_ * INNER];
__device__ __align__(256) __nv_bfloat16 g_hidhi[(size_t)B_ * S_ * DM];
__device__ __align__(256) __nv_bfloat16 g_hidlo[(size_t)B_ * S_ * DM];
__device__ __align__(256) __nv_bfloat16 g_wqhi[(size_t)DM * DM], g_wqlo[(size_t)DM * DM];
__device__ __align__(256) __nv_bfloat16 g_wkhi[(size_t)DM * DM], g_wklo[(size_t)DM * DM];
__device__ __align__(256) __nv_bfloat16 g_wvhi[(size_t)DM * DM], g_wvlo[(size_t)DM * DM];
__device__ __align__(256) __nv_bfloat16 g_wohi[(size_t)DM * DM], g_wolo[(size_t)DM * DM];
__device__ unsigned char g_bucket[(size_t)B_ * S_ * S_];
__device__ unsigned char g_lutb[256];

// ================= helpers =================
__device__ __forceinline__ void mma16816(float* c, const uint32_t* a, const uint32_t* b) {
    asm volatile(
        "mma.sync.aligned.m16n8k16.row.col.f32.bf16.bf16.f32 "
        "{%0,%1,%2,%3}, {%4,%5,%6,%7}, {%8,%9}, {%0,%1,%2,%3};\n"
        : "+f"(c[0]), "+f"(c[1]), "+f"(c[2]), "+f"(c[3])
        : "r"(a[0]), "r"(a[1]), "r"(a[2]), "r"(a[3]), "r"(b[0]), "r"(b[1]));
}

__device__ __forceinline__ void ldm4(uint32_t* r, uint32_t a) {
    asm volatile("ldmatrix.sync.aligned.m8n8.x4.shared.b16 {%0,%1,%2,%3}, [%4];"
                 : "=r"(r[0]), "=r"(r[1]), "=r"(r[2]), "=r"(r[3]) : "r"(a));
}

__device__ __forceinline__ void split2(float x, float y, uint32_t& hi, uint32_t& lo) {
    __nv_bfloat162 h = __floats2bfloat162_rn(x, y);
    float rx = x - __bfloat162float(h.x);
    float ry = y - __bfloat162float(h.y);
    __nv_bfloat162 l = __floats2bfloat162_rn(rx, ry);
    hi = *(uint32_t*)&h;
    lo = *(uint32_t*)&l;
}

__device__ __forceinline__ uint32_t smem_u32(const void* p) {
    uint32_t a;
    asm("{ .reg .u64 t; cvta.to.shared.u64 t, %1; cvt.u32.u64 %0, t; }" : "=r"(a) : "l"(p));
    return a;
}
__device__ __forceinline__ void cp16(uint32_t dst, const void* src) {
    asm volatile("cp.async.ca.shared.global [%0], [%1], 16;" :: "r"(dst), "l"(src) : "memory");
}
#define CP_COMMIT() asm volatile("cp.async.commit_group;" ::: "memory")
#define CP_WAIT1()  asm volatile("cp.async.wait_group 1;" ::: "memory")
#define CP_WAIT0()  asm volatile("cp.async.wait_group 0;" ::: "memory")

// ================= bucket LUT + bucket =================
__global__ void lut_kernel() {
    int rp = threadIdx.x;
    int bucket;
    if (rp < 8) {
        bucket = rp;
    } else {
        float v = logf((float)rp * 0.125f);
        v = v / 2.772588722239781f;
        v = v * 8.0f;
        bucket = 8 + (int)v;
        bucket = bucket < 15 ? bucket : 15;
    }
    g_lutb[rp] = (unsigned char)bucket;
}

__global__ void bucket_kernel(const int* __restrict__ pos) {
    int idx = blockIdx.x * blockDim.x + threadIdx.x;
    if (idx >= B_ * S_ * S_) return;
    int k = idx & (S_ - 1);
    int q = (idx >> 11) & (S_ - 1);
    int b = idx >> 22;
    int rel = pos[b * S_ + k] - pos[b * S_ + q];
    int ret = (rel > 0) ? 16 : 0;
    int rp = rel < 0 ? -rel : rel;
    int bucket = g_lutb[rp < 256 ? rp : 255];
    g_bucket[idx] = (unsigned char)(ret + bucket);
}

// ================= pre-split fp32 -> hi/lo bf16 =================
__global__ void presplit_kernel(const float4* __restrict__ src,
                                uint2* __restrict__ hi, uint2* __restrict__ lo, int n4) {
    int i = blockIdx.x * blockDim.x + threadIdx.x;
    if (i >= n4) return;
    float4 v = src[i];
    uint32_t h0, l0, h1, l1;
    split2(v.x, v.y, h0, l0);
    split2(v.z, v.w, h1, l1);
    uint2 uh = {h0, h1}, ul = {l0, l1};
    hi[i] = uh;
    lo[i] = ul;
}

// ================= bf16 double-buffered GEMM, 128 thr, warp tile 64x64 =========
// C[M,N] = A @ B^T, block 128x128, 4 warps (2m x 2n), warp tile 64x64.
#define RS 80
#define SA_HI 0
#define SA_LO 10240
#define SB_HI 20480
#define SB_LO 30720
#define STAGE 40960
#define GDSMEM (2 * STAGE)

__device__ __forceinline__ void gemm_stage(int c, uint32_t bufo, uint32_t sb,
                                           const __nv_bfloat16* Ahi, const __nv_bfloat16* Alo,
                                           const __nv_bfloat16* Bhi, const __nv_bfloat16* Blo,
                                           int m0, int n0, int tid) {
    int k0 = c * 32;
    #pragma unroll
    for (int j = 0; j < 4; j++) {
        int idx = tid + j * 128;
        int row = idx >> 2, q = idx & 3;
        size_t ga = (size_t)(m0 + row) * DM + k0 + q * 8;
        size_t gb = (size_t)(n0 + row) * DM + k0 + q * 8;
        uint32_t so = sb + bufo + row * RS + q * 16;
        cp16(so + SA_HI, Ahi + ga);
        cp16(so + SA_LO, Alo + ga);
        cp16(so + SB_HI, Bhi + gb);
        cp16(so + SB_LO, Blo + gb);
    }
    CP_COMMIT();
}

__device__ __forceinline__ void gemm_core(const __nv_bfloat16* Ahi, const __nv_bfloat16* Alo,
                                          const __nv_bfloat16* Bhi, const __nv_bfloat16* Blo,
                                          int m0, int n0, float acc[4][8][4], char* smem) {
    uint32_t sb = smem_u32(smem);
    int tid = threadIdx.x, lane = tid & 31, wid = tid >> 5;
    int wm = wid >> 1, wn = wid & 1;

    // ldmatrix per-thread offsets
    uint32_t aoff = (uint32_t)(wm * 64 + (lane & 15)) * RS + (lane >> 4) * 16;
    uint32_t boff = (uint32_t)(wn * 64 + ((lane >> 4) & 1) * 8 + (lane & 7)) * RS + ((lane >> 3) & 1) * 16;

    gemm_stage(0, 0, sb, Ahi, Alo, Bhi, Blo, m0, n0, tid);
    gemm_stage(1, STAGE, sb, Ahi, Alo, Bhi, Blo, m0, n0, tid);

    #pragma unroll 1
    for (int c = 0; c < 32; c++) {
        uint32_t bufo = (c & 1) * STAGE;
        if (c < 31) CP_WAIT1(); else CP_WAIT0();
        __syncthreads();
        uint32_t base = sb + bufo;
        #pragma unroll
        for (int kk = 0; kk < 2; kk++) {
            uint32_t ka = kk * 32;
            uint32_t bh[8][2], bl[8][2];
            #pragma unroll
            for (int p = 0; p < 4; p++) {
                uint32_t r[4];
                ldm4(r, base + SB_HI + boff + p * 16 * RS + ka);
                bh[2 * p][0] = r[0]; bh[2 * p][1] = r[1];
                bh[2 * p + 1][0] = r[2]; bh[2 * p + 1][1] = r[3];
                ldm4(r, base + SB_LO + boff + p * 16 * RS + ka);
                bl[2 * p][0] = r[0]; bl[2 * p][1] = r[1];
                bl[2 * p + 1][0] = r[2]; bl[2 * p + 1][1] = r[3];
            }
            #pragma unroll
            for (int mt = 0; mt < 4; mt++) {
                uint32_t ah[4], al[4];
                ldm4(ah, base + SA_HI + aoff + mt * 16 * RS + ka);
                ldm4(al, base + SA_LO + aoff + mt * 16 * RS + ka);
                #pragma unroll
                for (int nt = 0; nt < 8; nt++) {
                    mma16816(acc[mt][nt], ah, bh[nt]);
                    mma16816(acc[mt][nt], al, bh[nt]);
                    mma16816(acc[mt][nt], ah, bl[nt]);
                }
            }
        }
        __syncthreads();
        if (c + 2 < 32) gemm_stage(c + 2, bufo, sb, Ahi, Alo, Bhi, Blo, m0, n0, tid);
    }
}

// QKV projection. grid (24, 64), 128 thr
__global__ __launch_bounds__(128, 2) void proj_mma() {
    extern __shared__ char smem[];
    int bx = blockIdx.x;
    int wsel = bx >> 3;
    int n0 = (bx & 7) * 128;
    int m0 = blockIdx.y * 128;
    const __nv_bfloat16* Bh = (wsel == 0) ? g_wqhi : (wsel == 1) ? g_wkhi : g_wvhi;
    const __nv_bfloat16* Bl = (wsel == 0) ? g_wqlo : (wsel == 1) ? g_wklo : g_wvlo;

    float acc[4][8][4] = {};
    gemm_core(g_hidhi, g_hidlo, Bh, Bl, m0, n0, acc, smem);

    int lane = threadIdx.x & 31, wid = threadIdx.x >> 5;
    int wm = wid >> 1, wn = wid & 1;
    int g = lane >> 2, tg = lane & 3;
    #pragma unroll
    for (int mt = 0; mt < 4; mt++) {
        #pragma unroll
        for (int nt = 0; nt < 8; nt++) {
            int r0 = m0 + wm * 64 + mt * 16 + g;
            int r1 = r0 + 8;
            int c = n0 + wn * 64 + nt * 8 + tg * 2;
            int h = c >> 6, d = c & 63;
            int b0 = r0 >> 11, s0 = r0 & (S_ - 1);
            int b1 = r1 >> 11, s1 = r1 & (S_ - 1);
            float a0 = acc[mt][nt][0], a1 = acc[mt][nt][1];
            float a2 = acc[mt][nt][2], a3 = acc[mt][nt][3];
            if (wsel == 0) {
                float2 v0 = {a0, a1};
                *(float2*)&g_q[(((size_t)(b0 * NH + h) * S_ + s0) << 6) + d] = v0;
                float2 v1 = {a2, a3};
                *(float2*)&g_q[(((size_t)(b1 * NH + h) * S_ + s1) << 6) + d] = v1;
            } else if (wsel == 1) {
                uint32_t h0, l0, h1, l1;
                split2(a0, a1, h0, l0);
                split2(a2, a3, h1, l1);
                size_t o0 = (((size_t)(b0 * NH + h) * S_ + s0) << 6) + d;
                size_t o1 = (((size_t)(b1 * NH + h) * S_ + s1) << 6) + d;
                *(uint32_t*)&g_khi[o0] = h0; *(uint32_t*)&g_klo[o0] = l0;
                *(uint32_t*)&g_khi[o1] = h1; *(uint32_t*)&g_klo[o1] = l1;
            } else {
                size_t base0 = ((size_t)(b0 * NH + h) * DK + d) * S_;
                size_t base1 = ((size_t)(b1 * NH + h) * DK + d) * S_;
                #pragma unroll
                for (int e = 0; e < 4; e++) {
                    float x = acc[mt][nt][e];
                    __nv_bfloat16 hh = __float2bfloat16(x);
                    __nv_bfloat16 ll = __float2bfloat16(x - __bfloat162float(hh));
                    size_t o = (e < 2 ? base0 + s0 : base1 + s1) + (size_t)(e & 1) * S_;
                    g_vthi[o] = hh;
                    g_vtlo[o] = ll;
                }
            }
        }
    }
}

// output projection. grid (8, 64), 128 thr
__global__ __launch_bounds__(128, 2) void outproj_mma(float* __restrict__ out) {
    extern __shared__ char smem[];
    int n0 = blockIdx.x * 128;
    int m0 = blockIdx.y * 128;

    float acc[4][8][4] = {};
    gemm_core(g_ctxhi, g_ctxlo, g_wohi, g_wolo, m0, n0, acc, smem);

    int lane = threadIdx.x & 31, wid = threadIdx.x >> 5;
    int wm = wid >> 1, wn = wid & 1;
    int g = lane >> 2, tg = lane & 3;
    #pragma unroll
    for (int mt = 0; mt < 4; mt++) {
        #pragma unroll
        for (int nt = 0; nt < 8; nt++) {
            int r0 = m0 + wm * 64 + mt * 16 + g;
            int c = n0 + wn * 64 + nt * 8 + tg * 2;
            float2 v0 = {acc[mt][nt][0], acc[mt][nt][1]};
            *(float2*)&out[(size_t)r0 * DM + c] = v0;
            float2 v1 = {acc[mt][nt][2], acc[mt][nt][3]};
            *(float2*)&out[(size_t)(r0 + 8) * DM + c] = v1;
        }
    }
}

// ================= tensor-core flash attention (R5 version: 128 thr, q-tile 64) =====
#define KROWB 144
#define AT_KHI 0
#define AT_KLO 9216
#define AT_VTH 18432
#define AT_VTL 27648
#define ATSTAGE 36864
#define AT_MCL (2 * ATSTAGE)
#define AT_RBH (AT_MCL + 512)
#define AT_DSMEM (AT_RBH + 128)

__global__ __launch_bounds__(128, 2) void attn_mma(const float* __restrict__ rel_bias,
                                                   const float* __restrict__ mask) {
    extern __shared__ char sm[];
    float* rbh = (float*)(sm + AT_RBH);
    uint32_t sb = smem_u32(sm);

    int tid = threadIdx.x, lane = tid & 31, wrp = tid >> 5;
    int g = lane >> 2, tg = lane & 3;
    int q0 = blockIdx.x * 64, h = blockIdx.y, b = blockIdx.z;

    const __nv_bfloat16* khi = g_khi + (size_t)(b * NH + h) * S_ * DK;
    const __nv_bfloat16* klo = g_klo + (size_t)(b * NH + h) * S_ * DK;
    const __nv_bfloat16* vth = g_vthi + (size_t)(b * NH + h) * DK * S_;
    const __nv_bfloat16* vtl = g_vtlo + (size_t)(b * NH + h) * DK * S_;
    const float* maskp = mask + b * S_;

    if (tid < 32) rbh[tid] = rel_bias[tid * NH + h];

    auto stage = [&](int i) {
        int k0 = i * 64;
        uint32_t bufo = (i & 1) * ATSTAGE;
        #pragma unroll
        for (int j = 0; j < 4; j++) {
            int idx = tid + j * 128;
            int r = idx >> 3, q = idx & 7;
            uint32_t so = sb + bufo + r * KROWB + q * 16;
            cp16(so + AT_KHI, khi + (size_t)(k0 + r) * DK + q * 8);
            cp16(so + AT_KLO, klo + (size_t)(k0 + r) * DK + q * 8);
            cp16(so + AT_VTH, vth + (size_t)r * S_ + k0 + q * 8);
            cp16(so + AT_VTL, vtl + (size_t)r * S_ + k0 + q * 8);
        }
        if (tid < 16) cp16(sb + AT_MCL + (i & 1) * 256 + tid * 16, maskp + k0 + tid * 4);
        CP_COMMIT();
    };

    // Q fragments (hi/lo) in registers
    int r0 = q0 + wrp * 16 + g;
    const float* qp = g_q + ((size_t)(b * NH + h) * S_ + r0) * DK;
    uint32_t qh[4][4], ql[4][4];
    #pragma unroll
    for (int kc = 0; kc < 4; kc++) {
        int c = kc * 16 + 2 * tg;
        float2 v00 = *(const float2*)&qp[c];
        float2 v10 = *(const float2*)&qp[8 * DK + c];
        float2 v01 = *(const float2*)&qp[c + 8];
        float2 v11 = *(const float2*)&qp[8 * DK + c + 8];
        split2(v00.x, v00.y, qh[kc][0], ql[kc][0]);
        split2(v10.x, v10.y, qh[kc][1], ql[kc][1]);
        split2(v01.x, v01.y, qh[kc][2], ql[kc][2]);
        split2(v11.x, v11.y, qh[kc][3], ql[kc][3]);
    }

    const unsigned char* bk0 = g_bucket + ((size_t)b * S_ + r0) * S_;
    const unsigned char* bk1 = bk0 + 8 * (size_t)S_;

    float o[8][4] = {};
    float m0 = -1e30f, m1 = -1e30f, l0 = 0.f, l1 = 0.f;

    stage(0);
    stage(1);

    #pragma unroll 1
    for (int i = 0; i < 32; i++) {
        int k0 = i * 64;
        uint32_t bufo = (i & 1) * ATSTAGE;
        if (i < 31) CP_WAIT1(); else CP_WAIT0();
        __syncthreads();
        const char* bb = sm + bufo;
        const float* mclf = (const float*)(sm + AT_MCL + (i & 1) * 256);

        // ---- S = Q @ K^T ----
        float s[8][4] = {};
        #pragma unroll
        for (int kc = 0; kc < 4; kc++) {
            int kb = (kc * 16 + 2 * tg) * 2;
            #pragma unroll
            for (int nt = 0; nt < 8; nt++) {
                const char* ph = bb + AT_KHI + (nt * 8 + g) * KROWB + kb;
                const char* pl = bb + AT_KLO + (nt * 8 + g) * KROWB + kb;
                uint32_t bhf[2] = {*(const uint32_t*)ph, *(const uint32_t*)(ph + 16)};
                uint32_t blf[2] = {*(const uint32_t*)pl, *(const uint32_t*)(pl + 16)};
                mma16816(s[nt], qh[kc], bhf);
                mma16816(s[nt], ql[kc], bhf);
                mma16816(s[nt], qh[kc], blf);
            }
        }

        // ---- bias ----
        #pragma unroll
        for (int nt = 0; nt < 8; nt++) {
            int col = k0 + nt * 8 + 2 * tg;
            uchar2 u0 = *(const uchar2*)(bk0 + col);
            uchar2 u1 = *(const uchar2*)(bk1 + col);
            float mv0 = mclf[nt * 8 + 2 * tg], mv1 = mclf[nt * 8 + 2 * tg + 1];
            float mc0 = -1000.0f + 1000.0f * mv0;
            float mc1 = -1000.0f + 1000.0f * mv1;
            s[nt][0] += rbh[u0.x] + mc0;
            s[nt][1] += rbh[u0.y] + mc1;
            s[nt][2] += rbh[u1.x] + mc0;
            s[nt][3] += rbh[u1.y] + mc1;
        }

        // ---- online softmax ----
        float rm0 = -1e30f, rm1 = -1e30f;
        #pragma unroll
        for (int nt = 0; nt < 8; nt++) {
            rm0 = fmaxf(rm0, fmaxf(s[nt][0], s[nt][1]));
            rm1 = fmaxf(rm1, fmaxf(s[nt][2], s[nt][3]));
        }
        rm0 = fmaxf(rm0, __shfl_xor_sync(0xffffffffu, rm0, 1));
        rm0 = fmaxf(rm0, __shfl_xor_sync(0xffffffffu, rm0, 2));
        rm1 = fmaxf(rm1, __shfl_xor_sync(0xffffffffu, rm1, 1));
        rm1 = fmaxf(rm1, __shfl_xor_sync(0xffffffffu, rm1, 2));
        float mn0 = fmaxf(m0, rm0), mn1 = fmaxf(m1, rm1);
        float fac0 = __expf(m0 - mn0), fac1 = __expf(m1 - mn1);
        m0 = mn0; m1 = mn1;
        float rs0 = 0.f, rs1 = 0.f;
        #pragma unroll
        for (int nt = 0; nt < 8; nt++) {
            s[nt][0] = __expf(s[nt][0] - mn0);
            s[nt][1] = __expf(s[nt][1] - mn0);
            s[nt][2] = __expf(s[nt][2] - mn1);
            s[nt][3] = __expf(s[nt][3] - mn1);
            rs0 += s[nt][0] + s[nt][1];
            rs1 += s[nt][2] + s[nt][3];
        }
        rs0 += __shfl_xor_sync(0xffffffffu, rs0, 1);
        rs0 += __shfl_xor_sync(0xffffffffu, rs0, 2);
        rs1 += __shfl_xor_sync(0xffffffffu, rs1, 1);
        rs1 += __shfl_xor_sync(0xffffffffu, rs1, 2);
        l0 = l0 * fac0 + rs0;
        l1 = l1 * fac1 + rs1;
        #pragma unroll
        for (int dt = 0; dt < 8; dt++) {
            o[dt][0] *= fac0; o[dt][1] *= fac0;
            o[dt][2] *= fac1; o[dt][3] *= fac1;
        }

        // ---- O += P @ V ----
        #pragma unroll
        for (int kc = 0; kc < 4; kc++) {
            uint32_t ah[4], al[4];
            split2(s[2 * kc][0],     s[2 * kc][1],     ah[0], al[0]);
            split2(s[2 * kc][2],     s[2 * kc][3],     ah[1], al[1]);
            split2(s[2 * kc + 1][0], s[2 * kc + 1][1], ah[2], al[2]);
            split2(s[2 * kc + 1][2], s[2 * kc + 1][3], ah[3], al[3]);
            int kb = (kc * 16 + 2 * tg) * 2;
            #pragma unroll
            for (int dt = 0; dt < 8; dt++) {
                const char* ph = bb + AT_VTH + (dt * 8 + g) * KROWB + kb;
                const char* pl = bb + AT_VTL + (dt * 8 + g) * KROWB + kb;
                uint32_t bhf[2] = {*(const uint32_t*)ph, *(const uint32_t*)(ph + 16)};
                uint32_t blf[2] = {*(const uint32_t*)pl, *(const uint32_t*)(pl + 16)};
                mma16816(o[dt], ah, bhf);
                mma16816(o[dt], al, bhf);
                mma16816(o[dt], ah, blf);
            }
        }
        __syncthreads();
        if (i + 2 < 32) stage(i + 2);
    }

    // ---- epilogue ----
    float inv0 = 1.0f / l0, inv1 = 1.0f / l1;
    size_t cb0 = ((size_t)(b * S_ + r0)) * INNER + h * DK;
    size_t cb1 = cb0 + (size_t)8 * INNER;
    #pragma unroll
    for (int dt = 0; dt < 8; dt++) {
        uint32_t hh, ll;
        split2(o[dt][0] * inv0, o[dt][1] * inv0, hh, ll);
        *(uint32_t*)&g_ctxhi[cb0 + dt * 8 + 2 * tg] = hh;
        *(uint32_t*)&g_ctxlo[cb0 + dt * 8 + 2 * tg] = ll;
        split2(o[dt][2] * inv1, o[dt][3] * inv1, hh, ll);
        *(uint32_t*)&g_ctxhi[cb1 + dt * 8 + 2 * tg] = hh;
        *(uint32_t*)&g_ctxlo[cb1 + dt * 8 + 2 * tg] = ll;
    }
}

// ---------------- launch ----------------
extern "C" void kernel_launch(void* const* d_in, const int* in_sizes, int n_in,
                              void* d_out, int out_size) {
    const float* hidden    = (const float*)d_in[0];
    const int*   positions = (const int*)d_in[1];
    const float* mask      = (const float*)d_in[2];
    const float* wq        = (const float*)d_in[3];
    const float* wk        = (const float*)d_in[4];
    const float* wv        = (const float*)d_in[5];
    const float* wo        = (const float*)d_in[6];
    const float* rel_bias  = (const float*)d_in[7];
    float* out = (float*)d_out;

    cudaFuncSetAttribute(proj_mma, cudaFuncAttributeMaxDynamicSharedMemorySize, GDSMEM);
    cudaFuncSetAttribute(outproj_mma, cudaFuncAttributeMaxDynamicSharedMemorySize, GDSMEM);
    cudaFuncSetAttribute(attn_mma, cudaFuncAttributeMaxDynamicSharedMemorySize, AT_DSMEM);

    lut_kernel<<<1, 256>>>();
    int nb = B_ * S_ * S_;
    bucket_kernel<<<(nb + 255) / 256, 256>>>(positions);

    {
        __nv_bfloat16 *hh, *hl, *qh_, *ql_, *kh, *kl, *vh, *vl, *oh, *ol;
        cudaGetSymbolAddress((void**)&hh, g_hidhi);
        cudaGetSymbolAddress((void**)&hl, g_hidlo);
        cudaGetSymbolAddress((void**)&qh_, g_wqhi);
        cudaGetSymbolAddress((void**)&ql_, g_wqlo);
        cudaGetSymbolAddress((void**)&kh, g_wkhi);
        cudaGetSymbolAddress((void**)&kl, g_wklo);
        cudaGetSymbolAddress((void**)&vh, g_wvhi);
        cudaGetSymbolAddress((void**)&vl, g_wvlo);
        cudaGetSymbolAddress((void**)&oh, g_wohi);
        cudaGetSymbolAddress((void**)&ol, g_wolo);
        int nh4 = B_ * S_ * DM / 4;
        presplit_kernel<<<(nh4 + 255) / 256, 256>>>((const float4*)hidden, (uint2*)hh, (uint2*)hl, nh4);
        int nw4 = DM * DM / 4;
        presplit_kernel<<<(nw4 + 255) / 256, 256>>>((const float4*)wq, (uint2*)qh_, (uint2*)ql_, nw4);
        presplit_kernel<<<(nw4 + 255) / 256, 256>>>((const float4*)wk, (uint2*)kh, (uint2*)kl, nw4);
        presplit_kernel<<<(nw4 + 255) / 256, 256>>>((const float4*)wv, (uint2*)vh, (uint2*)vl, nw4);
        presplit_kernel<<<(nw4 + 255) / 256, 256>>>((const float4*)wo, (uint2*)oh, (uint2*)ol, nw4);
    }

    dim3 gproj(24, 64);
    proj_mma<<<gproj, 128, GDSMEM>>>();

    dim3 gattn(S_ / 64, NH, B_);
    attn_mma<<<gattn, 128, AT_DSMEM>>>(rel_bias, mask);

    dim3 gout(8, 64);
    outproj_mma<<<gout, 128, GDSMEM>>>(out);
}

// round 8
// speedup vs baseline: 1.1419x; 1.0354x over previous
#include <cuda_runtime.h>
#include <cuda_bf16.h>
#include <math.h>
#include <stdint.h>

#define B_    4
#define S_    2048
#define DM    1024
#define NH    16
#define DK    64
#define INNER 1024

// ---------------- scratch (static device globals; no allocation) ----------------
__device__ __align__(256) float g_q[(size_t)B_ * NH * S_ * DK];
__device__ __align__(256) __nv_bfloat16 g_khi[(size_t)B_ * NH * S_ * DK];
__device__ __align__(256) __nv_bfloat16 g_klo[(size_t)B_ * NH * S_ * DK];
__device__ __align__(256) __nv_bfloat16 g_vthi[(size_t)B_ * NH * DK * S_];
__device__ __align__(256) __nv_bfloat16 g_vtlo[(size_t)B_ * NH * DK * S_];
__device__ __align__(256) __nv_bfloat16 g_ctxhi[(size_t)B_ * S_ * INNER];
__device__ __align__(256) __nv_bfloat16 g_ctxlo[(size_t)B_ * S_ * INNER];
__device__ __align__(256) __nv_bfloat16 g_hidhi[(size_t)B_ * S_ * DM];
__device__ __align__(256) __nv_bfloat16 g_hidlo[(size_t)B_ * S_ * DM];
__device__ __align__(256) __nv_bfloat16 g_wqhi[(size_t)DM * DM], g_wqlo[(size_t)DM * DM];
__device__ __align__(256) __nv_bfloat16 g_wkhi[(size_t)DM * DM], g_wklo[(size_t)DM * DM];
__device__ __align__(256) __nv_bfloat16 g_wvhi[(size_t)DM * DM], g_wvlo[(size_t)DM * DM];
__device__ __align__(256) __nv_bfloat16 g_wohi[(size_t)DM * DM], g_wolo[(size_t)DM * DM];
__device__ unsigned char g_bucket[(size_t)B_ * S_ * S_];
__device__ unsigned char g_lutb[256];

// ================= helpers =================
__device__ __forceinline__ void mma16816(float* c, const uint32_t* a, const uint32_t* b) {
    asm volatile(
        "mma.sync.aligned.m16n8k16.row.col.f32.bf16.bf16.f32 "
        "{%0,%1,%2,%3}, {%4,%5,%6,%7}, {%8,%9}, {%0,%1,%2,%3};\n"
        : "+f"(c[0]), "+f"(c[1]), "+f"(c[2]), "+f"(c[3])
        : "r"(a[0]), "r"(a[1]), "r"(a[2]), "r"(a[3]), "r"(b[0]), "r"(b[1]));
}

__device__ __forceinline__ void ldm4(uint32_t* r, uint32_t a) {
    asm volatile("ldmatrix.sync.aligned.m8n8.x4.shared.b16 {%0,%1,%2,%3}, [%4];"
                 : "=r"(r[0]), "=r"(r[1]), "=r"(r[2]), "=r"(r[3]) : "r"(a));
}

__device__ __forceinline__ void split2(float x, float y, uint32_t& hi, uint32_t& lo) {
    __nv_bfloat162 h = __floats2bfloat162_rn(x, y);
    float rx = x - __bfloat162float(h.x);
    float ry = y - __bfloat162float(h.y);
    __nv_bfloat162 l = __floats2bfloat162_rn(rx, ry);
    hi = *(uint32_t*)&h;
    lo = *(uint32_t*)&l;
}

__device__ __forceinline__ uint32_t smem_u32(const void* p) {
    uint32_t a;
    asm("{ .reg .u64 t; cvta.to.shared.u64 t, %1; cvt.u32.u64 %0, t; }" : "=r"(a) : "l"(p));
    return a;
}
__device__ __forceinline__ void cp16(uint32_t dst, const void* src) {
    asm volatile("cp.async.ca.shared.global [%0], [%1], 16;" :: "r"(dst), "l"(src) : "memory");
}
#define CP_COMMIT() asm volatile("cp.async.commit_group;" ::: "memory")
#define CP_WAIT1()  asm volatile("cp.async.wait_group 1;" ::: "memory")
#define CP_WAIT0()  asm volatile("cp.async.wait_group 0;" ::: "memory")

// ================= bucket LUT + bucket =================
__global__ void lut_kernel() {
    int rp = threadIdx.x;
    int bucket;
    if (rp < 8) {
        bucket = rp;
    } else {
        float v = logf((float)rp * 0.125f);
        v = v / 2.772588722239781f;
        v = v * 8.0f;
        bucket = 8 + (int)v;
        bucket = bucket < 15 ? bucket : 15;
    }
    g_lutb[rp] = (unsigned char)bucket;
}

__global__ void bucket_kernel(const int* __restrict__ pos) {
    int idx = blockIdx.x * blockDim.x + threadIdx.x;
    if (idx >= B_ * S_ * S_) return;
    int k = idx & (S_ - 1);
    int q = (idx >> 11) & (S_ - 1);
    int b = idx >> 22;
    int rel = pos[b * S_ + k] - pos[b * S_ + q];
    int ret = (rel > 0) ? 16 : 0;
    int rp = rel < 0 ? -rel : rel;
    int bucket = g_lutb[rp < 256 ? rp : 255];
    g_bucket[idx] = (unsigned char)(ret + bucket);
}

// ================= pre-split fp32 -> hi/lo bf16 =================
__global__ void presplit_kernel(const float4* __restrict__ src,
                                uint2* __restrict__ hi, uint2* __restrict__ lo, int n4) {
    int i = blockIdx.x * blockDim.x + threadIdx.x;
    if (i >= n4) return;
    float4 v = src[i];
    uint32_t h0, l0, h1, l1;
    split2(v.x, v.y, h0, l0);
    split2(v.z, v.w, h1, l1);
    uint2 uh = {h0, h1}, ul = {l0, l1};
    hi[i] = uh;
    lo[i] = ul;
}

// ================= bf16 double-buffered GEMM, 128 thr, warp tile 64x64 =========
#define RS 80
#define SA_HI 0
#define SA_LO 10240
#define SB_HI 20480
#define SB_LO 30720
#define STAGE 40960
#define GDSMEM (2 * STAGE)

__device__ __forceinline__ void gemm_stage(int c, uint32_t bufo, uint32_t sb,
                                           const __nv_bfloat16* Ahi, const __nv_bfloat16* Alo,
                                           const __nv_bfloat16* Bhi, const __nv_bfloat16* Blo,
                                           int m0, int n0, int tid) {
    int k0 = c * 32;
    #pragma unroll
    for (int j = 0; j < 4; j++) {
        int idx = tid + j * 128;
        int row = idx >> 2, q = idx & 3;
        size_t ga = (size_t)(m0 + row) * DM + k0 + q * 8;
        size_t gb = (size_t)(n0 + row) * DM + k0 + q * 8;
        uint32_t so = sb + bufo + row * RS + q * 16;
        cp16(so + SA_HI, Ahi + ga);
        cp16(so + SA_LO, Alo + ga);
        cp16(so + SB_HI, Bhi + gb);
        cp16(so + SB_LO, Blo + gb);
    }
    CP_COMMIT();
}

__device__ __forceinline__ void gemm_core(const __nv_bfloat16* Ahi, const __nv_bfloat16* Alo,
                                          const __nv_bfloat16* Bhi, const __nv_bfloat16* Blo,
                                          int m0, int n0, float acc[4][8][4], char* smem) {
    uint32_t sb = smem_u32(smem);
    int tid = threadIdx.x, lane = tid & 31, wid = tid >> 5;
    int wm = wid >> 1, wn = wid & 1;

    uint32_t aoff = (uint32_t)(wm * 64 + (lane & 15)) * RS + (lane >> 4) * 16;
    uint32_t boff = (uint32_t)(wn * 64 + ((lane >> 4) & 1) * 8 + (lane & 7)) * RS + ((lane >> 3) & 1) * 16;

    gemm_stage(0, 0, sb, Ahi, Alo, Bhi, Blo, m0, n0, tid);
    gemm_stage(1, STAGE, sb, Ahi, Alo, Bhi, Blo, m0, n0, tid);

    #pragma unroll 1
    for (int c = 0; c < 32; c++) {
        uint32_t bufo = (c & 1) * STAGE;
        if (c < 31) CP_WAIT1(); else CP_WAIT0();
        __syncthreads();
        uint32_t base = sb + bufo;
        #pragma unroll
        for (int kk = 0; kk < 2; kk++) {
            uint32_t ka = kk * 32;
            uint32_t bh[8][2], bl[8][2];
            #pragma unroll
            for (int p = 0; p < 4; p++) {
                uint32_t r[4];
                ldm4(r, base + SB_HI + boff + p * 16 * RS + ka);
                bh[2 * p][0] = r[0]; bh[2 * p][1] = r[1];
                bh[2 * p + 1][0] = r[2]; bh[2 * p + 1][1] = r[3];
                ldm4(r, base + SB_LO + boff + p * 16 * RS + ka);
                bl[2 * p][0] = r[0]; bl[2 * p][1] = r[1];
                bl[2 * p + 1][0] = r[2]; bl[2 * p + 1][1] = r[3];
            }
            #pragma unroll
            for (int mt = 0; mt < 4; mt++) {
                uint32_t ah[4], al[4];
                ldm4(ah, base + SA_HI + aoff + mt * 16 * RS + ka);
                ldm4(al, base + SA_LO + aoff + mt * 16 * RS + ka);
                #pragma unroll
                for (int nt = 0; nt < 8; nt++) {
                    mma16816(acc[mt][nt], ah, bh[nt]);
                    mma16816(acc[mt][nt], al, bh[nt]);
                    mma16816(acc[mt][nt], ah, bl[nt]);
                }
            }
        }
        __syncthreads();
        if (c + 2 < 32) gemm_stage(c + 2, bufo, sb, Ahi, Alo, Bhi, Blo, m0, n0, tid);
    }
}

// QKV projection. grid (24, 64), 128 thr
__global__ __launch_bounds__(128, 2) void proj_mma() {
    extern __shared__ char smem[];
    int bx = blockIdx.x;
    int wsel = bx >> 3;
    int n0 = (bx & 7) * 128;
    int m0 = blockIdx.y * 128;
    const __nv_bfloat16* Bh = (wsel == 0) ? g_wqhi : (wsel == 1) ? g_wkhi : g_wvhi;
    const __nv_bfloat16* Bl = (wsel == 0) ? g_wqlo : (wsel == 1) ? g_wklo : g_wvlo;

    float acc[4][8][4] = {};
    gemm_core(g_hidhi, g_hidlo, Bh, Bl, m0, n0, acc, smem);

    int lane = threadIdx.x & 31, wid = threadIdx.x >> 5;
    int wm = wid >> 1, wn = wid & 1;
    int g = lane >> 2, tg = lane & 3;
    #pragma unroll
    for (int mt = 0; mt < 4; mt++) {
        #pragma unroll
        for (int nt = 0; nt < 8; nt++) {
            int r0 = m0 + wm * 64 + mt * 16 + g;
            int r1 = r0 + 8;
            int c = n0 + wn * 64 + nt * 8 + tg * 2;
            int h = c >> 6, d = c & 63;
            int b0 = r0 >> 11, s0 = r0 & (S_ - 1);
            int b1 = r1 >> 11, s1 = r1 & (S_ - 1);
            float a0 = acc[mt][nt][0], a1 = acc[mt][nt][1];
            float a2 = acc[mt][nt][2], a3 = acc[mt][nt][3];
            if (wsel == 0) {
                float2 v0 = {a0, a1};
                *(float2*)&g_q[(((size_t)(b0 * NH + h) * S_ + s0) << 6) + d] = v0;
                float2 v1 = {a2, a3};
                *(float2*)&g_q[(((size_t)(b1 * NH + h) * S_ + s1) << 6) + d] = v1;
            } else if (wsel == 1) {
                uint32_t h0, l0, h1, l1;
                split2(a0, a1, h0, l0);
                split2(a2, a3, h1, l1);
                size_t o0 = (((size_t)(b0 * NH + h) * S_ + s0) << 6) + d;
                size_t o1 = (((size_t)(b1 * NH + h) * S_ + s1) << 6) + d;
                *(uint32_t*)&g_khi[o0] = h0; *(uint32_t*)&g_klo[o0] = l0;
                *(uint32_t*)&g_khi[o1] = h1; *(uint32_t*)&g_klo[o1] = l1;
            } else {
                size_t base0 = ((size_t)(b0 * NH + h) * DK + d) * S_;
                size_t base1 = ((size_t)(b1 * NH + h) * DK + d) * S_;
                #pragma unroll
                for (int e = 0; e < 4; e++) {
                    float x = acc[mt][nt][e];
                    __nv_bfloat16 hh = __float2bfloat16(x);
                    __nv_bfloat16 ll = __float2bfloat16(x - __bfloat162float(hh));
                    size_t o = (e < 2 ? base0 + s0 : base1 + s1) + (size_t)(e & 1) * S_;
                    g_vthi[o] = hh;
                    g_vtlo[o] = ll;
                }
            }
        }
    }
}

// output projection. grid (8, 64), 128 thr
__global__ __launch_bounds__(128, 2) void outproj_mma(float* __restrict__ out) {
    extern __shared__ char smem[];
    int n0 = blockIdx.x * 128;
    int m0 = blockIdx.y * 128;

    float acc[4][8][4] = {};
    gemm_core(g_ctxhi, g_ctxlo, g_wohi, g_wolo, m0, n0, acc, smem);

    int lane = threadIdx.x & 31, wid = threadIdx.x >> 5;
    int wm = wid >> 1, wn = wid & 1;
    int g = lane >> 2, tg = lane & 3;
    #pragma unroll
    for (int mt = 0; mt < 4; mt++) {
        #pragma unroll
        for (int nt = 0; nt < 8; nt++) {
            int r0 = m0 + wm * 64 + mt * 16 + g;
            int c = n0 + wn * 64 + nt * 8 + tg * 2;
            float2 v0 = {acc[mt][nt][0], acc[mt][nt][1]};
            *(float2*)&out[(size_t)r0 * DM + c] = v0;
            float2 v1 = {acc[mt][nt][2], acc[mt][nt][3]};
            *(float2*)&out[(size_t)(r0 + 8) * DM + c] = v1;
        }
    }
}

// ================= tensor-core flash attention: 128 thr, q-tile 128 (2 m-tiles/warp) ==
#define KROWB 144
#define AT_KHI 0
#define AT_KLO 9216
#define AT_VTH 18432
#define AT_VTL 27648
#define ATSTAGE 36864
#define AT_MCL (2 * ATSTAGE)
#define AT_RBH (AT_MCL + 512)
#define AT_DSMEM (AT_RBH + 128)

__global__ __launch_bounds__(128, 2) void attn_mma(const float* __restrict__ rel_bias,
                                                   const float* __restrict__ mask) {
    extern __shared__ char sm[];
    float* rbh = (float*)(sm + AT_RBH);
    uint32_t sb = smem_u32(sm);

    int tid = threadIdx.x, lane = tid & 31, wrp = tid >> 5;
    int g = lane >> 2, tg = lane & 3;
    int q0 = blockIdx.x * 128, h = blockIdx.y, b = blockIdx.z;

    const __nv_bfloat16* khi = g_khi + (size_t)(b * NH + h) * S_ * DK;
    const __nv_bfloat16* klo = g_klo + (size_t)(b * NH + h) * S_ * DK;
    const __nv_bfloat16* vth = g_vthi + (size_t)(b * NH + h) * DK * S_;
    const __nv_bfloat16* vtl = g_vtlo + (size_t)(b * NH + h) * DK * S_;
    const float* maskp = mask + b * S_;

    if (tid < 32) rbh[tid] = rel_bias[tid * NH + h];

    auto stage = [&](int i) {
        int k0 = i * 64;
        uint32_t bufo = (i & 1) * ATSTAGE;
        #pragma unroll
        for (int j = 0; j < 4; j++) {
            int idx = tid + j * 128;
            int r = idx >> 3, q = idx & 7;
            uint32_t so = sb + bufo + r * KROWB + q * 16;
            cp16(so + AT_KHI, khi + (size_t)(k0 + r) * DK + q * 8);
            cp16(so + AT_KLO, klo + (size_t)(k0 + r) * DK + q * 8);
            cp16(so + AT_VTH, vth + (size_t)r * S_ + k0 + q * 8);
            cp16(so + AT_VTL, vtl + (size_t)r * S_ + k0 + q * 8);
        }
        if (tid < 16) cp16(sb + AT_MCL + (i & 1) * 256 + tid * 16, maskp + k0 + tid * 4);
        CP_COMMIT();
    };

    // Q fragments (hi/lo) in registers for two m16 tiles: rows ra, ra+8, rb, rb+8
    int ra = q0 + wrp * 32 + g;
    int rb = ra + 16;
    const float* qpa = g_q + ((size_t)(b * NH + h) * S_ + ra) * DK;
    const float* qpb = g_q + ((size_t)(b * NH + h) * S_ + rb) * DK;
    uint32_t qh0[4][4], ql0[4][4], qh1[4][4], ql1[4][4];
    #pragma unroll
    for (int kc = 0; kc < 4; kc++) {
        int c = kc * 16 + 2 * tg;
        float2 v;
        v = *(const float2*)&qpa[c];            split2(v.x, v.y, qh0[kc][0], ql0[kc][0]);
        v = *(const float2*)&qpa[8 * DK + c];   split2(v.x, v.y, qh0[kc][1], ql0[kc][1]);
        v = *(const float2*)&qpa[c + 8];        split2(v.x, v.y, qh0[kc][2], ql0[kc][2]);
        v = *(const float2*)&qpa[8 * DK + c + 8]; split2(v.x, v.y, qh0[kc][3], ql0[kc][3]);
        v = *(const float2*)&qpb[c];            split2(v.x, v.y, qh1[kc][0], ql1[kc][0]);
        v = *(const float2*)&qpb[8 * DK + c];   split2(v.x, v.y, qh1[kc][1], ql1[kc][1]);
        v = *(const float2*)&qpb[c + 8];        split2(v.x, v.y, qh1[kc][2], ql1[kc][2]);
        v = *(const float2*)&qpb[8 * DK + c + 8]; split2(v.x, v.y, qh1[kc][3], ql1[kc][3]);
    }

    const unsigned char* bka0 = g_bucket + ((size_t)b * S_ + ra) * S_;
    const unsigned char* bka1 = bka0 + 8 * (size_t)S_;
    const unsigned char* bkb0 = g_bucket + ((size_t)b * S_ + rb) * S_;
    const unsigned char* bkb1 = bkb0 + 8 * (size_t)S_;

    float o0[8][4] = {}, o1[8][4] = {};
    float ma0 = -1e30f, ma1 = -1e30f, la0 = 0.f, la1 = 0.f;
    float mb0 = -1e30f, mb1 = -1e30f, lb0 = 0.f, lb1 = 0.f;

    stage(0);
    stage(1);

    #pragma unroll 1
    for (int i = 0; i < 32; i++) {
        int k0 = i * 64;
        uint32_t bufo = (i & 1) * ATSTAGE;
        if (i < 31) CP_WAIT1(); else CP_WAIT0();
        __syncthreads();
        const char* bb = sm + bufo;
        const float* mclf = (const float*)(sm + AT_MCL + (i & 1) * 256);

        // ---- S = Q @ K^T, both m-tiles share each K fragment ----
        float s0[8][4] = {}, s1[8][4] = {};
        #pragma unroll
        for (int kc = 0; kc < 4; kc++) {
            int kb = (kc * 16 + 2 * tg) * 2;
            #pragma unroll
            for (int nt = 0; nt < 8; nt++) {
                const char* ph = bb + AT_KHI + (nt * 8 + g) * KROWB + kb;
                const char* pl = bb + AT_KLO + (nt * 8 + g) * KROWB + kb;
                uint32_t bhf[2] = {*(const uint32_t*)ph, *(const uint32_t*)(ph + 16)};
                uint32_t blf[2] = {*(const uint32_t*)pl, *(const uint32_t*)(pl + 16)};
                mma16816(s0[nt], qh0[kc], bhf);
                mma16816(s0[nt], ql0[kc], bhf);
                mma16816(s0[nt], qh0[kc], blf);
                mma16816(s1[nt], qh1[kc], bhf);
                mma16816(s1[nt], ql1[kc], bhf);
                mma16816(s1[nt], qh1[kc], blf);
            }
        }

        // ---- bias ----
        #pragma unroll
        for (int nt = 0; nt < 8; nt++) {
            int col = k0 + nt * 8 + 2 * tg;
            float mv0 = mclf[nt * 8 + 2 * tg], mv1 = mclf[nt * 8 + 2 * tg + 1];
            float mc0 = -1000.0f + 1000.0f * mv0;
            float mc1 = -1000.0f + 1000.0f * mv1;
            uchar2 ua0 = *(const uchar2*)(bka0 + col);
            uchar2 ua1 = *(const uchar2*)(bka1 + col);
            s0[nt][0] += rbh[ua0.x] + mc0;
            s0[nt][1] += rbh[ua0.y] + mc1;
            s0[nt][2] += rbh[ua1.x] + mc0;
            s0[nt][3] += rbh[ua1.y] + mc1;
            uchar2 ub0 = *(const uchar2*)(bkb0 + col);
            uchar2 ub1 = *(const uchar2*)(bkb1 + col);
            s1[nt][0] += rbh[ub0.x] + mc0;
            s1[nt][1] += rbh[ub0.y] + mc1;
            s1[nt][2] += rbh[ub1.x] + mc0;
            s1[nt][3] += rbh[ub1.y] + mc1;
        }

        // ---- online softmax, tile a ----
        {
            float rm0 = -1e30f, rm1 = -1e30f;
            #pragma unroll
            for (int nt = 0; nt < 8; nt++) {
                rm0 = fmaxf(rm0, fmaxf(s0[nt][0], s0[nt][1]));
                rm1 = fmaxf(rm1, fmaxf(s0[nt][2], s0[nt][3]));
            }
            rm0 = fmaxf(rm0, __shfl_xor_sync(0xffffffffu, rm0, 1));
            rm0 = fmaxf(rm0, __shfl_xor_sync(0xffffffffu, rm0, 2));
            rm1 = fmaxf(rm1, __shfl_xor_sync(0xffffffffu, rm1, 1));
            rm1 = fmaxf(rm1, __shfl_xor_sync(0xffffffffu, rm1, 2));
            float mn0 = fmaxf(ma0, rm0), mn1 = fmaxf(ma1, rm1);
            float fac0 = __expf(ma0 - mn0), fac1 = __expf(ma1 - mn1);
            ma0 = mn0; ma1 = mn1;
            float rs0 = 0.f, rs1 = 0.f;
            #pragma unroll
            for (int nt = 0; nt < 8; nt++) {
                s0[nt][0] = __expf(s0[nt][0] - mn0);
                s0[nt][1] = __expf(s0[nt][1] - mn0);
                s0[nt][2] = __expf(s0[nt][2] - mn1);
                s0[nt][3] = __expf(s0[nt][3] - mn1);
                rs0 += s0[nt][0] + s0[nt][1];
                rs1 += s0[nt][2] + s0[nt][3];
            }
            rs0 += __shfl_xor_sync(0xffffffffu, rs0, 1);
            rs0 += __shfl_xor_sync(0xffffffffu, rs0, 2);
            rs1 += __shfl_xor_sync(0xffffffffu, rs1, 1);
            rs1 += __shfl_xor_sync(0xffffffffu, rs1, 2);
            la0 = la0 * fac0 + rs0;
            la1 = la1 * fac1 + rs1;
            #pragma unroll
            for (int dt = 0; dt < 8; dt++) {
                o0[dt][0] *= fac0; o0[dt][1] *= fac0;
                o0[dt][2] *= fac1; o0[dt][3] *= fac1;
            }
        }
        // ---- online softmax, tile b ----
        {
            float rm0 = -1e30f, rm1 = -1e30f;
            #pragma unroll
            for (int nt = 0; nt < 8; nt++) {
                rm0 = fmaxf(rm0, fmaxf(s1[nt][0], s1[nt][1]));
                rm1 = fmaxf(rm1, fmaxf(s1[nt][2], s1[nt][3]));
            }
            rm0 = fmaxf(rm0, __shfl_xor_sync(0xffffffffu, rm0, 1));
            rm0 = fmaxf(rm0, __shfl_xor_sync(0xffffffffu, rm0, 2));
            rm1 = fmaxf(rm1, __shfl_xor_sync(0xffffffffu, rm1, 1));
            rm1 = fmaxf(rm1, __shfl_xor_sync(0xffffffffu, rm1, 2));
            float mn0 = fmaxf(mb0, rm0), mn1 = fmaxf(mb1, rm1);
            float fac0 = __expf(mb0 - mn0), fac1 = __expf(mb1 - mn1);
            mb0 = mn0; mb1 = mn1;
            float rs0 = 0.f, rs1 = 0.f;
            #pragma unroll
            for (int nt = 0; nt < 8; nt++) {
                s1[nt][0] = __expf(s1[nt][0] - mn0);
                s1[nt][1] = __expf(s1[nt][1] - mn0);
                s1[nt][2] = __expf(s1[nt][2] - mn1);
                s1[nt][3] = __expf(s1[nt][3] - mn1);
                rs0 += s1[nt][0] + s1[nt][1];
                rs1 += s1[nt][2] + s1[nt][3];
            }
            rs0 += __shfl_xor_sync(0xffffffffu, rs0, 1);
            rs0 += __shfl_xor_sync(0xffffffffu, rs0, 2);
            rs1 += __shfl_xor_sync(0xffffffffu, rs1, 1);
            rs1 += __shfl_xor_sync(0xffffffffu, rs1, 2);
            lb0 = lb0 * fac0 + rs0;
            lb1 = lb1 * fac1 + rs1;
            #pragma unroll
            for (int dt = 0; dt < 8; dt++) {
                o1[dt][0] *= fac0; o1[dt][1] *= fac0;
                o1[dt][2] *= fac1; o1[dt][3] *= fac1;
            }
        }

        // ---- O += P @ V, both m-tiles share each V fragment ----
        #pragma unroll
        for (int kc = 0; kc < 4; kc++) {
            uint32_t ah0[4], al0[4], ah1[4], al1[4];
            split2(s0[2 * kc][0],     s0[2 * kc][1],     ah0[0], al0[0]);
            split2(s0[2 * kc][2],     s0[2 * kc][3],     ah0[1], al0[1]);
            split2(s0[2 * kc + 1][0], s0[2 * kc + 1][1], ah0[2], al0[2]);
            split2(s0[2 * kc + 1][2], s0[2 * kc + 1][3], ah0[3], al0[3]);
            split2(s1[2 * kc][0],     s1[2 * kc][1],     ah1[0], al1[0]);
            split2(s1[2 * kc][2],     s1[2 * kc][3],     ah1[1], al1[1]);
            split2(s1[2 * kc + 1][0], s1[2 * kc + 1][1], ah1[2], al1[2]);
            split2(s1[2 * kc + 1][2], s1[2 * kc + 1][3], ah1[3], al1[3]);
            int kb = (kc * 16 + 2 * tg) * 2;
            #pragma unroll
            for (int dt = 0; dt < 8; dt++) {
                const char* ph = bb + AT_VTH + (dt * 8 + g) * KROWB + kb;
                const char* pl = bb + AT_VTL + (dt * 8 + g) * KROWB + kb;
                uint32_t bhf[2] = {*(const uint32_t*)ph, *(const uint32_t*)(ph + 16)};
                uint32_t blf[2] = {*(const uint32_t*)pl, *(const uint32_t*)(pl + 16)};
                mma16816(o0[dt], ah0, bhf);
                mma16816(o0[dt], al0, bhf);
                mma16816(o0[dt], ah0, blf);
                mma16816(o1[dt], ah1, bhf);
                mma16816(o1[dt], al1, bhf);
                mma16816(o1[dt], ah1, blf);
            }
        }
        __syncthreads();
        if (i + 2 < 32) stage(i + 2);
    }

    // ---- epilogue ----
    {
        float inv0 = 1.0f / la0, inv1 = 1.0f / la1;
        size_t cb0 = ((size_t)(b * S_ + ra)) * INNER + h * DK;
        size_t cb1 = cb0 + (size_t)8 * INNER;
        #pragma unroll
        for (int dt = 0; dt < 8; dt++) {
            uint32_t hh, ll;
            split2(o0[dt][0] * inv0, o0[dt][1] * inv0, hh, ll);
            *(uint32_t*)&g_ctxhi[cb0 + dt * 8 + 2 * tg] = hh;
            *(uint32_t*)&g_ctxlo[cb0 + dt * 8 + 2 * tg] = ll;
            split2(o0[dt][2] * inv1, o0[dt][3] * inv1, hh, ll);
            *(uint32_t*)&g_ctxhi[cb1 + dt * 8 + 2 * tg] = hh;
            *(uint32_t*)&g_ctxlo[cb1 + dt * 8 + 2 * tg] = ll;
        }
    }
    {
        float inv0 = 1.0f / lb0, inv1 = 1.0f / lb1;
        size_t cb0 = ((size_t)(b * S_ + rb)) * INNER + h * DK;
        size_t cb1 = cb0 + (size_t)8 * INNER;
        #pragma unroll
        for (int dt = 0; dt < 8; dt++) {
            uint32_t hh, ll;
            split2(o1[dt][0] * inv0, o1[dt][1] * inv0, hh, ll);
            *(uint32_t*)&g_ctxhi[cb0 + dt * 8 + 2 * tg] = hh;
            *(uint32_t*)&g_ctxlo[cb0 + dt * 8 + 2 * tg] = ll;
            split2(o1[dt][2] * inv1, o1[dt][3] * inv1, hh, ll);
            *(uint32_t*)&g_ctxhi[cb1 + dt * 8 + 2 * tg] = hh;
            *(uint32_t*)&g_ctxlo[cb1 + dt * 8 + 2 * tg] = ll;
        }
    }
}

// ---------------- launch ----------------
extern "C" void kernel_launch(void* const* d_in, const int* in_sizes, int n_in,
                              void* d_out, int out_size) {
    const float* hidden    = (const float*)d_in[0];
    const int*   positions = (const int*)d_in[1];
    const float* mask      = (const float*)d_in[2];
    const float* wq        = (const float*)d_in[3];
    const float* wk        = (const float*)d_in[4];
    const float* wv        = (const float*)d_in[5];
    const float* wo        = (const float*)d_in[6];
    const float* rel_bias  = (const float*)d_in[7];
    float* out = (float*)d_out;

    cudaFuncSetAttribute(proj_mma, cudaFuncAttributeMaxDynamicSharedMemorySize, GDSMEM);
    cudaFuncSetAttribute(outproj_mma, cudaFuncAttributeMaxDynamicSharedMemorySize, GDSMEM);
    cudaFuncSetAttribute(attn_mma, cudaFuncAttributeMaxDynamicSharedMemorySize, AT_DSMEM);

    lut_kernel<<<1, 256>>>();
    int nb = B_ * S_ * S_;
    bucket_kernel<<<(nb + 255) / 256, 256>>>(positions);

    {
        __nv_bfloat16 *hh, *hl, *qh_, *ql_, *kh, *kl, *vh, *vl, *oh, *ol;
        cudaGetSymbolAddress((void**)&hh, g_hidhi);
        cudaGetSymbolAddress((void**)&hl, g_hidlo);
        cudaGetSymbolAddress((void**)&qh_, g_wqhi);
        cudaGetSymbolAddress((void**)&ql_, g_wqlo);
        cudaGetSymbolAddress((void**)&kh, g_wkhi);
        cudaGetSymbolAddress((void**)&kl, g_wklo);
        cudaGetSymbolAddress((void**)&vh, g_wvhi);
        cudaGetSymbolAddress((void**)&vl, g_wvlo);
        cudaGetSymbolAddress((void**)&oh, g_wohi);
        cudaGetSymbolAddress((void**)&ol, g_wolo);
        int nh4 = B_ * S_ * DM / 4;
        presplit_kernel<<<(nh4 + 255) / 256, 256>>>((const float4*)hidden, (uint2*)hh, (uint2*)hl, nh4);
        int nw4 = DM * DM / 4;
        presplit_kernel<<<(nw4 + 255) / 256, 256>>>((const float4*)wq, (uint2*)qh_, (uint2*)ql_, nw4);
        presplit_kernel<<<(nw4 + 255) / 256, 256>>>((const float4*)wk, (uint2*)kh, (uint2*)kl, nw4);
        presplit_kernel<<<(nw4 + 255) / 256, 256>>>((const float4*)wv, (uint2*)vh, (uint2*)vl, nw4);
        presplit_kernel<<<(nw4 + 255) / 256, 256>>>((const float4*)wo, (uint2*)oh, (uint2*)ol, nw4);
    }

    dim3 gproj(24, 64);
    proj_mma<<<gproj, 128, GDSMEM>>>();

    dim3 gattn(S_ / 128, NH, B_);
    attn_mma<<<gattn, 128, AT_DSMEM>>>(rel_bias, mask);

    dim3 gout(8, 64);
    outproj_mma<<<gout, 128, GDSMEM>>>(out);
}

// round 10
// speedup vs baseline: 1.1448x; 1.0026x over previous
#include <cuda_runtime.h>
#include <cuda_bf16.h>
#include <math.h>
#include <stdint.h>

#define B_    4
#define S_    2048
#define DM    1024
#define NH    16
#define DK    64
#define INNER 1024

// ---------------- scratch (static device globals; no allocation) ----------------
__device__ __align__(256) float g_q[(size_t)B_ * NH * S_ * DK];
__device__ __align__(256) __nv_bfloat16 g_khi[(size_t)B_ * NH * S_ * DK];
__device__ __align__(256) __nv_bfloat16 g_klo[(size_t)B_ * NH * S_ * DK];
__device__ __align__(256) __nv_bfloat16 g_vthi[(size_t)B_ * NH * DK * S_];
__device__ __align__(256) __nv_bfloat16 g_vtlo[(size_t)B_ * NH * DK * S_];
__device__ __align__(256) __nv_bfloat16 g_ctxhi[(size_t)B_ * S_ * INNER];
__device__ __align__(256) __nv_bfloat16 g_ctxlo[(size_t)B_ * S_ * INNER];
__device__ __align__(256) __nv_bfloat16 g_hidhi[(size_t)B_ * S_ * DM];
__device__ __align__(256) __nv_bfloat16 g_hidlo[(size_t)B_ * S_ * DM];
__device__ __align__(256) __nv_bfloat16 g_wqhi[(size_t)DM * DM], g_wqlo[(size_t)DM * DM];
__device__ __align__(256) __nv_bfloat16 g_wkhi[(size_t)DM * DM], g_wklo[(size_t)DM * DM];
__device__ __align__(256) __nv_bfloat16 g_wvhi[(size_t)DM * DM], g_wvlo[(size_t)DM * DM];
__device__ __align__(256) __nv_bfloat16 g_wohi[(size_t)DM * DM], g_wolo[(size_t)DM * DM];
__device__ unsigned char g_bucket[(size_t)B_ * S_ * S_];
__device__ unsigned char g_lutb[256];

// ================= helpers =================
__device__ __forceinline__ void mma16816(float* c, const uint32_t* a, const uint32_t* b) {
    asm volatile(
        "mma.sync.aligned.m16n8k16.row.col.f32.bf16.bf16.f32 "
        "{%0,%1,%2,%3}, {%4,%5,%6,%7}, {%8,%9}, {%0,%1,%2,%3};\n"
        : "+f"(c[0]), "+f"(c[1]), "+f"(c[2]), "+f"(c[3])
        : "r"(a[0]), "r"(a[1]), "r"(a[2]), "r"(a[3]), "r"(b[0]), "r"(b[1]));
}

__device__ __forceinline__ void ldm4(uint32_t* r, uint32_t a) {
    asm volatile("ldmatrix.sync.aligned.m8n8.x4.shared.b16 {%0,%1,%2,%3}, [%4];"
                 : "=r"(r[0]), "=r"(r[1]), "=r"(r[2]), "=r"(r[3]) : "r"(a));
}

__device__ __forceinline__ void split2(float x, float y, uint32_t& hi, uint32_t& lo) {
    __nv_bfloat162 h = __floats2bfloat162_rn(x, y);
    float rx = x - __bfloat162float(h.x);
    float ry = y - __bfloat162float(h.y);
    __nv_bfloat162 l = __floats2bfloat162_rn(rx, ry);
    hi = *(uint32_t*)&h;
    lo = *(uint32_t*)&l;
}

__device__ __forceinline__ uint32_t smem_u32(const void* p) {
    uint32_t a;
    asm("{ .reg .u64 t; cvta.to.shared.u64 t, %1; cvt.u32.u64 %0, t; }" : "=r"(a) : "l"(p));
    return a;
}
__device__ __forceinline__ void cp16(uint32_t dst, const void* src) {
    asm volatile("cp.async.ca.shared.global [%0], [%1], 16;" :: "r"(dst), "l"(src) : "memory");
}
#define CP_COMMIT() asm volatile("cp.async.commit_group;" ::: "memory")
#define CP_WAIT1()  asm volatile("cp.async.wait_group 1;" ::: "memory")
#define CP_WAIT0()  asm volatile("cp.async.wait_group 0;" ::: "memory")

// ================= bucket LUT + bucket =================
__global__ void lut_kernel() {
    int rp = threadIdx.x;
    int bucket;
    if (rp < 8) {
        bucket = rp;
    } else {
        float v = logf((float)rp * 0.125f);
        v = v / 2.772588722239781f;
        v = v * 8.0f;
        bucket = 8 + (int)v;
        bucket = bucket < 15 ? bucket : 15;
    }
    g_lutb[rp] = (unsigned char)bucket;
}

__global__ void bucket_kernel(const int* __restrict__ pos) {
    int idx = blockIdx.x * blockDim.x + threadIdx.x;
    if (idx >= B_ * S_ * S_) return;
    int k = idx & (S_ - 1);
    int q = (idx >> 11) & (S_ - 1);
    int b = idx >> 22;
    int rel = pos[b * S_ + k] - pos[b * S_ + q];
    int ret = (rel > 0) ? 16 : 0;
    int rp = rel < 0 ? -rel : rel;
    int bucket = g_lutb[rp < 256 ? rp : 255];
    g_bucket[idx] = (unsigned char)(ret + bucket);
}

// ================= pre-split fp32 -> hi/lo bf16 =================
__global__ void presplit_kernel(const float4* __restrict__ src,
                                uint2* __restrict__ hi, uint2* __restrict__ lo, int n4) {
    int i = blockIdx.x * blockDim.x + threadIdx.x;
    if (i >= n4) return;
    float4 v = src[i];
    uint32_t h0, l0, h1, l1;
    split2(v.x, v.y, h0, l0);
    split2(v.z, v.w, h1, l1);
    uint2 uh = {h0, h1}, ul = {l0, l1};
    hi[i] = uh;
    lo[i] = ul;
}

// ================= bf16 double-buffered GEMM, 128 thr, warp tile 64x64 =========
#define RS 80
#define SA_HI 0
#define SA_LO 10240
#define SB_HI 20480
#define SB_LO 30720
#define STAGE 40960
#define GDSMEM (2 * STAGE)

__device__ __forceinline__ void gemm_stage(int c, uint32_t bufo, uint32_t sb,
                                           const __nv_bfloat16* Ahi, const __nv_bfloat16* Alo,
                                           const __nv_bfloat16* Bhi, const __nv_bfloat16* Blo,
                                           int m0, int n0, int tid) {
    int k0 = c * 32;
    #pragma unroll
    for (int j = 0; j < 4; j++) {
        int idx = tid + j * 128;
        int row = idx >> 2, q = idx & 3;
        size_t ga = (size_t)(m0 + row) * DM + k0 + q * 8;
        size_t gb = (size_t)(n0 + row) * DM + k0 + q * 8;
        uint32_t so = sb + bufo + row * RS + q * 16;
        cp16(so + SA_HI, Ahi + ga);
        cp16(so + SA_LO, Alo + ga);
        cp16(so + SB_HI, Bhi + gb);
        cp16(so + SB_LO, Blo + gb);
    }
    CP_COMMIT();
}

__device__ __forceinline__ void gemm_core(const __nv_bfloat16* Ahi, const __nv_bfloat16* Alo,
                                          const __nv_bfloat16* Bhi, const __nv_bfloat16* Blo,
                                          int m0, int n0, float acc[4][8][4], char* smem) {
    uint32_t sb = smem_u32(smem);
    int tid = threadIdx.x, lane = tid & 31, wid = tid >> 5;
    int wm = wid >> 1, wn = wid & 1;

    uint32_t aoff = (uint32_t)(wm * 64 + (lane & 15)) * RS + (lane >> 4) * 16;
    uint32_t boff = (uint32_t)(wn * 64 + ((lane >> 4) & 1) * 8 + (lane & 7)) * RS + ((lane >> 3) & 1) * 16;

    gemm_stage(0, 0, sb, Ahi, Alo, Bhi, Blo, m0, n0, tid);
    gemm_stage(1, STAGE, sb, Ahi, Alo, Bhi, Blo, m0, n0, tid);

    #pragma unroll 1
    for (int c = 0; c < 32; c++) {
        uint32_t bufo = (c & 1) * STAGE;
        if (c < 31) CP_WAIT1(); else CP_WAIT0();
        __syncthreads();
        uint32_t base = sb + bufo;
        #pragma unroll
        for (int kk = 0; kk < 2; kk++) {
            uint32_t ka = kk * 32;
            uint32_t bh[8][2], bl[8][2];
            #pragma unroll
            for (int p = 0; p < 4; p++) {
                uint32_t r[4];
                ldm4(r, base + SB_HI + boff + p * 16 * RS + ka);
                bh[2 * p][0] = r[0]; bh[2 * p][1] = r[1];
                bh[2 * p + 1][0] = r[2]; bh[2 * p + 1][1] = r[3];
                ldm4(r, base + SB_LO + boff + p * 16 * RS + ka);
                bl[2 * p][0] = r[0]; bl[2 * p][1] = r[1];
                bl[2 * p + 1][0] = r[2]; bl[2 * p + 1][1] = r[3];
            }
            #pragma unroll
            for (int mt = 0; mt < 4; mt++) {
                uint32_t ah[4], al[4];
                ldm4(ah, base + SA_HI + aoff + mt * 16 * RS + ka);
                ldm4(al, base + SA_LO + aoff + mt * 16 * RS + ka);
                #pragma unroll
                for (int nt = 0; nt < 8; nt++) {
                    mma16816(acc[mt][nt], ah, bh[nt]);
                    mma16816(acc[mt][nt], al, bh[nt]);
                    mma16816(acc[mt][nt], ah, bl[nt]);
                }
            }
        }
        __syncthreads();
        if (c + 2 < 32) gemm_stage(c + 2, bufo, sb, Ahi, Alo, Bhi, Blo, m0, n0, tid);
    }
}

// QKV projection. grid (24, 64), 128 thr
__global__ __launch_bounds__(128, 2) void proj_mma() {
    extern __shared__ char smem[];
    int bx = blockIdx.x;
    int wsel = bx >> 3;
    int n0 = (bx & 7) * 128;
    int m0 = blockIdx.y * 128;
    const __nv_bfloat16* Bh = (wsel == 0) ? g_wqhi : (wsel == 1) ? g_wkhi : g_wvhi;
    const __nv_bfloat16* Bl = (wsel == 0) ? g_wqlo : (wsel == 1) ? g_wklo : g_wvlo;

    float acc[4][8][4] = {};
    gemm_core(g_hidhi, g_hidlo, Bh, Bl, m0, n0, acc, smem);

    int lane = threadIdx.x & 31, wid = threadIdx.x >> 5;
    int wm = wid >> 1, wn = wid & 1;
    int g = lane >> 2, tg = lane & 3;
    #pragma unroll
    for (int mt = 0; mt < 4; mt++) {
        #pragma unroll
        for (int nt = 0; nt < 8; nt++) {
            int r0 = m0 + wm * 64 + mt * 16 + g;
            int r1 = r0 + 8;
            int c = n0 + wn * 64 + nt * 8 + tg * 2;
            int h = c >> 6, d = c & 63;
            int b0 = r0 >> 11, s0 = r0 & (S_ - 1);
            int b1 = r1 >> 11, s1 = r1 & (S_ - 1);
            float a0 = acc[mt][nt][0], a1 = acc[mt][nt][1];
            float a2 = acc[mt][nt][2], a3 = acc[mt][nt][3];
            if (wsel == 0) {
                float2 v0 = {a0, a1};
                *(float2*)&g_q[(((size_t)(b0 * NH + h) * S_ + s0) << 6) + d] = v0;
                float2 v1 = {a2, a3};
                *(float2*)&g_q[(((size_t)(b1 * NH + h) * S_ + s1) << 6) + d] = v1;
            } else if (wsel == 1) {
                uint32_t h0, l0, h1, l1;
                split2(a0, a1, h0, l0);
                split2(a2, a3, h1, l1);
                size_t o0 = (((size_t)(b0 * NH + h) * S_ + s0) << 6) + d;
                size_t o1 = (((size_t)(b1 * NH + h) * S_ + s1) << 6) + d;
                *(uint32_t*)&g_khi[o0] = h0; *(uint32_t*)&g_klo[o0] = l0;
                *(uint32_t*)&g_khi[o1] = h1; *(uint32_t*)&g_klo[o1] = l1;
            } else {
                size_t base0 = ((size_t)(b0 * NH + h) * DK + d) * S_;
                size_t base1 = ((size_t)(b1 * NH + h) * DK + d) * S_;
                #pragma unroll
                for (int e = 0; e < 4; e++) {
                    float x = acc[mt][nt][e];
                    __nv_bfloat16 hh = __float2bfloat16(x);
                    __nv_bfloat16 ll = __float2bfloat16(x - __bfloat162float(hh));
                    size_t o = (e < 2 ? base0 + s0 : base1 + s1) + (size_t)(e & 1) * S_;
                    g_vthi[o] = hh;
                    g_vtlo[o] = ll;
                }
            }
        }
    }
}

// output projection. grid (8, 64), 128 thr
__global__ __launch_bounds__(128, 2) void outproj_mma(float* __restrict__ out) {
    extern __shared__ char smem[];
    int n0 = blockIdx.x * 128;
    int m0 = blockIdx.y * 128;

    float acc[4][8][4] = {};
    gemm_core(g_ctxhi, g_ctxlo, g_wohi, g_wolo, m0, n0, acc, smem);

    int lane = threadIdx.x & 31, wid = threadIdx.x >> 5;
    int wm = wid >> 1, wn = wid & 1;
    int g = lane >> 2, tg = lane & 3;
    #pragma unroll
    for (int mt = 0; mt < 4; mt++) {
        #pragma unroll
        for (int nt = 0; nt < 8; nt++) {
            int r0 = m0 + wm * 64 + mt * 16 + g;
            int c = n0 + wn * 64 + nt * 8 + tg * 2;
            float2 v0 = {acc[mt][nt][0], acc[mt][nt][1]};
            *(float2*)&out[(size_t)r0 * DM + c] = v0;
            float2 v1 = {acc[mt][nt][2], acc[mt][nt][3]};
            *(float2*)&out[(size_t)(r0 + 8) * DM + c] = v1;
        }
    }
}

// ===== tensor-core flash attention: 128 thr, q-tile 128, bucket tile via cp.async =====
#define KROWB 144
#define AT_KHI 0
#define AT_KLO 9216
#define AT_VTH 18432
#define AT_VTL 27648
#define AT_BUK 36864                    // 128 rows x 80B stride (64 bucket bytes + pad, 16B-aligned)
#define BUKRS 80
#define ATSTAGE (36864 + 128 * BUKRS)   // 47104
#define AT_MCL (2 * ATSTAGE)
#define AT_RBH (AT_MCL + 512)
#define AT_DSMEM (AT_RBH + 128)

__global__ __launch_bounds__(128, 2) void attn_mma(const float* __restrict__ rel_bias,
                                                   const float* __restrict__ mask) {
    extern __shared__ char sm[];
    float* rbh = (float*)(sm + AT_RBH);
    uint32_t sb = smem_u32(sm);

    int tid = threadIdx.x, lane = tid & 31, wrp = tid >> 5;
    int g = lane >> 2, tg = lane & 3;
    int q0 = blockIdx.x * 128, h = blockIdx.y, b = blockIdx.z;

    const __nv_bfloat16* khi = g_khi + (size_t)(b * NH + h) * S_ * DK;
    const __nv_bfloat16* klo = g_klo + (size_t)(b * NH + h) * S_ * DK;
    const __nv_bfloat16* vth = g_vthi + (size_t)(b * NH + h) * DK * S_;
    const __nv_bfloat16* vtl = g_vtlo + (size_t)(b * NH + h) * DK * S_;
    const float* maskp = mask + b * S_;
    const unsigned char* bukp = g_bucket + ((size_t)b * S_ + q0) * S_;

    if (tid < 32) rbh[tid] = rel_bias[tid * NH + h];

    auto stage = [&](int i) {
        int k0 = i * 64;
        uint32_t bufo = (i & 1) * ATSTAGE;
        #pragma unroll
        for (int j = 0; j < 4; j++) {
            int idx = tid + j * 128;
            int r = idx >> 3, q = idx & 7;
            uint32_t so = sb + bufo + r * KROWB + q * 16;
            cp16(so + AT_KHI, khi + (size_t)(k0 + r) * DK + q * 8);
            cp16(so + AT_KLO, klo + (size_t)(k0 + r) * DK + q * 8);
            cp16(so + AT_VTH, vth + (size_t)r * S_ + k0 + q * 8);
            cp16(so + AT_VTL, vtl + (size_t)r * S_ + k0 + q * 8);
        }
        // bucket tile: 128 q-rows x 64 k-cols, smem row stride 80 (16B-aligned)
        #pragma unroll
        for (int j = 0; j < 4; j++) {
            int idx = tid + j * 128;
            int r = idx >> 2, qq = idx & 3;
            cp16(sb + bufo + AT_BUK + r * BUKRS + qq * 16, bukp + (size_t)r * S_ + k0 + qq * 16);
        }
        if (tid < 16) cp16(sb + AT_MCL + (i & 1) * 256 + tid * 16, maskp + k0 + tid * 4);
        CP_COMMIT();
    };

    // Q fragments (hi/lo) in registers for two m16 tiles: rows ra, ra+8, rb, rb+8
    int ra = q0 + wrp * 32 + g;
    int rb = ra + 16;
    const float* qpa = g_q + ((size_t)(b * NH + h) * S_ + ra) * DK;
    const float* qpb = g_q + ((size_t)(b * NH + h) * S_ + rb) * DK;
    uint32_t qh0[4][4], ql0[4][4], qh1[4][4], ql1[4][4];
    #pragma unroll
    for (int kc = 0; kc < 4; kc++) {
        int c = kc * 16 + 2 * tg;
        float2 v;
        v = *(const float2*)&qpa[c];            split2(v.x, v.y, qh0[kc][0], ql0[kc][0]);
        v = *(const float2*)&qpa[8 * DK + c];   split2(v.x, v.y, qh0[kc][1], ql0[kc][1]);
        v = *(const float2*)&qpa[c + 8];        split2(v.x, v.y, qh0[kc][2], ql0[kc][2]);
        v = *(const float2*)&qpa[8 * DK + c + 8]; split2(v.x, v.y, qh0[kc][3], ql0[kc][3]);
        v = *(const float2*)&qpb[c];            split2(v.x, v.y, qh1[kc][0], ql1[kc][0]);
        v = *(const float2*)&qpb[8 * DK + c];   split2(v.x, v.y, qh1[kc][1], ql1[kc][1]);
        v = *(const float2*)&qpb[c + 8];        split2(v.x, v.y, qh1[kc][2], ql1[kc][2]);
        v = *(const float2*)&qpb[8 * DK + c + 8]; split2(v.x, v.y, qh1[kc][3], ql1[kc][3]);
    }

    float o0[8][4] = {}, o1[8][4] = {};
    float ma0 = -1e30f, ma1 = -1e30f, la0 = 0.f, la1 = 0.f;
    float mb0 = -1e30f, mb1 = -1e30f, lb0 = 0.f, lb1 = 0.f;

    stage(0);
    stage(1);

    int rowa = wrp * 32 + g;   // local q-row of tile a frag row 0

    #pragma unroll 1
    for (int i = 0; i < 32; i++) {
        uint32_t bufo = (i & 1) * ATSTAGE;
        if (i < 31) CP_WAIT1(); else CP_WAIT0();
        __syncthreads();
        const char* bb = sm + bufo;
        const float* mclf = (const float*)(sm + AT_MCL + (i & 1) * 256);
        const char* bkt = bb + AT_BUK;

        // ---- S = Q @ K^T, both m-tiles share each K fragment ----
        float s0[8][4] = {}, s1[8][4] = {};
        #pragma unroll
        for (int kc = 0; kc < 4; kc++) {
            int kb = (kc * 16 + 2 * tg) * 2;
            #pragma unroll
            for (int nt = 0; nt < 8; nt++) {
                const char* ph = bb + AT_KHI + (nt * 8 + g) * KROWB + kb;
                const char* pl = bb + AT_KLO + (nt * 8 + g) * KROWB + kb;
                uint32_t bhf[2] = {*(const uint32_t*)ph, *(const uint32_t*)(ph + 16)};
                uint32_t blf[2] = {*(const uint32_t*)pl, *(const uint32_t*)(pl + 16)};
                mma16816(s0[nt], qh0[kc], bhf);
                mma16816(s0[nt], ql0[kc], bhf);
                mma16816(s0[nt], qh0[kc], blf);
                mma16816(s1[nt], qh1[kc], bhf);
                mma16816(s1[nt], ql1[kc], bhf);
                mma16816(s1[nt], qh1[kc], blf);
            }
        }

        // ---- bias (bucket tile in smem, conflict-free) ----
        #pragma unroll
        for (int nt = 0; nt < 8; nt++) {
            int col = nt * 8 + 2 * tg;
            float mv0 = mclf[nt * 8 + 2 * tg], mv1 = mclf[nt * 8 + 2 * tg + 1];
            float mc0 = -1000.0f + 1000.0f * mv0;
            float mc1 = -1000.0f + 1000.0f * mv1;
            uchar2 ua0 = *(const uchar2*)(bkt + (rowa) * BUKRS + col);
            uchar2 ua1 = *(const uchar2*)(bkt + (rowa + 8) * BUKRS + col);
            s0[nt][0] += rbh[ua0.x] + mc0;
            s0[nt][1] += rbh[ua0.y] + mc1;
            s0[nt][2] += rbh[ua1.x] + mc0;
            s0[nt][3] += rbh[ua1.y] + mc1;
            uchar2 ub0 = *(const uchar2*)(bkt + (rowa + 16) * BUKRS + col);
            uchar2 ub1 = *(const uchar2*)(bkt + (rowa + 24) * BUKRS + col);
            s1[nt][0] += rbh[ub0.x] + mc0;
            s1[nt][1] += rbh[ub0.y] + mc1;
            s1[nt][2] += rbh[ub1.x] + mc0;
            s1[nt][3] += rbh[ub1.y] + mc1;
        }

        // ---- online softmax, tile a ----
        {
            float rm0 = -1e30f, rm1 = -1e30f;
            #pragma unroll
            for (int nt = 0; nt < 8; nt++) {
                rm0 = fmaxf(rm0, fmaxf(s0[nt][0], s0[nt][1]));
                rm1 = fmaxf(rm1, fmaxf(s0[nt][2], s0[nt][3]));
            }
            rm0 = fmaxf(rm0, __shfl_xor_sync(0xffffffffu, rm0, 1));
            rm0 = fmaxf(rm0, __shfl_xor_sync(0xffffffffu, rm0, 2));
            rm1 = fmaxf(rm1, __shfl_xor_sync(0xffffffffu, rm1, 1));
            rm1 = fmaxf(rm1, __shfl_xor_sync(0xffffffffu, rm1, 2));
            float mn0 = fmaxf(ma0, rm0), mn1 = fmaxf(ma1, rm1);
            float fac0 = __expf(ma0 - mn0), fac1 = __expf(ma1 - mn1);
            ma0 = mn0; ma1 = mn1;
            float rs0 = 0.f, rs1 = 0.f;
            #pragma unroll
            for (int nt = 0; nt < 8; nt++) {
                s0[nt][0] = __expf(s0[nt][0] - mn0);
                s0[nt][1] = __expf(s0[nt][1] - mn0);
                s0[nt][2] = __expf(s0[nt][2] - mn1);
                s0[nt][3] = __expf(s0[nt][3] - mn1);
                rs0 += s0[nt][0] + s0[nt][1];
                rs1 += s0[nt][2] + s0[nt][3];
            }
            rs0 += __shfl_xor_sync(0xffffffffu, rs0, 1);
            rs0 += __shfl_xor_sync(0xffffffffu, rs0, 2);
            rs1 += __shfl_xor_sync(0xffffffffu, rs1, 1);
            rs1 += __shfl_xor_sync(0xffffffffu, rs1, 2);
            la0 = la0 * fac0 + rs0;
            la1 = la1 * fac1 + rs1;
            #pragma unroll
            for (int dt = 0; dt < 8; dt++) {
                o0[dt][0] *= fac0; o0[dt][1] *= fac0;
                o0[dt][2] *= fac1; o0[dt][3] *= fac1;
            }
        }
        // ---- online softmax, tile b ----
        {
            float rm0 = -1e30f, rm1 = -1e30f;
            #pragma unroll
            for (int nt = 0; nt < 8; nt++) {
                rm0 = fmaxf(rm0, fmaxf(s1[nt][0], s1[nt][1]));
                rm1 = fmaxf(rm1, fmaxf(s1[nt][2], s1[nt][3]));
            }
            rm0 = fmaxf(rm0, __shfl_xor_sync(0xffffffffu, rm0, 1));
            rm0 = fmaxf(rm0, __shfl_xor_sync(0xffffffffu, rm0, 2));
            rm1 = fmaxf(rm1, __shfl_xor_sync(0xffffffffu, rm1, 1));
            rm1 = fmaxf(rm1, __shfl_xor_sync(0xffffffffu, rm1, 2));
            float mn0 = fmaxf(mb0, rm0), mn1 = fmaxf(mb1, rm1);
            float fac0 = __expf(mb0 - mn0), fac1 = __expf(mb1 - mn1);
            mb0 = mn0; mb1 = mn1;
            float rs0 = 0.f, rs1 = 0.f;
            #pragma unroll
            for (int nt = 0; nt < 8; nt++) {
                s1[nt][0] = __expf(s1[nt][0] - mn0);
                s1[nt][1] = __expf(s1[nt][1] - mn0);
                s1[nt][2] = __expf(s1[nt][2] - mn1);
                s1[nt][3] = __expf(s1[nt][3] - mn1);
                rs0 += s1[nt][0] + s1[nt][1];
                rs1 += s1[nt][2] + s1[nt][3];
            }
            rs0 += __shfl_xor_sync(0xffffffffu, rs0, 1);
            rs0 += __shfl_xor_sync(0xffffffffu, rs0, 2);
            rs1 += __shfl_xor_sync(0xffffffffu, rs1, 1);
            rs1 += __shfl_xor_sync(0xffffffffu, rs1, 2);
            lb0 = lb0 * fac0 + rs0;
            lb1 = lb1 * fac1 + rs1;
            #pragma unroll
            for (int dt = 0; dt < 8; dt++) {
                o1[dt][0] *= fac0; o1[dt][1] *= fac0;
                o1[dt][2] *= fac1; o1[dt][3] *= fac1;
            }
        }

        // ---- O += P @ V, both m-tiles share each V fragment ----
        #pragma unroll
        for (int kc = 0; kc < 4; kc++) {
            uint32_t ah0[4], al0[4], ah1[4], al1[4];
            split2(s0[2 * kc][0],     s0[2 * kc][1],     ah0[0], al0[0]);
            split2(s0[2 * kc][2],     s0[2 * kc][3],     ah0[1], al0[1]);
            split2(s0[2 * kc + 1][0], s0[2 * kc + 1][1], ah0[2], al0[2]);
            split2(s0[2 * kc + 1][2], s0[2 * kc + 1][3], ah0[3], al0[3]);
            split2(s1[2 * kc][0],     s1[2 * kc][1],     ah1[0], al1[0]);
            split2(s1[2 * kc][2],     s1[2 * kc][3],     ah1[1], al1[1]);
            split2(s1[2 * kc + 1][0], s1[2 * kc + 1][1], ah1[2], al1[2]);
            split2(s1[2 * kc + 1][2], s1[2 * kc + 1][3], ah1[3], al1[3]);
            int kb = (kc * 16 + 2 * tg) * 2;
            #pragma unroll
            for (int dt = 0; dt < 8; dt++) {
                const char* ph = bb + AT_VTH + (dt * 8 + g) * KROWB + kb;
                const char* pl = bb + AT_VTL + (dt * 8 + g) * KROWB + kb;
                uint32_t bhf[2] = {*(const uint32_t*)ph, *(const uint32_t*)(ph + 16)};
                uint32_t blf[2] = {*(const uint32_t*)pl, *(const uint32_t*)(pl + 16)};
                mma16816(o0[dt], ah0, bhf);
                mma16816(o0[dt], al0, bhf);
                mma16816(o0[dt], ah0, blf);
                mma16816(o1[dt], ah1, bhf);
                mma16816(o1[dt], al1, bhf);
                mma16816(o1[dt], ah1, blf);
            }
        }
        __syncthreads();
        if (i + 2 < 32) stage(i + 2);
    }

    // ---- epilogue ----
    {
        float inv0 = 1.0f / la0, inv1 = 1.0f / la1;
        size_t cb0 = ((size_t)(b * S_ + ra)) * INNER + h * DK;
        size_t cb1 = cb0 + (size_t)8 * INNER;
        #pragma unroll
        for (int dt = 0; dt < 8; dt++) {
            uint32_t hh, ll;
            split2(o0[dt][0] * inv0, o0[dt][1] * inv0, hh, ll);
            *(uint32_t*)&g_ctxhi[cb0 + dt * 8 + 2 * tg] = hh;
            *(uint32_t*)&g_ctxlo[cb0 + dt * 8 + 2 * tg] = ll;
            split2(o0[dt][2] * inv1, o0[dt][3] * inv1, hh, ll);
            *(uint32_t*)&g_ctxhi[cb1 + dt * 8 + 2 * tg] = hh;
            *(uint32_t*)&g_ctxlo[cb1 + dt * 8 + 2 * tg] = ll;
        }
    }
    {
        float inv0 = 1.0f / lb0, inv1 = 1.0f / lb1;
        size_t cb0 = ((size_t)(b * S_ + rb)) * INNER + h * DK;
        size_t cb1 = cb0 + (size_t)8 * INNER;
        #pragma unroll
        for (int dt = 0; dt < 8; dt++) {
            uint32_t hh, ll;
            split2(o1[dt][0] * inv0, o1[dt][1] * inv0, hh, ll);
            *(uint32_t*)&g_ctxhi[cb0 + dt * 8 + 2 * tg] = hh;
            *(uint32_t*)&g_ctxlo[cb0 + dt * 8 + 2 * tg] = ll;
            split2(o1[dt][2] * inv1, o1[dt][3] * inv1, hh, ll);
            *(uint32_t*)&g_ctxhi[cb1 + dt * 8 + 2 * tg] = hh;
            *(uint32_t*)&g_ctxlo[cb1 + dt * 8 + 2 * tg] = ll;
        }
    }
}

// ---------------- launch ----------------
extern "C" void kernel_launch(void* const* d_in, const int* in_sizes, int n_in,
                              void* d_out, int out_size) {
    const float* hidden    = (const float*)d_in[0];
    const int*   positions = (const int*)d_in[1];
    const float* mask      = (const float*)d_in[2];
    const float* wq        = (const float*)d_in[3];
    const float* wk        = (const float*)d_in[4];
    const float* wv        = (const float*)d_in[5];
    const float* wo        = (const float*)d_in[6];
    const float* rel_bias  = (const float*)d_in[7];
    float* out = (float*)d_out;

    cudaFuncSetAttribute(proj_mma, cudaFuncAttributeMaxDynamicSharedMemorySize, GDSMEM);
    cudaFuncSetAttribute(outproj_mma, cudaFuncAttributeMaxDynamicSharedMemorySize, GDSMEM);
    cudaFuncSetAttribute(attn_mma, cudaFuncAttributeMaxDynamicSharedMemorySize, AT_DSMEM);

    lut_kernel<<<1, 256>>>();
    int nb = B_ * S_ * S_;
    bucket_kernel<<<(nb + 255) / 256, 256>>>(positions);

    {
        __nv_bfloat16 *hh, *hl, *qh_, *ql_, *kh, *kl, *vh, *vl, *oh, *ol;
        cudaGetSymbolAddress((void**)&hh, g_hidhi);
        cudaGetSymbolAddress((void**)&hl, g_hidlo);
        cudaGetSymbolAddress((void**)&qh_, g_wqhi);
        cudaGetSymbolAddress((void**)&ql_, g_wqlo);
        cudaGetSymbolAddress((void**)&kh, g_wkhi);
        cudaGetSymbolAddress((void**)&kl, g_wklo);
        cudaGetSymbolAddress((void**)&vh, g_wvhi);
        cudaGetSymbolAddress((void**)&vl, g_wvlo);
        cudaGetSymbolAddress((void**)&oh, g_wohi);
        cudaGetSymbolAddress((void**)&ol, g_wolo);
        int nh4 = B_ * S_ * DM / 4;
        presplit_kernel<<<(nh4 + 255) / 256, 256>>>((const float4*)hidden, (uint2*)hh, (uint2*)hl, nh4);
        int nw4 = DM * DM / 4;
        presplit_kernel<<<(nw4 + 255) / 256, 256>>>((const float4*)wq, (uint2*)qh_, (uint2*)ql_, nw4);
        presplit_kernel<<<(nw4 + 255) / 256, 256>>>((const float4*)wk, (uint2*)kh, (uint2*)kl, nw4);
        presplit_kernel<<<(nw4 + 255) / 256, 256>>>((const float4*)wv, (uint2*)vh, (uint2*)vl, nw4);
        presplit_kernel<<<(nw4 + 255) / 256, 256>>>((const float4*)wo, (uint2*)oh, (uint2*)ol, nw4);
    }

    dim3 gproj(24, 64);
    proj_mma<<<gproj, 128, GDSMEM>>>();

    dim3 gattn(S_ / 128, NH, B_);
    attn_mma<<<gattn, 128, AT_DSMEM>>>(rel_bias, mask);

    dim3 gout(8, 64);
    outproj_mma<<<gout, 128, GDSMEM>>>(out);
}

// round 15
// speedup vs baseline: 1.1484x; 1.0031x over previous
#include <cuda_runtime.h>
#include <cuda_bf16.h>
#include <math.h>
#include <stdint.h>

#define B_    4
#define S_    2048
#define DM    1024
#define NH    16
#define DK    64
#define INNER 1024

// ---------------- scratch (static device globals; no allocation) ----------------
__device__ __align__(256) float g_q[(size_t)B_ * NH * S_ * DK];
__device__ __align__(256) __nv_bfloat16 g_khi[(size_t)B_ * NH * S_ * DK];
__device__ __align__(256) __nv_bfloat16 g_klo[(size_t)B_ * NH * S_ * DK];
__device__ __align__(256) __nv_bfloat16 g_vthi[(size_t)B_ * NH * DK * S_];
__device__ __align__(256) __nv_bfloat16 g_vtlo[(size_t)B_ * NH * DK * S_];
__device__ __align__(256) __nv_bfloat16 g_ctxhi[(size_t)B_ * S_ * INNER];
__device__ __align__(256) __nv_bfloat16 g_ctxlo[(size_t)B_ * S_ * INNER];
__device__ __align__(256) __nv_bfloat16 g_hidhi[(size_t)B_ * S_ * DM];
__device__ __align__(256) __nv_bfloat16 g_hidlo[(size_t)B_ * S_ * DM];
__device__ __align__(256) __nv_bfloat16 g_wqhi[(size_t)DM * DM], g_wqlo[(size_t)DM * DM];
__device__ __align__(256) __nv_bfloat16 g_wkhi[(size_t)DM * DM], g_wklo[(size_t)DM * DM];
__device__ __align__(256) __nv_bfloat16 g_wvhi[(size_t)DM * DM], g_wvlo[(size_t)DM * DM];
__device__ __align__(256) __nv_bfloat16 g_wohi[(size_t)DM * DM], g_wolo[(size_t)DM * DM];
__device__ unsigned char g_bucket[(size_t)B_ * S_ * S_];
__device__ unsigned char g_lutb[256];

// ================= helpers =================
__device__ __forceinline__ void mma16816(float* c, const uint32_t* a, const uint32_t* b) {
    asm volatile(
        "mma.sync.aligned.m16n8k16.row.col.f32.bf16.bf16.f32 "
        "{%0,%1,%2,%3}, {%4,%5,%6,%7}, {%8,%9}, {%0,%1,%2,%3};\n"
        : "+f"(c[0]), "+f"(c[1]), "+f"(c[2]), "+f"(c[3])
        : "r"(a[0]), "r"(a[1]), "r"(a[2]), "r"(a[3]), "r"(b[0]), "r"(b[1]));
}

__device__ __forceinline__ void ldm4(uint32_t* r, uint32_t a) {
    asm volatile("ldmatrix.sync.aligned.m8n8.x4.shared.b16 {%0,%1,%2,%3}, [%4];"
                 : "=r"(r[0]), "=r"(r[1]), "=r"(r[2]), "=r"(r[3]) : "r"(a));
}

__device__ __forceinline__ void split2(float x, float y, uint32_t& hi, uint32_t& lo) {
    __nv_bfloat162 h = __floats2bfloat162_rn(x, y);
    float rx = x - __bfloat162float(h.x);
    float ry = y - __bfloat162float(h.y);
    __nv_bfloat162 l = __floats2bfloat162_rn(rx, ry);
    hi = *(uint32_t*)&h;
    lo = *(uint32_t*)&l;
}

__device__ __forceinline__ uint32_t smem_u32(const void* p) {
    uint32_t a;
    asm("{ .reg .u64 t; cvta.to.shared.u64 t, %1; cvt.u32.u64 %0, t; }" : "=r"(a) : "l"(p));
    return a;
}
__device__ __forceinline__ void cp16(uint32_t dst, const void* src) {
    asm volatile("cp.async.ca.shared.global [%0], [%1], 16;" :: "r"(dst), "l"(src) : "memory");
}
#define CP_COMMIT() asm volatile("cp.async.commit_group;" ::: "memory")
#define CP_WAIT1()  asm volatile("cp.async.wait_group 1;" ::: "memory")
#define CP_WAIT0()  asm volatile("cp.async.wait_group 0;" ::: "memory")

// ================= bucket LUT + bucket =================
__global__ void lut_kernel() {
    int rp = threadIdx.x;
    int bucket;
    if (rp < 8) {
        bucket = rp;
    } else {
        float v = logf((float)rp * 0.125f);
        v = v / 2.772588722239781f;
        v = v * 8.0f;
        bucket = 8 + (int)v;
        bucket = bucket < 15 ? bucket : 15;
    }
    g_lutb[rp] = (unsigned char)bucket;
}

__global__ void bucket_kernel(const int* __restrict__ pos) {
    int idx = blockIdx.x * blockDim.x + threadIdx.x;
    if (idx >= B_ * S_ * S_) return;
    int k = idx & (S_ - 1);
    int q = (idx >> 11) & (S_ - 1);
    int b = idx >> 22;
    int rel = pos[b * S_ + k] - pos[b * S_ + q];
    int ret = (rel > 0) ? 16 : 0;
    int rp = rel < 0 ? -rel : rel;
    int bucket = g_lutb[rp < 256 ? rp : 255];
    g_bucket[idx] = (unsigned char)(ret + bucket);
}

// ================= pre-split fp32 -> hi/lo bf16 =================
__global__ void presplit_kernel(const float4* __restrict__ src,
                                uint2* __restrict__ hi, uint2* __restrict__ lo, int n4) {
    int i = blockIdx.x * blockDim.x + threadIdx.x;
    if (i >= n4) return;
    float4 v = src[i];
    uint32_t h0, l0, h1, l1;
    split2(v.x, v.y, h0, l0);
    split2(v.z, v.w, h1, l1);
    uint2 uh = {h0, h1}, ul = {l0, l1};
    hi[i] = uh;
    lo[i] = ul;
}

// ================= bf16 double-buffered GEMM, 128 thr, warp tile 64x64 =========
#define RS 80
#define SA_HI 0
#define SA_LO 10240
#define SB_HI 20480
#define SB_LO 30720
#define STAGE 40960
#define GDSMEM (2 * STAGE)

__device__ __forceinline__ void gemm_stage(int c, uint32_t bufo, uint32_t sb,
                                           const __nv_bfloat16* Ahi, const __nv_bfloat16* Alo,
                                           const __nv_bfloat16* Bhi, const __nv_bfloat16* Blo,
                                           int m0, int n0, int tid) {
    int k0 = c * 32;
    #pragma unroll
    for (int j = 0; j < 4; j++) {
        int idx = tid + j * 128;
        int row = idx >> 2, q = idx & 3;
        size_t ga = (size_t)(m0 + row) * DM + k0 + q * 8;
        size_t gb = (size_t)(n0 + row) * DM + k0 + q * 8;
        uint32_t so = sb + bufo + row * RS + q * 16;
        cp16(so + SA_HI, Ahi + ga);
        cp16(so + SA_LO, Alo + ga);
        cp16(so + SB_HI, Bhi + gb);
        cp16(so + SB_LO, Blo + gb);
    }
    CP_COMMIT();
}

__device__ __forceinline__ void gemm_core(const __nv_bfloat16* Ahi, const __nv_bfloat16* Alo,
                                          const __nv_bfloat16* Bhi, const __nv_bfloat16* Blo,
                                          int m0, int n0, float acc[4][8][4], char* smem) {
    uint32_t sb = smem_u32(smem);
    int tid = threadIdx.x, lane = tid & 31, wid = tid >> 5;
    int wm = wid >> 1, wn = wid & 1;

    uint32_t aoff = (uint32_t)(wm * 64 + (lane & 15)) * RS + (lane >> 4) * 16;
    uint32_t boff = (uint32_t)(wn * 64 + ((lane >> 4) & 1) * 8 + (lane & 7)) * RS + ((lane >> 3) & 1) * 16;

    gemm_stage(0, 0, sb, Ahi, Alo, Bhi, Blo, m0, n0, tid);
    gemm_stage(1, STAGE, sb, Ahi, Alo, Bhi, Blo, m0, n0, tid);

    #pragma unroll 1
    for (int c = 0; c < 32; c++) {
        uint32_t bufo = (c & 1) * STAGE;
        if (c < 31) CP_WAIT1(); else CP_WAIT0();
        __syncthreads();
        uint32_t base = sb + bufo;
        #pragma unroll
        for (int kk = 0; kk < 2; kk++) {
            uint32_t ka = kk * 32;
            uint32_t bh[8][2], bl[8][2];
            #pragma unroll
            for (int p = 0; p < 4; p++) {
                uint32_t r[4];
                ldm4(r, base + SB_HI + boff + p * 16 * RS + ka);
                bh[2 * p][0] = r[0]; bh[2 * p][1] = r[1];
                bh[2 * p + 1][0] = r[2]; bh[2 * p + 1][1] = r[3];
                ldm4(r, base + SB_LO + boff + p * 16 * RS + ka);
                bl[2 * p][0] = r[0]; bl[2 * p][1] = r[1];
                bl[2 * p + 1][0] = r[2]; bl[2 * p + 1][1] = r[3];
            }
            #pragma unroll
            for (int mt = 0; mt < 4; mt++) {
                uint32_t ah[4], al[4];
                ldm4(ah, base + SA_HI + aoff + mt * 16 * RS + ka);
                ldm4(al, base + SA_LO + aoff + mt * 16 * RS + ka);
                // term-major: same-accumulator MMAs spaced 8 apart
                #pragma unroll
                for (int nt = 0; nt < 8; nt++) mma16816(acc[mt][nt], ah, bh[nt]);
                #pragma unroll
                for (int nt = 0; nt < 8; nt++) mma16816(acc[mt][nt], al, bh[nt]);
                #pragma unroll
                for (int nt = 0; nt < 8; nt++) mma16816(acc[mt][nt], ah, bl[nt]);
            }
        }
        __syncthreads();
        if (c + 2 < 32) gemm_stage(c + 2, bufo, sb, Ahi, Alo, Bhi, Blo, m0, n0, tid);
    }
}

// QKV projection. grid (24, 64), 128 thr
__global__ __launch_bounds__(128, 2) void proj_mma() {
    extern __shared__ char smem[];
    int bx = blockIdx.x;
    int wsel = bx >> 3;
    int n0 = (bx & 7) * 128;
    int m0 = blockIdx.y * 128;
    const __nv_bfloat16* Bh = (wsel == 0) ? g_wqhi : (wsel == 1) ? g_wkhi : g_wvhi;
    const __nv_bfloat16* Bl = (wsel == 0) ? g_wqlo : (wsel == 1) ? g_wklo : g_wvlo;

    float acc[4][8][4] = {};
    gemm_core(g_hidhi, g_hidlo, Bh, Bl, m0, n0, acc, smem);

    int lane = threadIdx.x & 31, wid = threadIdx.x >> 5;
    int wm = wid >> 1, wn = wid & 1;
    int g = lane >> 2, tg = lane & 3;
    #pragma unroll
    for (int mt = 0; mt < 4; mt++) {
        #pragma unroll
        for (int nt = 0; nt < 8; nt++) {
            int r0 = m0 + wm * 64 + mt * 16 + g;
            int r1 = r0 + 8;
            int c = n0 + wn * 64 + nt * 8 + tg * 2;
            int h = c >> 6, d = c & 63;
            int b0 = r0 >> 11, s0 = r0 & (S_ - 1);
            int b1 = r1 >> 11, s1 = r1 & (S_ - 1);
            float a0 = acc[mt][nt][0], a1 = acc[mt][nt][1];
            float a2 = acc[mt][nt][2], a3 = acc[mt][nt][3];
            if (wsel == 0) {
                float2 v0 = {a0, a1};
                *(float2*)&g_q[(((size_t)(b0 * NH + h) * S_ + s0) << 6) + d] = v0;
                float2 v1 = {a2, a3};
                *(float2*)&g_q[(((size_t)(b1 * NH + h) * S_ + s1) << 6) + d] = v1;
            } else if (wsel == 1) {
                uint32_t h0, l0, h1, l1;
                split2(a0, a1, h0, l0);
                split2(a2, a3, h1, l1);
                size_t o0 = (((size_t)(b0 * NH + h) * S_ + s0) << 6) + d;
                size_t o1 = (((size_t)(b1 * NH + h) * S_ + s1) << 6) + d;
                *(uint32_t*)&g_khi[o0] = h0; *(uint32_t*)&g_klo[o0] = l0;
                *(uint32_t*)&g_khi[o1] = h1; *(uint32_t*)&g_klo[o1] = l1;
            } else {
                size_t base0 = ((size_t)(b0 * NH + h) * DK + d) * S_;
                size_t base1 = ((size_t)(b1 * NH + h) * DK + d) * S_;
                #pragma unroll
                for (int e = 0; e < 4; e++) {
                    float x = acc[mt][nt][e];
                    __nv_bfloat16 hh = __float2bfloat16(x);
                    __nv_bfloat16 ll = __float2bfloat16(x - __bfloat162float(hh));
                    size_t o = (e < 2 ? base0 + s0 : base1 + s1) + (size_t)(e & 1) * S_;
                    g_vthi[o] = hh;
                    g_vtlo[o] = ll;
                }
            }
        }
    }
}

// output projection. grid (8, 64), 128 thr
__global__ __launch_bounds__(128, 2) void outproj_mma(float* __restrict__ out) {
    extern __shared__ char smem[];
    int n0 = blockIdx.x * 128;
    int m0 = blockIdx.y * 128;

    float acc[4][8][4] = {};
    gemm_core(g_ctxhi, g_ctxlo, g_wohi, g_wolo, m0, n0, acc, smem);

    int lane = threadIdx.x & 31, wid = threadIdx.x >> 5;
    int wm = wid >> 1, wn = wid & 1;
    int g = lane >> 2, tg = lane & 3;
    #pragma unroll
    for (int mt = 0; mt < 4; mt++) {
        #pragma unroll
        for (int nt = 0; nt < 8; nt++) {
            int r0 = m0 + wm * 64 + mt * 16 + g;
            int c = n0 + wn * 64 + nt * 8 + tg * 2;
            float2 v0 = {acc[mt][nt][0], acc[mt][nt][1]};
            *(float2*)&out[(size_t)r0 * DM + c] = v0;
            float2 v1 = {acc[mt][nt][2], acc[mt][nt][3]};
            *(float2*)&out[(size_t)(r0 + 8) * DM + c] = v1;
        }
    }
}

// ===== tensor-core flash attention: 128 thr, q-tile 128, bucket tile via cp.async =====
#define KROWB 144
#define AT_KHI 0
#define AT_KLO 9216
#define AT_VTH 18432
#define AT_VTL 27648
#define AT_BUK 36864
#define BUKRS 80
#define ATSTAGE (36864 + 128 * BUKRS)
#define AT_MCL (2 * ATSTAGE)
#define AT_RBH (AT_MCL + 512)
#define AT_DSMEM (AT_RBH + 128)

__global__ __launch_bounds__(128, 2) void attn_mma(const float* __restrict__ rel_bias,
                                                   const float* __restrict__ mask) {
    extern __shared__ char sm[];
    float* rbh = (float*)(sm + AT_RBH);
    uint32_t sb = smem_u32(sm);

    int tid = threadIdx.x, lane = tid & 31, wrp = tid >> 5;
    int g = lane >> 2, tg = lane & 3;
    int q0 = blockIdx.x * 128, h = blockIdx.y, b = blockIdx.z;

    const __nv_bfloat16* khi = g_khi + (size_t)(b * NH + h) * S_ * DK;
    const __nv_bfloat16* klo = g_klo + (size_t)(b * NH + h) * S_ * DK;
    const __nv_bfloat16* vth = g_vthi + (size_t)(b * NH + h) * DK * S_;
    const __nv_bfloat16* vtl = g_vtlo + (size_t)(b * NH + h) * DK * S_;
    const float* maskp = mask + b * S_;
    const unsigned char* bukp = g_bucket + ((size_t)b * S_ + q0) * S_;

    if (tid < 32) rbh[tid] = rel_bias[tid * NH + h];

    auto stage = [&](int i) {
        int k0 = i * 64;
        uint32_t bufo = (i & 1) * ATSTAGE;
        #pragma unroll
        for (int j = 0; j < 4; j++) {
            int idx = tid + j * 128;
            int r = idx >> 3, q = idx & 7;
            uint32_t so = sb + bufo + r * KROWB + q * 16;
            cp16(so + AT_KHI, khi + (size_t)(k0 + r) * DK + q * 8);
            cp16(so + AT_KLO, klo + (size_t)(k0 + r) * DK + q * 8);
            cp16(so + AT_VTH, vth + (size_t)r * S_ + k0 + q * 8);
            cp16(so + AT_VTL, vtl + (size_t)r * S_ + k0 + q * 8);
        }
        #pragma unroll
        for (int j = 0; j < 4; j++) {
            int idx = tid + j * 128;
            int r = idx >> 2, qq = idx & 3;
            cp16(sb + bufo + AT_BUK + r * BUKRS + qq * 16, bukp + (size_t)r * S_ + k0 + qq * 16);
        }
        if (tid < 16) cp16(sb + AT_MCL + (i & 1) * 256 + tid * 16, maskp + k0 + tid * 4);
        CP_COMMIT();
    };

    // Q fragments (hi/lo) in registers for two m16 tiles: rows ra, ra+8, rb, rb+8
    int ra = q0 + wrp * 32 + g;
    int rb = ra + 16;
    const float* qpa = g_q + ((size_t)(b * NH + h) * S_ + ra) * DK;
    const float* qpb = g_q + ((size_t)(b * NH + h) * S_ + rb) * DK;
    uint32_t qh0[4][4], ql0[4][4], qh1[4][4], ql1[4][4];
    #pragma unroll
    for (int kc = 0; kc < 4; kc++) {
        int c = kc * 16 + 2 * tg;
        float2 v;
        v = *(const float2*)&qpa[c];            split2(v.x, v.y, qh0[kc][0], ql0[kc][0]);
        v = *(const float2*)&qpa[8 * DK + c];   split2(v.x, v.y, qh0[kc][1], ql0[kc][1]);
        v = *(const float2*)&qpa[c + 8];        split2(v.x, v.y, qh0[kc][2], ql0[kc][2]);
        v = *(const float2*)&qpa[8 * DK + c + 8]; split2(v.x, v.y, qh0[kc][3], ql0[kc][3]);
        v = *(const float2*)&qpb[c];            split2(v.x, v.y, qh1[kc][0], ql1[kc][0]);
        v = *(const float2*)&qpb[8 * DK + c];   split2(v.x, v.y, qh1[kc][1], ql1[kc][1]);
        v = *(const float2*)&qpb[c + 8];        split2(v.x, v.y, qh1[kc][2], ql1[kc][2]);
        v = *(const float2*)&qpb[8 * DK + c + 8]; split2(v.x, v.y, qh1[kc][3], ql1[kc][3]);
    }

    float o0[8][4] = {}, o1[8][4] = {};
    float ma0 = -1e30f, ma1 = -1e30f, la0 = 0.f, la1 = 0.f;
    float mb0 = -1e30f, mb1 = -1e30f, lb0 = 0.f, lb1 = 0.f;

    stage(0);
    stage(1);

    int rowa = wrp * 32 + g;

    #pragma unroll 1
    for (int i = 0; i < 32; i++) {
        uint32_t bufo = (i & 1) * ATSTAGE;
        if (i < 31) CP_WAIT1(); else CP_WAIT0();
        __syncthreads();
        const char* bb = sm + bufo;
        const float* mclf = (const float*)(sm + AT_MCL + (i & 1) * 256);
        const char* bkt = bb + AT_BUK;

        // ---- S = Q @ K^T; interleave m-tiles so same-acc MMAs are spaced ----
        float s0[8][4] = {}, s1[8][4] = {};
        #pragma unroll
        for (int kc = 0; kc < 4; kc++) {
            int kb = (kc * 16 + 2 * tg) * 2;
            #pragma unroll
            for (int nt = 0; nt < 8; nt++) {
                const char* ph = bb + AT_KHI + (nt * 8 + g) * KROWB + kb;
                const char* pl = bb + AT_KLO + (nt * 8 + g) * KROWB + kb;
                uint32_t bhf[2] = {*(const uint32_t*)ph, *(const uint32_t*)(ph + 16)};
                uint32_t blf[2] = {*(const uint32_t*)pl, *(const uint32_t*)(pl + 16)};
                mma16816(s0[nt], qh0[kc], bhf);
                mma16816(s1[nt], qh1[kc], bhf);
                mma16816(s0[nt], ql0[kc], bhf);
                mma16816(s1[nt], ql1[kc], bhf);
                mma16816(s0[nt], qh0[kc], blf);
                mma16816(s1[nt], qh1[kc], blf);
            }
        }

        // ---- bias ----
        #pragma unroll
        for (int nt = 0; nt < 8; nt++) {
            int col = nt * 8 + 2 * tg;
            float mv0 = mclf[nt * 8 + 2 * tg], mv1 = mclf[nt * 8 + 2 * tg + 1];
            float mc0 = -1000.0f + 1000.0f * mv0;
            float mc1 = -1000.0f + 1000.0f * mv1;
            uchar2 ua0 = *(const uchar2*)(bkt + (rowa) * BUKRS + col);
            uchar2 ua1 = *(const uchar2*)(bkt + (rowa + 8) * BUKRS + col);
            s0[nt][0] += rbh[ua0.x] + mc0;
            s0[nt][1] += rbh[ua0.y] + mc1;
            s0[nt][2] += rbh[ua1.x] + mc0;
            s0[nt][3] += rbh[ua1.y] + mc1;
            uchar2 ub0 = *(const uchar2*)(bkt + (rowa + 16) * BUKRS + col);
            uchar2 ub1 = *(const uchar2*)(bkt + (rowa + 24) * BUKRS + col);
            s1[nt][0] += rbh[ub0.x] + mc0;
            s1[nt][1] += rbh[ub0.y] + mc1;
            s1[nt][2] += rbh[ub1.x] + mc0;
            s1[nt][3] += rbh[ub1.y] + mc1;
        }

        // ---- online softmax, tile a ----
        {
            float rm0 = -1e30f, rm1 = -1e30f;
            #pragma unroll
            for (int nt = 0; nt < 8; nt++) {
                rm0 = fmaxf(rm0, fmaxf(s0[nt][0], s0[nt][1]));
                rm1 = fmaxf(rm1, fmaxf(s0[nt][2], s0[nt][3]));
            }
            rm0 = fmaxf(rm0, __shfl_xor_sync(0xffffffffu, rm0, 1));
            rm0 = fmaxf(rm0, __shfl_xor_sync(0xffffffffu, rm0, 2));
            rm1 = fmaxf(rm1, __shfl_xor_sync(0xffffffffu, rm1, 1));
            rm1 = fmaxf(rm1, __shfl_xor_sync(0xffffffffu, rm1, 2));
            float mn0 = fmaxf(ma0, rm0), mn1 = fmaxf(ma1, rm1);
            float fac0 = __expf(ma0 - mn0), fac1 = __expf(ma1 - mn1);
            ma0 = mn0; ma1 = mn1;
            float rs0 = 0.f, rs1 = 0.f;
            #pragma unroll
            for (int nt = 0; nt < 8; nt++) {
                s0[nt][0] = __expf(s0[nt][0] - mn0);
                s0[nt][1] = __expf(s0[nt][1] - mn0);
                s0[nt][2] = __expf(s0[nt][2] - mn1);
                s0[nt][3] = __expf(s0[nt][3] - mn1);
                rs0 += s0[nt][0] + s0[nt][1];
                rs1 += s0[nt][2] + s0[nt][3];
            }
            rs0 += __shfl_xor_sync(0xffffffffu, rs0, 1);
            rs0 += __shfl_xor_sync(0xffffffffu, rs0, 2);
            rs1 += __shfl_xor_sync(0xffffffffu, rs1, 1);
            rs1 += __shfl_xor_sync(0xffffffffu, rs1, 2);
            la0 = la0 * fac0 + rs0;
            la1 = la1 * fac1 + rs1;
            #pragma unroll
            for (int dt = 0; dt < 8; dt++) {
                o0[dt][0] *= fac0; o0[dt][1] *= fac0;
                o0[dt][2] *= fac1; o0[dt][3] *= fac1;
            }
        }
        // ---- online softmax, tile b ----
        {
            float rm0 = -1e30f, rm1 = -1e30f;
            #pragma unroll
            for (int nt = 0; nt < 8; nt++) {
                rm0 = fmaxf(rm0, fmaxf(s1[nt][0], s1[nt][1]));
                rm1 = fmaxf(rm1, fmaxf(s1[nt][2], s1[nt][3]));
            }
            rm0 = fmaxf(rm0, __shfl_xor_sync(0xffffffffu, rm0, 1));
            rm0 = fmaxf(rm0, __shfl_xor_sync(0xffffffffu, rm0, 2));
            rm1 = fmaxf(rm1, __shfl_xor_sync(0xffffffffu, rm1, 1));
            rm1 = fmaxf(rm1, __shfl_xor_sync(0xffffffffu, rm1, 2));
            float mn0 = fmaxf(mb0, rm0), mn1 = fmaxf(mb1, rm1);
            float fac0 = __expf(mb0 - mn0), fac1 = __expf(mb1 - mn1);
            mb0 = mn0; mb1 = mn1;
            float rs0 = 0.f, rs1 = 0.f;
            #pragma unroll
            for (int nt = 0; nt < 8; nt++) {
                s1[nt][0] = __expf(s1[nt][0] - mn0);
                s1[nt][1] = __expf(s1[nt][1] - mn0);
                s1[nt][2] = __expf(s1[nt][2] - mn1);
                s1[nt][3] = __expf(s1[nt][3] - mn1);
                rs0 += s1[nt][0] + s1[nt][1];
                rs1 += s1[nt][2] + s1[nt][3];
            }
            rs0 += __shfl_xor_sync(0xffffffffu, rs0, 1);
            rs0 += __shfl_xor_sync(0xffffffffu, rs0, 2);
            rs1 += __shfl_xor_sync(0xffffffffu, rs1, 1);
            rs1 += __shfl_xor_sync(0xffffffffu, rs1, 2);
            lb0 = lb0 * fac0 + rs0;
            lb1 = lb1 * fac1 + rs1;
            #pragma unroll
            for (int dt = 0; dt < 8; dt++) {
                o1[dt][0] *= fac0; o1[dt][1] *= fac0;
                o1[dt][2] *= fac1; o1[dt][3] *= fac1;
            }
        }

        // ---- O += P @ V; interleave m-tiles for same-acc spacing ----
        #pragma unroll
        for (int kc = 0; kc < 4; kc++) {
            uint32_t ah0[4], al0[4], ah1[4], al1[4];
            split2(s0[2 * kc][0],     s0[2 * kc][1],     ah0[0], al0[0]);
            split2(s0[2 * kc][2],     s0[2 * kc][3],     ah0[1], al0[1]);
            split2(s0[2 * kc + 1][0], s0[2 * kc + 1][1], ah0[2], al0[2]);
            split2(s0[2 * kc + 1][2], s0[2 * kc + 1][3], ah0[3], al0[3]);
            split2(s1[2 * kc][0],     s1[2 * kc][1],     ah1[0], al1[0]);
            split2(s1[2 * kc][2],     s1[2 * kc][3],     ah1[1], al1[1]);
            split2(s1[2 * kc + 1][0], s1[2 * kc + 1][1], ah1[2], al1[2]);
            split2(s1[2 * kc + 1][2], s1[2 * kc + 1][3], ah1[3], al1[3]);
            int kb = (kc * 16 + 2 * tg) * 2;
            #pragma unroll
            for (int dt = 0; dt < 8; dt++) {
                const char* ph = bb + AT_VTH + (dt * 8 + g) * KROWB + kb;
                const char* pl = bb + AT_VTL + (dt * 8 + g) * KROWB + kb;
                uint32_t bhf[2] = {*(const uint32_t*)ph, *(const uint32_t*)(ph + 16)};
                uint32_t blf[2] = {*(const uint32_t*)pl, *(const uint32_t*)(pl + 16)};
                mma16816(o0[dt], ah0, bhf);
                mma16816(o1[dt], ah1, bhf);
                mma16816(o0[dt], al0, bhf);
                mma16816(o1[dt], al1, bhf);
                mma16816(o0[dt], ah0, blf);
                mma16816(o1[dt], ah1, blf);
            }
        }
        __syncthreads();
        if (i + 2 < 32) stage(i + 2);
    }

    // ---- epilogue ----
    {
        float inv0 = 1.0f / la0, inv1 = 1.0f / la1;
        size_t cb0 = ((size_t)(b * S_ + ra)) * INNER + h * DK;
        size_t cb1 = cb0 + (size_t)8 * INNER;
        #pragma unroll
        for (int dt = 0; dt < 8; dt++) {
            uint32_t hh, ll;
            split2(o0[dt][0] * inv0, o0[dt][1] * inv0, hh, ll);
            *(uint32_t*)&g_ctxhi[cb0 + dt * 8 + 2 * tg] = hh;
            *(uint32_t*)&g_ctxlo[cb0 + dt * 8 + 2 * tg] = ll;
            split2(o0[dt][2] * inv1, o0[dt][3] * inv1, hh, ll);
            *(uint32_t*)&g_ctxhi[cb1 + dt * 8 + 2 * tg] = hh;
            *(uint32_t*)&g_ctxlo[cb1 + dt * 8 + 2 * tg] = ll;
        }
    }
    {
        float inv0 = 1.0f / lb0, inv1 = 1.0f / lb1;
        size_t cb0 = ((size_t)(b * S_ + rb)) * INNER + h * DK;
        size_t cb1 = cb0 + (size_t)8 * INNER;
        #pragma unroll
        for (int dt = 0; dt < 8; dt++) {
            uint32_t hh, ll;
            split2(o1[dt][0] * inv0, o1[dt][1] * inv0, hh, ll);
            *(uint32_t*)&g_ctxhi[cb0 + dt * 8 + 2 * tg] = hh;
            *(uint32_t*)&g_ctxlo[cb0 + dt * 8 + 2 * tg] = ll;
            split2(o1[dt][2] * inv1, o1[dt][3] * inv1, hh, ll);
            *(uint32_t*)&g_ctxhi[cb1 + dt * 8 + 2 * tg] = hh;
            *(uint32_t*)&g_ctxlo[cb1 + dt * 8 + 2 * tg] = ll;
        }
    }
}

// ---------------- launch ----------------
extern "C" void kernel_launch(void* const* d_in, const int* in_sizes, int n_in,
                              void* d_out, int out_size) {
    const float* hidden    = (const float*)d_in[0];
    const int*   positions = (const int*)d_in[1];
    const float* mask      = (const float*)d_in[2];
    const float* wq        = (const float*)d_in[3];
    const float* wk        = (const float*)d_in[4];
    const float* wv        = (const float*)d_in[5];
    const float* wo        = (const float*)d_in[6];
    const float* rel_bias  = (const float*)d_in[7];
    float* out = (float*)d_out;

    cudaFuncSetAttribute(proj_mma, cudaFuncAttributeMaxDynamicSharedMemorySize, GDSMEM);
    cudaFuncSetAttribute(outproj_mma, cudaFuncAttributeMaxDynamicSharedMemorySize, GDSMEM);
    cudaFuncSetAttribute(attn_mma, cudaFuncAttributeMaxDynamicSharedMemorySize, AT_DSMEM);

    lut_kernel<<<1, 256>>>();
    int nb = B_ * S_ * S_;
    bucket_kernel<<<(nb + 255) / 256, 256>>>(positions);

    {
        __nv_bfloat16 *hh, *hl, *qh_, *ql_, *kh, *kl, *vh, *vl, *oh, *ol;
        cudaGetSymbolAddress((void**)&hh, g_hidhi);
        cudaGetSymbolAddress((void**)&hl, g_hidlo);
        cudaGetSymbolAddress((void**)&qh_, g_wqhi);
        cudaGetSymbolAddress((void**)&ql_, g_wqlo);
        cudaGetSymbolAddress((void**)&kh, g_wkhi);
        cudaGetSymbolAddress((void**)&kl, g_wklo);
        cudaGetSymbolAddress((void**)&vh, g_wvhi);
        cudaGetSymbolAddress((void**)&vl, g_wvlo);
        cudaGetSymbolAddress((void**)&oh, g_wohi);
        cudaGetSymbolAddress((void**)&ol, g_wolo);
        int nh4 = B_ * S_ * DM / 4;
        presplit_kernel<<<(nh4 + 255) / 256, 256>>>((const float4*)hidden, (uint2*)hh, (uint2*)hl, nh4);
        int nw4 = DM * DM / 4;
        presplit_kernel<<<(nw4 + 255) / 256, 256>>>((const float4*)wq, (uint2*)qh_, (uint2*)ql_, nw4);
        presplit_kernel<<<(nw4 + 255) / 256, 256>>>((const float4*)wk, (uint2*)kh, (uint2*)kl, nw4);
        presplit_kernel<<<(nw4 + 255) / 256, 256>>>((const float4*)wv, (uint2*)vh, (uint2*)vl, nw4);
        presplit_kernel<<<(nw4 + 255) / 256, 256>>>((const float4*)wo, (uint2*)oh, (uint2*)ol, nw4);
    }

    dim3 gproj(24, 64);
    proj_mma<<<gproj, 128, GDSMEM>>>();

    dim3 gattn(S_ / 128, NH, B_);
    attn_mma<<<gattn, 128, AT_DSMEM>>>(rel_bias, mask);

    dim3 gout(8, 64);
    outproj_mma<<<gout, 128, GDSMEM>>>(out);
}

// round 16
// speedup vs baseline: 1.1817x; 1.0290x over previous
#include <cuda_runtime.h>
#include <cuda_bf16.h>
#include <math.h>
#include <stdint.h>

#define B_    4
#define S_    2048
#define DM    1024
#define NH    16
#define DK    64
#define INNER 1024

// ---------------- scratch (static device globals; no allocation) ----------------
__device__ __align__(256) float g_q[(size_t)B_ * NH * S_ * DK];
__device__ __align__(256) __nv_bfloat16 g_khi[(size_t)B_ * NH * S_ * DK];
__device__ __align__(256) __nv_bfloat16 g_klo[(size_t)B_ * NH * S_ * DK];
__device__ __align__(256) __nv_bfloat16 g_vthi[(size_t)B_ * NH * DK * S_];
__device__ __align__(256) __nv_bfloat16 g_vtlo[(size_t)B_ * NH * DK * S_];
__device__ __align__(256) __nv_bfloat16 g_ctxhi[(size_t)B_ * S_ * INNER];
__device__ __align__(256) __nv_bfloat16 g_ctxlo[(size_t)B_ * S_ * INNER];
__device__ __align__(256) __nv_bfloat16 g_hidhi[(size_t)B_ * S_ * DM];
__device__ __align__(256) __nv_bfloat16 g_hidlo[(size_t)B_ * S_ * DM];
__device__ __align__(256) __nv_bfloat16 g_wqhi[(size_t)DM * DM], g_wqlo[(size_t)DM * DM];
__device__ __align__(256) __nv_bfloat16 g_wkhi[(size_t)DM * DM], g_wklo[(size_t)DM * DM];
__device__ __align__(256) __nv_bfloat16 g_wvhi[(size_t)DM * DM], g_wvlo[(size_t)DM * DM];
__device__ __align__(256) __nv_bfloat16 g_wohi[(size_t)DM * DM], g_wolo[(size_t)DM * DM];
__device__ unsigned char g_bucket[(size_t)B_ * S_ * S_];
__device__ unsigned char g_lutb[256];

// ================= helpers =================
__device__ __forceinline__ void mma16816(float* c, const uint32_t* a, const uint32_t* b) {
    asm volatile(
        "mma.sync.aligned.m16n8k16.row.col.f32.bf16.bf16.f32 "
        "{%0,%1,%2,%3}, {%4,%5,%6,%7}, {%8,%9}, {%0,%1,%2,%3};\n"
        : "+f"(c[0]), "+f"(c[1]), "+f"(c[2]), "+f"(c[3])
        : "r"(a[0]), "r"(a[1]), "r"(a[2]), "r"(a[3]), "r"(b[0]), "r"(b[1]));
}

__device__ __forceinline__ void ldm4(uint32_t* r, uint32_t a) {
    asm volatile("ldmatrix.sync.aligned.m8n8.x4.shared.b16 {%0,%1,%2,%3}, [%4];"
                 : "=r"(r[0]), "=r"(r[1]), "=r"(r[2]), "=r"(r[3]) : "r"(a));
}

__device__ __forceinline__ void split2(float x, float y, uint32_t& hi, uint32_t& lo) {
    __nv_bfloat162 h = __floats2bfloat162_rn(x, y);
    float rx = x - __bfloat162float(h.x);
    float ry = y - __bfloat162float(h.y);
    __nv_bfloat162 l = __floats2bfloat162_rn(rx, ry);
    hi = *(uint32_t*)&h;
    lo = *(uint32_t*)&l;
}

__device__ __forceinline__ uint32_t smem_u32(const void* p) {
    uint32_t a;
    asm("{ .reg .u64 t; cvta.to.shared.u64 t, %1; cvt.u32.u64 %0, t; }" : "=r"(a) : "l"(p));
    return a;
}
__device__ __forceinline__ void cp16(uint32_t dst, const void* src) {
    asm volatile("cp.async.ca.shared.global [%0], [%1], 16;" :: "r"(dst), "l"(src) : "memory");
}
#define CP_COMMIT() asm volatile("cp.async.commit_group;" ::: "memory")
#define CP_WAIT1()  asm volatile("cp.async.wait_group 1;" ::: "memory")
#define CP_WAIT0()  asm volatile("cp.async.wait_group 0;" ::: "memory")

// ================= bucket LUT + bucket (vectorized x4) =================
__global__ void lut_kernel() {
    int rp = threadIdx.x;
    int bucket;
    if (rp < 8) {
        bucket = rp;
    } else {
        float v = logf((float)rp * 0.125f);
        v = v / 2.772588722239781f;
        v = v * 8.0f;
        bucket = 8 + (int)v;
        bucket = bucket < 15 ? bucket : 15;
    }
    g_lutb[rp] = (unsigned char)bucket;
}

__global__ void bucket_kernel(const int* __restrict__ pos) {
    int t = blockIdx.x * blockDim.x + threadIdx.x;
    if (t >= B_ * S_ * S_ / 4) return;
    int kq = (t & (S_ / 4 - 1)) * 4;
    int q = (t >> 9) & (S_ - 1);
    int b = t >> 20;
    int pq = pos[b * S_ + q];
    int4 pk = *(const int4*)&pos[b * S_ + kq];
    uchar4 r;
    int rel, ret, rp;
    rel = pk.x - pq; ret = (rel > 0) ? 16 : 0; rp = rel < 0 ? -rel : rel;
    r.x = (unsigned char)(ret + g_lutb[rp < 256 ? rp : 255]);
    rel = pk.y - pq; ret = (rel > 0) ? 16 : 0; rp = rel < 0 ? -rel : rel;
    r.y = (unsigned char)(ret + g_lutb[rp < 256 ? rp : 255]);
    rel = pk.z - pq; ret = (rel > 0) ? 16 : 0; rp = rel < 0 ? -rel : rel;
    r.z = (unsigned char)(ret + g_lutb[rp < 256 ? rp : 255]);
    rel = pk.w - pq; ret = (rel > 0) ? 16 : 0; rp = rel < 0 ? -rel : rel;
    r.w = (unsigned char)(ret + g_lutb[rp < 256 ? rp : 255]);
    *(uchar4*)&g_bucket[((size_t)b * S_ + q) * S_ + kq] = r;
}

// ================= pre-split fp32 -> hi/lo bf16 =================
__global__ void presplit_kernel(const float4* __restrict__ src,
                                uint2* __restrict__ hi, uint2* __restrict__ lo, int n4) {
    int i = blockIdx.x * blockDim.x + threadIdx.x;
    if (i >= n4) return;
    float4 v = src[i];
    uint32_t h0, l0, h1, l1;
    split2(v.x, v.y, h0, l0);
    split2(v.z, v.w, h1, l1);
    uint2 uh = {h0, h1}, ul = {l0, l1};
    hi[i] = uh;
    lo[i] = ul;
}

// ================= bf16 double-buffered GEMM, 128 thr, warp tile 64x64 =========
#define RS 80
#define SA_HI 0
#define SA_LO 10240
#define SB_HI 20480
#define SB_LO 30720
#define STAGE 40960
#define GDSMEM (2 * STAGE)

__device__ __forceinline__ void gemm_stage(int c, uint32_t bufo, uint32_t sb,
                                           const __nv_bfloat16* Ahi, const __nv_bfloat16* Alo,
                                           const __nv_bfloat16* Bhi, const __nv_bfloat16* Blo,
                                           int m0, int n0, int tid) {
    int k0 = c * 32;
    #pragma unroll
    for (int j = 0; j < 4; j++) {
        int idx = tid + j * 128;
        int row = idx >> 2, q = idx & 3;
        size_t ga = (size_t)(m0 + row) * DM + k0 + q * 8;
        size_t gb = (size_t)(n0 + row) * DM + k0 + q * 8;
        uint32_t so = sb + bufo + row * RS + q * 16;
        cp16(so + SA_HI, Ahi + ga);
        cp16(so + SA_LO, Alo + ga);
        cp16(so + SB_HI, Bhi + gb);
        cp16(so + SB_LO, Blo + gb);
    }
    CP_COMMIT();
}

__device__ __forceinline__ void gemm_core(const __nv_bfloat16* Ahi, const __nv_bfloat16* Alo,
                                          const __nv_bfloat16* Bhi, const __nv_bfloat16* Blo,
                                          int m0, int n0, float acc[4][8][4], char* smem) {
    uint32_t sb = smem_u32(smem);
    int tid = threadIdx.x, lane = tid & 31, wid = tid >> 5;
    int wm = wid >> 1, wn = wid & 1;

    uint32_t aoff = (uint32_t)(wm * 64 + (lane & 15)) * RS + (lane >> 4) * 16;
    uint32_t boff = (uint32_t)(wn * 64 + ((lane >> 4) & 1) * 8 + (lane & 7)) * RS + ((lane >> 3) & 1) * 16;

    gemm_stage(0, 0, sb, Ahi, Alo, Bhi, Blo, m0, n0, tid);
    gemm_stage(1, STAGE, sb, Ahi, Alo, Bhi, Blo, m0, n0, tid);

    #pragma unroll 1
    for (int c = 0; c < 32; c++) {
        uint32_t bufo = (c & 1) * STAGE;
        if (c < 31) CP_WAIT1(); else CP_WAIT0();
        __syncthreads();
        uint32_t base = sb + bufo;
        #pragma unroll
        for (int kk = 0; kk < 2; kk++) {
            uint32_t ka = kk * 32;
            uint32_t bh[8][2], bl[8][2];
            #pragma unroll
            for (int p = 0; p < 4; p++) {
                uint32_t r[4];
                ldm4(r, base + SB_HI + boff + p * 16 * RS + ka);
                bh[2 * p][0] = r[0]; bh[2 * p][1] = r[1];
                bh[2 * p + 1][0] = r[2]; bh[2 * p + 1][1] = r[3];
                ldm4(r, base + SB_LO + boff + p * 16 * RS + ka);
                bl[2 * p][0] = r[0]; bl[2 * p][1] = r[1];
                bl[2 * p + 1][0] = r[2]; bl[2 * p + 1][1] = r[3];
            }
            #pragma unroll
            for (int mt = 0; mt < 4; mt++) {
                uint32_t ah[4], al[4];
                ldm4(ah, base + SA_HI + aoff + mt * 16 * RS + ka);
                ldm4(al, base + SA_LO + aoff + mt * 16 * RS + ka);
                #pragma unroll
                for (int nt = 0; nt < 8; nt++) mma16816(acc[mt][nt], ah, bh[nt]);
                #pragma unroll
                for (int nt = 0; nt < 8; nt++) mma16816(acc[mt][nt], al, bh[nt]);
                #pragma unroll
                for (int nt = 0; nt < 8; nt++) mma16816(acc[mt][nt], ah, bl[nt]);
            }
        }
        __syncthreads();
        if (c + 2 < 32) gemm_stage(c + 2, bufo, sb, Ahi, Alo, Bhi, Blo, m0, n0, tid);
    }
}

// QKV projection. grid (24, 64), 128 thr
__global__ __launch_bounds__(128, 2) void proj_mma() {
    extern __shared__ char smem[];
    int bx = blockIdx.x;
    int wsel = bx >> 3;
    int n0 = (bx & 7) * 128;
    int m0 = blockIdx.y * 128;
    const __nv_bfloat16* Bh = (wsel == 0) ? g_wqhi : (wsel == 1) ? g_wkhi : g_wvhi;
    const __nv_bfloat16* Bl = (wsel == 0) ? g_wqlo : (wsel == 1) ? g_wklo : g_wvlo;

    float acc[4][8][4] = {};
    gemm_core(g_hidhi, g_hidlo, Bh, Bl, m0, n0, acc, smem);

    int lane = threadIdx.x & 31, wid = threadIdx.x >> 5;
    int wm = wid >> 1, wn = wid & 1;
    int g = lane >> 2, tg = lane & 3;
    #pragma unroll
    for (int mt = 0; mt < 4; mt++) {
        #pragma unroll
        for (int nt = 0; nt < 8; nt++) {
            int r0 = m0 + wm * 64 + mt * 16 + g;
            int r1 = r0 + 8;
            int c = n0 + wn * 64 + nt * 8 + tg * 2;
            int h = c >> 6, d = c & 63;
            int b0 = r0 >> 11, s0 = r0 & (S_ - 1);
            int b1 = r1 >> 11, s1 = r1 & (S_ - 1);
            float a0 = acc[mt][nt][0], a1 = acc[mt][nt][1];
            float a2 = acc[mt][nt][2], a3 = acc[mt][nt][3];
            if (wsel == 0) {
                float2 v0 = {a0, a1};
                *(float2*)&g_q[(((size_t)(b0 * NH + h) * S_ + s0) << 6) + d] = v0;
                float2 v1 = {a2, a3};
                *(float2*)&g_q[(((size_t)(b1 * NH + h) * S_ + s1) << 6) + d] = v1;
            } else if (wsel == 1) {
                uint32_t h0, l0, h1, l1;
                split2(a0, a1, h0, l0);
                split2(a2, a3, h1, l1);
                size_t o0 = (((size_t)(b0 * NH + h) * S_ + s0) << 6) + d;
                size_t o1 = (((size_t)(b1 * NH + h) * S_ + s1) << 6) + d;
                *(uint32_t*)&g_khi[o0] = h0; *(uint32_t*)&g_klo[o0] = l0;
                *(uint32_t*)&g_khi[o1] = h1; *(uint32_t*)&g_klo[o1] = l1;
            } else {
                size_t base0 = ((size_t)(b0 * NH + h) * DK + d) * S_;
                size_t base1 = ((size_t)(b1 * NH + h) * DK + d) * S_;
                #pragma unroll
                for (int e = 0; e < 4; e++) {
                    float x = acc[mt][nt][e];
                    __nv_bfloat16 hh = __float2bfloat16(x);
                    __nv_bfloat16 ll = __float2bfloat16(x - __bfloat162float(hh));
                    size_t o = (e < 2 ? base0 + s0 : base1 + s1) + (size_t)(e & 1) * S_;
                    g_vthi[o] = hh;
                    g_vtlo[o] = ll;
                }
            }
        }
    }
}

// output projection. grid (8, 64), 128 thr
__global__ __launch_bounds__(128, 2) void outproj_mma(float* __restrict__ out) {
    extern __shared__ char smem[];
    int n0 = blockIdx.x * 128;
    int m0 = blockIdx.y * 128;

    float acc[4][8][4] = {};
    gemm_core(g_ctxhi, g_ctxlo, g_wohi, g_wolo, m0, n0, acc, smem);

    int lane = threadIdx.x & 31, wid = threadIdx.x >> 5;
    int wm = wid >> 1, wn = wid & 1;
    int g = lane >> 2, tg = lane & 3;
    #pragma unroll
    for (int mt = 0; mt < 4; mt++) {
        #pragma unroll
        for (int nt = 0; nt < 8; nt++) {
            int r0 = m0 + wm * 64 + mt * 16 + g;
            int c = n0 + wn * 64 + nt * 8 + tg * 2;
            float2 v0 = {acc[mt][nt][0], acc[mt][nt][1]};
            *(float2*)&out[(size_t)r0 * DM + c] = v0;
            float2 v1 = {acc[mt][nt][2], acc[mt][nt][3]};
            *(float2*)&out[(size_t)(r0 + 8) * DM + c] = v1;
        }
    }
}

// ===== tensor-core flash attention: 128 thr, q-tile 128, ldmatrix fragment loads =====
#define KROWB 144
#define AT_KHI 0
#define AT_KLO 9216
#define AT_VTH 18432
#define AT_VTL 27648
#define AT_BUK 36864
#define BUKRS 80
#define ATSTAGE (36864 + 128 * BUKRS)
#define AT_MCL (2 * ATSTAGE)
#define AT_RBH (AT_MCL + 512)
#define AT_DSMEM (AT_RBH + 128)

__global__ __launch_bounds__(128, 2) void attn_mma(const float* __restrict__ rel_bias,
                                                   const float* __restrict__ mask) {
    extern __shared__ char sm[];
    float* rbh = (float*)(sm + AT_RBH);
    uint32_t sb = smem_u32(sm);

    int tid = threadIdx.x, lane = tid & 31, wrp = tid >> 5;
    int g = lane >> 2, tg = lane & 3;
    int q0 = blockIdx.x * 128, h = blockIdx.y, b = blockIdx.z;

    const __nv_bfloat16* khi = g_khi + (size_t)(b * NH + h) * S_ * DK;
    const __nv_bfloat16* klo = g_klo + (size_t)(b * NH + h) * S_ * DK;
    const __nv_bfloat16* vth = g_vthi + (size_t)(b * NH + h) * DK * S_;
    const __nv_bfloat16* vtl = g_vtlo + (size_t)(b * NH + h) * DK * S_;
    const float* maskp = mask + b * S_;
    const unsigned char* bukp = g_bucket + ((size_t)b * S_ + q0) * S_;

    if (tid < 32) rbh[tid] = rel_bias[tid * NH + h];

    auto stage = [&](int i) {
        int k0 = i * 64;
        uint32_t bufo = (i & 1) * ATSTAGE;
        #pragma unroll
        for (int j = 0; j < 4; j++) {
            int idx = tid + j * 128;
            int r = idx >> 3, q = idx & 7;
            uint32_t so = sb + bufo + r * KROWB + q * 16;
            cp16(so + AT_KHI, khi + (size_t)(k0 + r) * DK + q * 8);
            cp16(so + AT_KLO, klo + (size_t)(k0 + r) * DK + q * 8);
            cp16(so + AT_VTH, vth + (size_t)r * S_ + k0 + q * 8);
            cp16(so + AT_VTL, vtl + (size_t)r * S_ + k0 + q * 8);
        }
        #pragma unroll
        for (int j = 0; j < 4; j++) {
            int idx = tid + j * 128;
            int r = idx >> 2, qq = idx & 3;
            cp16(sb + bufo + AT_BUK + r * BUKRS + qq * 16, bukp + (size_t)r * S_ + k0 + qq * 16);
        }
        if (tid < 16) cp16(sb + AT_MCL + (i & 1) * 256 + tid * 16, maskp + k0 + tid * 4);
        CP_COMMIT();
    };

    // Q fragments (hi/lo) in registers for two m16 tiles: rows ra, ra+8, rb, rb+8
    int ra = q0 + wrp * 32 + g;
    int rb = ra + 16;
    const float* qpa = g_q + ((size_t)(b * NH + h) * S_ + ra) * DK;
    const float* qpb = g_q + ((size_t)(b * NH + h) * S_ + rb) * DK;
    uint32_t qh0[4][4], ql0[4][4], qh1[4][4], ql1[4][4];
    #pragma unroll
    for (int kc = 0; kc < 4; kc++) {
        int c = kc * 16 + 2 * tg;
        float2 v;
        v = *(const float2*)&qpa[c];            split2(v.x, v.y, qh0[kc][0], ql0[kc][0]);
        v = *(const float2*)&qpa[8 * DK + c];   split2(v.x, v.y, qh0[kc][1], ql0[kc][1]);
        v = *(const float2*)&qpa[c + 8];        split2(v.x, v.y, qh0[kc][2], ql0[kc][2]);
        v = *(const float2*)&qpa[8 * DK + c + 8]; split2(v.x, v.y, qh0[kc][3], ql0[kc][3]);
        v = *(const float2*)&qpb[c];            split2(v.x, v.y, qh1[kc][0], ql1[kc][0]);
        v = *(const float2*)&qpb[8 * DK + c];   split2(v.x, v.y, qh1[kc][1], ql1[kc][1]);
        v = *(const float2*)&qpb[c + 8];        split2(v.x, v.y, qh1[kc][2], ql1[kc][2]);
        v = *(const float2*)&qpb[8 * DK + c + 8]; split2(v.x, v.y, qh1[kc][3], ql1[kc][3]);
    }

    float o0[8][4] = {}, o1[8][4] = {};
    float ma0 = -1e30f, ma1 = -1e30f, la0 = 0.f, la1 = 0.f;
    float mb0 = -1e30f, mb1 = -1e30f, lb0 = 0.f, lb1 = 0.f;

    stage(0);
    stage(1);

    int rowa = wrp * 32 + g;
    // ldmatrix per-thread offset for K/V B-operand pairs (validated in R6)
    uint32_t koff = (uint32_t)(((lane >> 4) & 1) * 8 + (lane & 7)) * KROWB + ((lane >> 3) & 1) * 16;

    #pragma unroll 1
    for (int i = 0; i < 32; i++) {
        uint32_t bufo = (i & 1) * ATSTAGE;
        if (i < 31) CP_WAIT1(); else CP_WAIT0();
        __syncthreads();
        uint32_t base = sb + bufo;
        const float* mclf = (const float*)(sm + AT_MCL + (i & 1) * 256);
        const char* bkt = sm + bufo + AT_BUK;

        // ---- S = Q @ K^T; ldm4 fragment loads, m-tiles interleaved ----
        float s0[8][4] = {}, s1[8][4] = {};
        #pragma unroll
        for (int kc = 0; kc < 4; kc++) {
            uint32_t ka = kc * 32;
            #pragma unroll
            for (int p = 0; p < 4; p++) {
                uint32_t rh[4], rl[4];
                ldm4(rh, base + AT_KHI + koff + p * 16 * KROWB + ka);
                ldm4(rl, base + AT_KLO + koff + p * 16 * KROWB + ka);
                uint32_t bh0[2] = {rh[0], rh[1]}, bh1[2] = {rh[2], rh[3]};
                uint32_t bl0[2] = {rl[0], rl[1]}, bl1[2] = {rl[2], rl[3]};
                int n0t = 2 * p, n1t = 2 * p + 1;
                mma16816(s0[n0t], qh0[kc], bh0);
                mma16816(s1[n0t], qh1[kc], bh0);
                mma16816(s0[n1t], qh0[kc], bh1);
                mma16816(s1[n1t], qh1[kc], bh1);
                mma16816(s0[n0t], ql0[kc], bh0);
                mma16816(s1[n0t], ql1[kc], bh0);
                mma16816(s0[n1t], ql0[kc], bh1);
                mma16816(s1[n1t], ql1[kc], bh1);
                mma16816(s0[n0t], qh0[kc], bl0);
                mma16816(s1[n0t], qh1[kc], bl0);
                mma16816(s0[n1t], qh0[kc], bl1);
                mma16816(s1[n1t], qh1[kc], bl1);
            }
        }

        // ---- bias ----
        #pragma unroll
        for (int nt = 0; nt < 8; nt++) {
            int col = nt * 8 + 2 * tg;
            float mv0 = mclf[nt * 8 + 2 * tg], mv1 = mclf[nt * 8 + 2 * tg + 1];
            float mc0 = -1000.0f + 1000.0f * mv0;
            float mc1 = -1000.0f + 1000.0f * mv1;
            uchar2 ua0 = *(const uchar2*)(bkt + (rowa) * BUKRS + col);
            uchar2 ua1 = *(const uchar2*)(bkt + (rowa + 8) * BUKRS + col);
            s0[nt][0] += rbh[ua0.x] + mc0;
            s0[nt][1] += rbh[ua0.y] + mc1;
            s0[nt][2] += rbh[ua1.x] + mc0;
            s0[nt][3] += rbh[ua1.y] + mc1;
            uchar2 ub0 = *(const uchar2*)(bkt + (rowa + 16) * BUKRS + col);
            uchar2 ub1 = *(const uchar2*)(bkt + (rowa + 24) * BUKRS + col);
            s1[nt][0] += rbh[ub0.x] + mc0;
            s1[nt][1] += rbh[ub0.y] + mc1;
            s1[nt][2] += rbh[ub1.x] + mc0;
            s1[nt][3] += rbh[ub1.y] + mc1;
        }

        // ---- online softmax, tile a ----
        {
            float rm0 = -1e30f, rm1 = -1e30f;
            #pragma unroll
            for (int nt = 0; nt < 8; nt++) {
                rm0 = fmaxf(rm0, fmaxf(s0[nt][0], s0[nt][1]));
                rm1 = fmaxf(rm1, fmaxf(s0[nt][2], s0[nt][3]));
            }
            rm0 = fmaxf(rm0, __shfl_xor_sync(0xffffffffu, rm0, 1));
            rm0 = fmaxf(rm0, __shfl_xor_sync(0xffffffffu, rm0, 2));
            rm1 = fmaxf(rm1, __shfl_xor_sync(0xffffffffu, rm1, 1));
            rm1 = fmaxf(rm1, __shfl_xor_sync(0xffffffffu, rm1, 2));
            float mn0 = fmaxf(ma0, rm0), mn1 = fmaxf(ma1, rm1);
            float fac0 = __expf(ma0 - mn0), fac1 = __expf(ma1 - mn1);
            ma0 = mn0; ma1 = mn1;
            float rs0 = 0.f, rs1 = 0.f;
            #pragma unroll
            for (int nt = 0; nt < 8; nt++) {
                s0[nt][0] = __expf(s0[nt][0] - mn0);
                s0[nt][1] = __expf(s0[nt][1] - mn0);
                s0[nt][2] = __expf(s0[nt][2] - mn1);
                s0[nt][3] = __expf(s0[nt][3] - mn1);
                rs0 += s0[nt][0] + s0[nt][1];
                rs1 += s0[nt][2] + s0[nt][3];
            }
            rs0 += __shfl_xor_sync(0xffffffffu, rs0, 1);
            rs0 += __shfl_xor_sync(0xffffffffu, rs0, 2);
            rs1 += __shfl_xor_sync(0xffffffffu, rs1, 1);
            rs1 += __shfl_xor_sync(0xffffffffu, rs1, 2);
            la0 = la0 * fac0 + rs0;
            la1 = la1 * fac1 + rs1;
            #pragma unroll
            for (int dt = 0; dt < 8; dt++) {
                o0[dt][0] *= fac0; o0[dt][1] *= fac0;
                o0[dt][2] *= fac1; o0[dt][3] *= fac1;
            }
        }
        // ---- online softmax, tile b ----
        {
            float rm0 = -1e30f, rm1 = -1e30f;
            #pragma unroll
            for (int nt = 0; nt < 8; nt++) {
                rm0 = fmaxf(rm0, fmaxf(s1[nt][0], s1[nt][1]));
                rm1 = fmaxf(rm1, fmaxf(s1[nt][2], s1[nt][3]));
            }
            rm0 = fmaxf(rm0, __shfl_xor_sync(0xffffffffu, rm0, 1));
            rm0 = fmaxf(rm0, __shfl_xor_sync(0xffffffffu, rm0, 2));
            rm1 = fmaxf(rm1, __shfl_xor_sync(0xffffffffu, rm1, 1));
            rm1 = fmaxf(rm1, __shfl_xor_sync(0xffffffffu, rm1, 2));
            float mn0 = fmaxf(mb0, rm0), mn1 = fmaxf(mb1, rm1);
            float fac0 = __expf(mb0 - mn0), fac1 = __expf(mb1 - mn1);
            mb0 = mn0; mb1 = mn1;
            float rs0 = 0.f, rs1 = 0.f;
            #pragma unroll
            for (int nt = 0; nt < 8; nt++) {
                s1[nt][0] = __expf(s1[nt][0] - mn0);
                s1[nt][1] = __expf(s1[nt][1] - mn0);
                s1[nt][2] = __expf(s1[nt][2] - mn1);
                s1[nt][3] = __expf(s1[nt][3] - mn1);
                rs0 += s1[nt][0] + s1[nt][1];
                rs1 += s1[nt][2] + s1[nt][3];
            }
            rs0 += __shfl_xor_sync(0xffffffffu, rs0, 1);
            rs0 += __shfl_xor_sync(0xffffffffu, rs0, 2);
            rs1 += __shfl_xor_sync(0xffffffffu, rs1, 1);
            rs1 += __shfl_xor_sync(0xffffffffu, rs1, 2);
            lb0 = lb0 * fac0 + rs0;
            lb1 = lb1 * fac1 + rs1;
            #pragma unroll
            for (int dt = 0; dt < 8; dt++) {
                o1[dt][0] *= fac0; o1[dt][1] *= fac0;
                o1[dt][2] *= fac1; o1[dt][3] *= fac1;
            }
        }

        // ---- O += P @ V; ldm4 fragment loads, m-tiles interleaved ----
        #pragma unroll
        for (int kc = 0; kc < 4; kc++) {
            uint32_t ah0[4], al0[4], ah1[4], al1[4];
            split2(s0[2 * kc][0],     s0[2 * kc][1],     ah0[0], al0[0]);
            split2(s0[2 * kc][2],     s0[2 * kc][3],     ah0[1], al0[1]);
            split2(s0[2 * kc + 1][0], s0[2 * kc + 1][1], ah0[2], al0[2]);
            split2(s0[2 * kc + 1][2], s0[2 * kc + 1][3], ah0[3], al0[3]);
            split2(s1[2 * kc][0],     s1[2 * kc][1],     ah1[0], al1[0]);
            split2(s1[2 * kc][2],     s1[2 * kc][3],     ah1[1], al1[1]);
            split2(s1[2 * kc + 1][0], s1[2 * kc + 1][1], ah1[2], al1[2]);
            split2(s1[2 * kc + 1][2], s1[2 * kc + 1][3], ah1[3], al1[3]);
            uint32_t ka = kc * 32;
            #pragma unroll
            for (int p = 0; p < 4; p++) {
                uint32_t rh[4], rl[4];
                ldm4(rh, base + AT_VTH + koff + p * 16 * KROWB + ka);
                ldm4(rl, base + AT_VTL + koff + p * 16 * KROWB + ka);
                uint32_t vh0[2] = {rh[0], rh[1]}, vh1[2] = {rh[2], rh[3]};
                uint32_t vl0[2] = {rl[0], rl[1]}, vl1[2] = {rl[2], rl[3]};
                int d0 = 2 * p, d1 = 2 * p + 1;
                mma16816(o0[d0], ah0, vh0);
                mma16816(o1[d0], ah1, vh0);
                mma16816(o0[d1], ah0, vh1);
                mma16816(o1[d1], ah1, vh1);
                mma16816(o0[d0], al0, vh0);
                mma16816(o1[d0], al1, vh0);
                mma16816(o0[d1], al0, vh1);
                mma16816(o1[d1], al1, vh1);
                mma16816(o0[d0], ah0, vl0);
                mma16816(o1[d0], ah1, vl0);
                mma16816(o0[d1], ah0, vl1);
                mma16816(o1[d1], ah1, vl1);
            }
        }
        __syncthreads();
        if (i + 2 < 32) stage(i + 2);
    }

    // ---- epilogue ----
    {
        float inv0 = 1.0f / la0, inv1 = 1.0f / la1;
        size_t cb0 = ((size_t)(b * S_ + ra)) * INNER + h * DK;
        size_t cb1 = cb0 + (size_t)8 * INNER;
        #pragma unroll
        for (int dt = 0; dt < 8; dt++) {
            uint32_t hh, ll;
            split2(o0[dt][0] * inv0, o0[dt][1] * inv0, hh, ll);
            *(uint32_t*)&g_ctxhi[cb0 + dt * 8 + 2 * tg] = hh;
            *(uint32_t*)&g_ctxlo[cb0 + dt * 8 + 2 * tg] = ll;
            split2(o0[dt][2] * inv1, o0[dt][3] * inv1, hh, ll);
            *(uint32_t*)&g_ctxhi[cb1 + dt * 8 + 2 * tg] = hh;
            *(uint32_t*)&g_ctxlo[cb1 + dt * 8 + 2 * tg] = ll;
        }
    }
    {
        float inv0 = 1.0f / lb0, inv1 = 1.0f / lb1;
        size_t cb0 = ((size_t)(b * S_ + rb)) * INNER + h * DK;
        size_t cb1 = cb0 + (size_t)8 * INNER;
        #pragma unroll
        for (int dt = 0; dt < 8; dt++) {
            uint32_t hh, ll;
            split2(o1[dt][0] * inv0, o1[dt][1] * inv0, hh, ll);
            *(uint32_t*)&g_ctxhi[cb0 + dt * 8 + 2 * tg] = hh;
            *(uint32_t*)&g_ctxlo[cb0 + dt * 8 + 2 * tg] = ll;
            split2(o1[dt][2] * inv1, o1[dt][3] * inv1, hh, ll);
            *(uint32_t*)&g_ctxhi[cb1 + dt * 8 + 2 * tg] = hh;
            *(uint32_t*)&g_ctxlo[cb1 + dt * 8 + 2 * tg] = ll;
        }
    }
}

// ---------------- launch ----------------
extern "C" void kernel_launch(void* const* d_in, const int* in_sizes, int n_in,
                              void* d_out, int out_size) {
    const float* hidden    = (const float*)d_in[0];
    const int*   positions = (const int*)d_in[1];
    const float* mask      = (const float*)d_in[2];
    const float* wq        = (const float*)d_in[3];
    const float* wk        = (const float*)d_in[4];
    const float* wv        = (const float*)d_in[5];
    const float* wo        = (const float*)d_in[6];
    const float* rel_bias  = (const float*)d_in[7];
    float* out = (float*)d_out;

    cudaFuncSetAttribute(proj_mma, cudaFuncAttributeMaxDynamicSharedMemorySize, GDSMEM);
    cudaFuncSetAttribute(outproj_mma, cudaFuncAttributeMaxDynamicSharedMemorySize, GDSMEM);
    cudaFuncSetAttribute(attn_mma, cudaFuncAttributeMaxDynamicSharedMemorySize, AT_DSMEM);

    lut_kernel<<<1, 256>>>();
    int nb4 = B_ * S_ * S_ / 4;
    bucket_kernel<<<(nb4 + 255) / 256, 256>>>(positions);

    {
        __nv_bfloat16 *hh, *hl, *qh_, *ql_, *kh, *kl, *vh, *vl, *oh, *ol;
        cudaGetSymbolAddress((void**)&hh, g_hidhi);
        cudaGetSymbolAddress((void**)&hl, g_hidlo);
        cudaGetSymbolAddress((void**)&qh_, g_wqhi);
        cudaGetSymbolAddress((void**)&ql_, g_wqlo);
        cudaGetSymbolAddress((void**)&kh, g_wkhi);
        cudaGetSymbolAddress((void**)&kl, g_wklo);
        cudaGetSymbolAddress((void**)&vh, g_wvhi);
        cudaGetSymbolAddress((void**)&vl, g_wvlo);
        cudaGetSymbolAddress((void**)&oh, g_wohi);
        cudaGetSymbolAddress((void**)&ol, g_wolo);
        int nh4 = B_ * S_ * DM / 4;
        presplit_kernel<<<(nh4 + 255) / 256, 256>>>((const float4*)hidden, (uint2*)hh, (uint2*)hl, nh4);
        int nw4 = DM * DM / 4;
        presplit_kernel<<<(nw4 + 255) / 256, 256>>>((const float4*)wq, (uint2*)qh_, (uint2*)ql_, nw4);
        presplit_kernel<<<(nw4 + 255) / 256, 256>>>((const float4*)wk, (uint2*)kh, (uint2*)kl, nw4);
        presplit_kernel<<<(nw4 + 255) / 256, 256>>>((const float4*)wv, (uint2*)vh, (uint2*)vl, nw4);
        presplit_kernel<<<(nw4 + 255) / 256, 256>>>((const float4*)wo, (uint2*)oh, (uint2*)ol, nw4);
    }

    dim3 gproj(24, 64);
    proj_mma<<<gproj, 128, GDSMEM>>>();

    dim3 gattn(S_ / 128, NH, B_);
    attn_mma<<<gattn, 128, AT_DSMEM>>>(rel_bias, mask);

    dim3 gout(8, 64);
    outproj_mma<<<gout, 128, GDSMEM>>>(out);
}

// round 17
// speedup vs baseline: 1.2776x; 1.0811x over previous
#include <cuda_runtime.h>
#include <cuda_bf16.h>
#include <math.h>
#include <stdint.h>

#define B_    4
#define S_    2048
#define DM    1024
#define NH    16
#define DK    64
#define INNER 1024

// ---------------- scratch (static device globals; no allocation) ----------------
__device__ __align__(256) float g_q[(size_t)B_ * NH * S_ * DK];
__device__ __align__(256) __nv_bfloat16 g_khi[(size_t)B_ * NH * S_ * DK];
__device__ __align__(256) __nv_bfloat16 g_klo[(size_t)B_ * NH * S_ * DK];
__device__ __align__(256) __nv_bfloat16 g_vthi[(size_t)B_ * NH * DK * S_];
__device__ __align__(256) __nv_bfloat16 g_vtlo[(size_t)B_ * NH * DK * S_];
__device__ __align__(256) __nv_bfloat16 g_ctxhi[(size_t)B_ * S_ * INNER];
__device__ __align__(256) __nv_bfloat16 g_ctxlo[(size_t)B_ * S_ * INNER];
__device__ __align__(256) __nv_bfloat16 g_hidhi[(size_t)B_ * S_ * DM];
__device__ __align__(256) __nv_bfloat16 g_hidlo[(size_t)B_ * S_ * DM];
__device__ __align__(256) __nv_bfloat16 g_wqhi[(size_t)DM * DM], g_wqlo[(size_t)DM * DM];
__device__ __align__(256) __nv_bfloat16 g_wkhi[(size_t)DM * DM], g_wklo[(size_t)DM * DM];
__device__ __align__(256) __nv_bfloat16 g_wvhi[(size_t)DM * DM], g_wvlo[(size_t)DM * DM];
__device__ __align__(256) __nv_bfloat16 g_wohi[(size_t)DM * DM], g_wolo[(size_t)DM * DM];
__device__ unsigned char g_bucket[(size_t)B_ * S_ * S_];
__device__ unsigned char g_lutb[256];

// ================= helpers =================
__device__ __forceinline__ void mma16816(float* c, const uint32_t* a, const uint32_t* b) {
    asm volatile(
        "mma.sync.aligned.m16n8k16.row.col.f32.bf16.bf16.f32 "
        "{%0,%1,%2,%3}, {%4,%5,%6,%7}, {%8,%9}, {%0,%1,%2,%3};\n"
        : "+f"(c[0]), "+f"(c[1]), "+f"(c[2]), "+f"(c[3])
        : "r"(a[0]), "r"(a[1]), "r"(a[2]), "r"(a[3]), "r"(b[0]), "r"(b[1]));
}

__device__ __forceinline__ void ldm4(uint32_t* r, uint32_t a) {
    asm volatile("ldmatrix.sync.aligned.m8n8.x4.shared.b16 {%0,%1,%2,%3}, [%4];"
                 : "=r"(r[0]), "=r"(r[1]), "=r"(r[2]), "=r"(r[3]) : "r"(a));
}

__device__ __forceinline__ void split2(float x, float y, uint32_t& hi, uint32_t& lo) {
    __nv_bfloat162 h = __floats2bfloat162_rn(x, y);
    float rx = x - __bfloat162float(h.x);
    float ry = y - __bfloat162float(h.y);
    __nv_bfloat162 l = __floats2bfloat162_rn(rx, ry);
    hi = *(uint32_t*)&h;
    lo = *(uint32_t*)&l;
}

__device__ __forceinline__ uint32_t smem_u32(const void* p) {
    uint32_t a;
    asm("{ .reg .u64 t; cvta.to.shared.u64 t, %1; cvt.u32.u64 %0, t; }" : "=r"(a) : "l"(p));
    return a;
}
__device__ __forceinline__ void cp16(uint32_t dst, const void* src) {
    asm volatile("cp.async.ca.shared.global [%0], [%1], 16;" :: "r"(dst), "l"(src) : "memory");
}
#define CP_COMMIT() asm volatile("cp.async.commit_group;" ::: "memory")
#define CP_WAIT1()  asm volatile("cp.async.wait_group 1;" ::: "memory")
#define CP_WAIT0()  asm volatile("cp.async.wait_group 0;" ::: "memory")

// ================= bucket LUT + bucket (vectorized x4) =================
__global__ void lut_kernel() {
    int rp = threadIdx.x;
    int bucket;
    if (rp < 8) {
        bucket = rp;
    } else {
        float v = logf((float)rp * 0.125f);
        v = v / 2.772588722239781f;
        v = v * 8.0f;
        bucket = 8 + (int)v;
        bucket = bucket < 15 ? bucket : 15;
    }
    g_lutb[rp] = (unsigned char)bucket;
}

__global__ void bucket_kernel(const int* __restrict__ pos) {
    int t = blockIdx.x * blockDim.x + threadIdx.x;
    if (t >= B_ * S_ * S_ / 4) return;
    int kq = (t & (S_ / 4 - 1)) * 4;
    int q = (t >> 9) & (S_ - 1);
    int b = t >> 20;
    int pq = pos[b * S_ + q];
    int4 pk = *(const int4*)&pos[b * S_ + kq];
    uchar4 r;
    int rel, ret, rp;
    rel = pk.x - pq; ret = (rel > 0) ? 16 : 0; rp = rel < 0 ? -rel : rel;
    r.x = (unsigned char)(ret + g_lutb[rp < 256 ? rp : 255]);
    rel = pk.y - pq; ret = (rel > 0) ? 16 : 0; rp = rel < 0 ? -rel : rel;
    r.y = (unsigned char)(ret + g_lutb[rp < 256 ? rp : 255]);
    rel = pk.z - pq; ret = (rel > 0) ? 16 : 0; rp = rel < 0 ? -rel : rel;
    r.z = (unsigned char)(ret + g_lutb[rp < 256 ? rp : 255]);
    rel = pk.w - pq; ret = (rel > 0) ? 16 : 0; rp = rel < 0 ? -rel : rel;
    r.w = (unsigned char)(ret + g_lutb[rp < 256 ? rp : 255]);
    *(uchar4*)&g_bucket[((size_t)b * S_ + q) * S_ + kq] = r;
}

// ================= pre-split fp32 -> hi/lo bf16 =================
__global__ void presplit_kernel(const float4* __restrict__ src,
                                uint2* __restrict__ hi, uint2* __restrict__ lo, int n4) {
    int i = blockIdx.x * blockDim.x + threadIdx.x;
    if (i >= n4) return;
    float4 v = src[i];
    uint32_t h0, l0, h1, l1;
    split2(v.x, v.y, h0, l0);
    split2(v.z, v.w, h1, l1);
    uint2 uh = {h0, h1}, ul = {l0, l1};
    hi[i] = uh;
    lo[i] = ul;
}

// ================= bf16 double-buffered GEMM, 128 thr, warp tile 64x64 =========
#define RS 80
#define SA_HI 0
#define SA_LO 10240
#define SB_HI 20480
#define SB_LO 30720
#define STAGE 40960
#define GDSMEM (2 * STAGE)

__device__ __forceinline__ void gemm_stage(int c, uint32_t bufo, uint32_t sb,
                                           const __nv_bfloat16* Ahi, const __nv_bfloat16* Alo,
                                           const __nv_bfloat16* Bhi, const __nv_bfloat16* Blo,
                                           int m0, int n0, int tid) {
    int k0 = c * 32;
    #pragma unroll
    for (int j = 0; j < 4; j++) {
        int idx = tid + j * 128;
        int row = idx >> 2, q = idx & 3;
        size_t ga = (size_t)(m0 + row) * DM + k0 + q * 8;
        size_t gb = (size_t)(n0 + row) * DM + k0 + q * 8;
        uint32_t so = sb + bufo + row * RS + q * 16;
        cp16(so + SA_HI, Ahi + ga);
        cp16(so + SA_LO, Alo + ga);
        cp16(so + SB_HI, Bhi + gb);
        cp16(so + SB_LO, Blo + gb);
    }
    CP_COMMIT();
}

__device__ __forceinline__ void gemm_core(const __nv_bfloat16* Ahi, const __nv_bfloat16* Alo,
                                          const __nv_bfloat16* Bhi, const __nv_bfloat16* Blo,
                                          int m0, int n0, float acc[4][8][4], char* smem) {
    uint32_t sb = smem_u32(smem);
    int tid = threadIdx.x, lane = tid & 31, wid = tid >> 5;
    int wm = wid >> 1, wn = wid & 1;

    uint32_t aoff = (uint32_t)(wm * 64 + (lane & 15)) * RS + (lane >> 4) * 16;
    uint32_t boff = (uint32_t)(wn * 64 + ((lane >> 4) & 1) * 8 + (lane & 7)) * RS + ((lane >> 3) & 1) * 16;

    gemm_stage(0, 0, sb, Ahi, Alo, Bhi, Blo, m0, n0, tid);
    gemm_stage(1, STAGE, sb, Ahi, Alo, Bhi, Blo, m0, n0, tid);

    #pragma unroll 1
    for (int c = 0; c < 32; c++) {
        uint32_t bufo = (c & 1) * STAGE;
        if (c < 31) CP_WAIT1(); else CP_WAIT0();
        __syncthreads();
        uint32_t base = sb + bufo;
        #pragma unroll
        for (int kk = 0; kk < 2; kk++) {
            uint32_t ka = kk * 32;
            uint32_t bh[8][2], bl[8][2];
            #pragma unroll
            for (int p = 0; p < 4; p++) {
                uint32_t r[4];
                ldm4(r, base + SB_HI + boff + p * 16 * RS + ka);
                bh[2 * p][0] = r[0]; bh[2 * p][1] = r[1];
                bh[2 * p + 1][0] = r[2]; bh[2 * p + 1][1] = r[3];
                ldm4(r, base + SB_LO + boff + p * 16 * RS + ka);
                bl[2 * p][0] = r[0]; bl[2 * p][1] = r[1];
                bl[2 * p + 1][0] = r[2]; bl[2 * p + 1][1] = r[3];
            }
            #pragma unroll
            for (int mt = 0; mt < 4; mt++) {
                uint32_t ah[4], al[4];
                ldm4(ah, base + SA_HI + aoff + mt * 16 * RS + ka);
                ldm4(al, base + SA_LO + aoff + mt * 16 * RS + ka);
                #pragma unroll
                for (int nt = 0; nt < 8; nt++) mma16816(acc[mt][nt], ah, bh[nt]);
                #pragma unroll
                for (int nt = 0; nt < 8; nt++) mma16816(acc[mt][nt], al, bh[nt]);
                #pragma unroll
                for (int nt = 0; nt < 8; nt++) mma16816(acc[mt][nt], ah, bl[nt]);
            }
        }
        __syncthreads();
        if (c + 2 < 32) gemm_stage(c + 2, bufo, sb, Ahi, Alo, Bhi, Blo, m0, n0, tid);
    }
}

// QKV projection. grid (24, 64), 128 thr
__global__ __launch_bounds__(128, 2) void proj_mma() {
    extern __shared__ char smem[];
    int bx = blockIdx.x;
    int wsel = bx >> 3;
    int n0 = (bx & 7) * 128;
    int m0 = blockIdx.y * 128;
    const __nv_bfloat16* Bh = (wsel == 0) ? g_wqhi : (wsel == 1) ? g_wkhi : g_wvhi;
    const __nv_bfloat16* Bl = (wsel == 0) ? g_wqlo : (wsel == 1) ? g_wklo : g_wvlo;

    float acc[4][8][4] = {};
    gemm_core(g_hidhi, g_hidlo, Bh, Bl, m0, n0, acc, smem);

    int lane = threadIdx.x & 31, wid = threadIdx.x >> 5;
    int wm = wid >> 1, wn = wid & 1;
    int g = lane >> 2, tg = lane & 3;
    #pragma unroll
    for (int mt = 0; mt < 4; mt++) {
        #pragma unroll
        for (int nt = 0; nt < 8; nt++) {
            int r0 = m0 + wm * 64 + mt * 16 + g;
            int r1 = r0 + 8;
            int c = n0 + wn * 64 + nt * 8 + tg * 2;
            int h = c >> 6, d = c & 63;
            int b0 = r0 >> 11, s0 = r0 & (S_ - 1);
            int b1 = r1 >> 11, s1 = r1 & (S_ - 1);
            float a0 = acc[mt][nt][0], a1 = acc[mt][nt][1];
            float a2 = acc[mt][nt][2], a3 = acc[mt][nt][3];
            if (wsel == 0) {
                float2 v0 = {a0, a1};
                *(float2*)&g_q[(((size_t)(b0 * NH + h) * S_ + s0) << 6) + d] = v0;
                float2 v1 = {a2, a3};
                *(float2*)&g_q[(((size_t)(b1 * NH + h) * S_ + s1) << 6) + d] = v1;
            } else if (wsel == 1) {
                uint32_t h0, l0, h1, l1;
                split2(a0, a1, h0, l0);
                split2(a2, a3, h1, l1);
                size_t o0 = (((size_t)(b0 * NH + h) * S_ + s0) << 6) + d;
                size_t o1 = (((size_t)(b1 * NH + h) * S_ + s1) << 6) + d;
                *(uint32_t*)&g_khi[o0] = h0; *(uint32_t*)&g_klo[o0] = l0;
                *(uint32_t*)&g_khi[o1] = h1; *(uint32_t*)&g_klo[o1] = l1;
            } else {
                size_t base0 = ((size_t)(b0 * NH + h) * DK + d) * S_;
                size_t base1 = ((size_t)(b1 * NH + h) * DK + d) * S_;
                #pragma unroll
                for (int e = 0; e < 4; e++) {
                    float x = acc[mt][nt][e];
                    __nv_bfloat16 hh = __float2bfloat16(x);
                    __nv_bfloat16 ll = __float2bfloat16(x - __bfloat162float(hh));
                    size_t o = (e < 2 ? base0 + s0 : base1 + s1) + (size_t)(e & 1) * S_;
                    g_vthi[o] = hh;
                    g_vtlo[o] = ll;
                }
            }
        }
    }
}

// output projection. grid (8, 64), 128 thr
__global__ __launch_bounds__(128, 2) void outproj_mma(float* __restrict__ out) {
    extern __shared__ char smem[];
    int n0 = blockIdx.x * 128;
    int m0 = blockIdx.y * 128;

    float acc[4][8][4] = {};
    gemm_core(g_ctxhi, g_ctxlo, g_wohi, g_wolo, m0, n0, acc, smem);

    int lane = threadIdx.x & 31, wid = threadIdx.x >> 5;
    int wm = wid >> 1, wn = wid & 1;
    int g = lane >> 2, tg = lane & 3;
    #pragma unroll
    for (int mt = 0; mt < 4; mt++) {
        #pragma unroll
        for (int nt = 0; nt < 8; nt++) {
            int r0 = m0 + wm * 64 + mt * 16 + g;
            int c = n0 + wn * 64 + nt * 8 + tg * 2;
            float2 v0 = {acc[mt][nt][0], acc[mt][nt][1]};
            *(float2*)&out[(size_t)r0 * DM + c] = v0;
            float2 v1 = {acc[mt][nt][2], acc[mt][nt][3]};
            *(float2*)&out[(size_t)(r0 + 8) * DM + c] = v1;
        }
    }
}

// ===== tensor-core flash attention: no-max softmax (exp direct, deferred l-reduce) =====
#define KROWB 144
#define AT_KHI 0
#define AT_KLO 9216
#define AT_VTH 18432
#define AT_VTL 27648
#define AT_BUK 36864
#define BUKRS 80
#define ATSTAGE (36864 + 128 * BUKRS)
#define AT_MCL (2 * ATSTAGE)
#define AT_RBH (AT_MCL + 512)
#define AT_DSMEM (AT_RBH + 128)

__global__ __launch_bounds__(128, 2) void attn_mma(const float* __restrict__ rel_bias,
                                                   const float* __restrict__ mask) {
    extern __shared__ char sm[];
    float* rbh = (float*)(sm + AT_RBH);
    uint32_t sb = smem_u32(sm);

    int tid = threadIdx.x, lane = tid & 31, wrp = tid >> 5;
    int g = lane >> 2, tg = lane & 3;
    int q0 = blockIdx.x * 128, h = blockIdx.y, b = blockIdx.z;

    const __nv_bfloat16* khi = g_khi + (size_t)(b * NH + h) * S_ * DK;
    const __nv_bfloat16* klo = g_klo + (size_t)(b * NH + h) * S_ * DK;
    const __nv_bfloat16* vth = g_vthi + (size_t)(b * NH + h) * DK * S_;
    const __nv_bfloat16* vtl = g_vtlo + (size_t)(b * NH + h) * DK * S_;
    const float* maskp = mask + b * S_;
    const unsigned char* bukp = g_bucket + ((size_t)b * S_ + q0) * S_;

    if (tid < 32) rbh[tid] = rel_bias[tid * NH + h];

    auto stage = [&](int i) {
        int k0 = i * 64;
        uint32_t bufo = (i & 1) * ATSTAGE;
        #pragma unroll
        for (int j = 0; j < 4; j++) {
            int idx = tid + j * 128;
            int r = idx >> 3, q = idx & 7;
            uint32_t so = sb + bufo + r * KROWB + q * 16;
            cp16(so + AT_KHI, khi + (size_t)(k0 + r) * DK + q * 8);
            cp16(so + AT_KLO, klo + (size_t)(k0 + r) * DK + q * 8);
            cp16(so + AT_VTH, vth + (size_t)r * S_ + k0 + q * 8);
            cp16(so + AT_VTL, vtl + (size_t)r * S_ + k0 + q * 8);
        }
        #pragma unroll
        for (int j = 0; j < 4; j++) {
            int idx = tid + j * 128;
            int r = idx >> 2, qq = idx & 3;
            cp16(sb + bufo + AT_BUK + r * BUKRS + qq * 16, bukp + (size_t)r * S_ + k0 + qq * 16);
        }
        if (tid < 16) cp16(sb + AT_MCL + (i & 1) * 256 + tid * 16, maskp + k0 + tid * 4);
        CP_COMMIT();
    };

    // Q fragments (hi/lo) in registers for two m16 tiles: rows ra, ra+8, rb, rb+8
    int ra = q0 + wrp * 32 + g;
    int rb = ra + 16;
    const float* qpa = g_q + ((size_t)(b * NH + h) * S_ + ra) * DK;
    const float* qpb = g_q + ((size_t)(b * NH + h) * S_ + rb) * DK;
    uint32_t qh0[4][4], ql0[4][4], qh1[4][4], ql1[4][4];
    #pragma unroll
    for (int kc = 0; kc < 4; kc++) {
        int c = kc * 16 + 2 * tg;
        float2 v;
        v = *(const float2*)&qpa[c];            split2(v.x, v.y, qh0[kc][0], ql0[kc][0]);
        v = *(const float2*)&qpa[8 * DK + c];   split2(v.x, v.y, qh0[kc][1], ql0[kc][1]);
        v = *(const float2*)&qpa[c + 8];        split2(v.x, v.y, qh0[kc][2], ql0[kc][2]);
        v = *(const float2*)&qpa[8 * DK + c + 8]; split2(v.x, v.y, qh0[kc][3], ql0[kc][3]);
        v = *(const float2*)&qpb[c];            split2(v.x, v.y, qh1[kc][0], ql1[kc][0]);
        v = *(const float2*)&qpb[8 * DK + c];   split2(v.x, v.y, qh1[kc][1], ql1[kc][1]);
        v = *(const float2*)&qpb[c + 8];        split2(v.x, v.y, qh1[kc][2], ql1[kc][2]);
        v = *(const float2*)&qpb[8 * DK + c + 8]; split2(v.x, v.y, qh1[kc][3], ql1[kc][3]);
    }

    float o0[8][4] = {}, o1[8][4] = {};
    float la0 = 0.f, la1 = 0.f, lb0 = 0.f, lb1 = 0.f;   // per-thread partial row sums

    stage(0);
    stage(1);

    int rowa = wrp * 32 + g;
    uint32_t koff = (uint32_t)(((lane >> 4) & 1) * 8 + (lane & 7)) * KROWB + ((lane >> 3) & 1) * 16;

    #pragma unroll 1
    for (int i = 0; i < 32; i++) {
        uint32_t bufo = (i & 1) * ATSTAGE;
        if (i < 31) CP_WAIT1(); else CP_WAIT0();
        __syncthreads();
        uint32_t base = sb + bufo;
        const float* mclf = (const float*)(sm + AT_MCL + (i & 1) * 256);
        const char* bkt = sm + bufo + AT_BUK;

        // ---- S = Q @ K^T ----
        float s0[8][4] = {}, s1[8][4] = {};
        #pragma unroll
        for (int kc = 0; kc < 4; kc++) {
            uint32_t ka = kc * 32;
            #pragma unroll
            for (int p = 0; p < 4; p++) {
                uint32_t rh[4], rl[4];
                ldm4(rh, base + AT_KHI + koff + p * 16 * KROWB + ka);
                ldm4(rl, base + AT_KLO + koff + p * 16 * KROWB + ka);
                uint32_t bh0[2] = {rh[0], rh[1]}, bh1[2] = {rh[2], rh[3]};
                uint32_t bl0[2] = {rl[0], rl[1]}, bl1[2] = {rl[2], rl[3]};
                int n0t = 2 * p, n1t = 2 * p + 1;
                mma16816(s0[n0t], qh0[kc], bh0);
                mma16816(s1[n0t], qh1[kc], bh0);
                mma16816(s0[n1t], qh0[kc], bh1);
                mma16816(s1[n1t], qh1[kc], bh1);
                mma16816(s0[n0t], ql0[kc], bh0);
                mma16816(s1[n0t], ql1[kc], bh0);
                mma16816(s0[n1t], ql0[kc], bh1);
                mma16816(s1[n1t], ql1[kc], bh1);
                mma16816(s0[n0t], qh0[kc], bl0);
                mma16816(s1[n0t], qh1[kc], bl0);
                mma16816(s0[n1t], qh0[kc], bl1);
                mma16816(s1[n1t], qh1[kc], bl1);
            }
        }

        // ---- bias + direct exp (no max subtraction) + partial row sums ----
        #pragma unroll
        for (int nt = 0; nt < 8; nt++) {
            int col = nt * 8 + 2 * tg;
            float mv0 = mclf[nt * 8 + 2 * tg], mv1 = mclf[nt * 8 + 2 * tg + 1];
            float mc0 = -1000.0f + 1000.0f * mv0;
            float mc1 = -1000.0f + 1000.0f * mv1;
            uchar2 ua0 = *(const uchar2*)(bkt + (rowa) * BUKRS + col);
            uchar2 ua1 = *(const uchar2*)(bkt + (rowa + 8) * BUKRS + col);
            s0[nt][0] = __expf(s0[nt][0] + rbh[ua0.x] + mc0);
            s0[nt][1] = __expf(s0[nt][1] + rbh[ua0.y] + mc1);
            s0[nt][2] = __expf(s0[nt][2] + rbh[ua1.x] + mc0);
            s0[nt][3] = __expf(s0[nt][3] + rbh[ua1.y] + mc1);
            la0 += s0[nt][0] + s0[nt][1];
            la1 += s0[nt][2] + s0[nt][3];
            uchar2 ub0 = *(const uchar2*)(bkt + (rowa + 16) * BUKRS + col);
            uchar2 ub1 = *(const uchar2*)(bkt + (rowa + 24) * BUKRS + col);
            s1[nt][0] = __expf(s1[nt][0] + rbh[ub0.x] + mc0);
            s1[nt][1] = __expf(s1[nt][1] + rbh[ub0.y] + mc1);
            s1[nt][2] = __expf(s1[nt][2] + rbh[ub1.x] + mc0);
            s1[nt][3] = __expf(s1[nt][3] + rbh[ub1.y] + mc1);
            lb0 += s1[nt][0] + s1[nt][1];
            lb1 += s1[nt][2] + s1[nt][3];
        }

        // ---- O += P @ V ----
        #pragma unroll
        for (int kc = 0; kc < 4; kc++) {
            uint32_t ah0[4], al0[4], ah1[4], al1[4];
            split2(s0[2 * kc][0],     s0[2 * kc][1],     ah0[0], al0[0]);
            split2(s0[2 * kc][2],     s0[2 * kc][3],     ah0[1], al0[1]);
            split2(s0[2 * kc + 1][0], s0[2 * kc + 1][1], ah0[2], al0[2]);
            split2(s0[2 * kc + 1][2], s0[2 * kc + 1][3], ah0[3], al0[3]);
            split2(s1[2 * kc][0],     s1[2 * kc][1],     ah1[0], al1[0]);
            split2(s1[2 * kc][2],     s1[2 * kc][3],     ah1[1], al1[1]);
            split2(s1[2 * kc + 1][0], s1[2 * kc + 1][1], ah1[2], al1[2]);
            split2(s1[2 * kc + 1][2], s1[2 * kc + 1][3], ah1[3], al1[3]);
            uint32_t ka = kc * 32;
            #pragma unroll
            for (int p = 0; p < 4; p++) {
                uint32_t rh[4], rl[4];
                ldm4(rh, base + AT_VTH + koff + p * 16 * KROWB + ka);
                ldm4(rl, base + AT_VTL + koff + p * 16 * KROWB + ka);
                uint32_t vh0[2] = {rh[0], rh[1]}, vh1[2] = {rh[2], rh[3]};
                uint32_t vl0[2] = {rl[0], rl[1]}, vl1[2] = {rl[2], rl[3]};
                int d0 = 2 * p, d1 = 2 * p + 1;
                mma16816(o0[d0], ah0, vh0);
                mma16816(o1[d0], ah1, vh0);
                mma16816(o0[d1], ah0, vh1);
                mma16816(o1[d1], ah1, vh1);
                mma16816(o0[d0], al0, vh0);
                mma16816(o1[d0], al1, vh0);
                mma16816(o0[d1], al0, vh1);
                mma16816(o1[d1], al1, vh1);
                mma16816(o0[d0], ah0, vl0);
                mma16816(o1[d0], ah1, vl0);
                mma16816(o0[d1], ah0, vl1);
                mma16816(o1[d1], ah1, vl1);
            }
        }
        __syncthreads();
        if (i + 2 < 32) stage(i + 2);
    }

    // ---- final l reduction across tg group (once) ----
    la0 += __shfl_xor_sync(0xffffffffu, la0, 1);
    la0 += __shfl_xor_sync(0xffffffffu, la0, 2);
    la1 += __shfl_xor_sync(0xffffffffu, la1, 1);
    la1 += __shfl_xor_sync(0xffffffffu, la1, 2);
    lb0 += __shfl_xor_sync(0xffffffffu, lb0, 1);
    lb0 += __shfl_xor_sync(0xffffffffu, lb0, 2);
    lb1 += __shfl_xor_sync(0xffffffffu, lb1, 1);
    lb1 += __shfl_xor_sync(0xffffffffu, lb1, 2);

    // ---- epilogue ----
    {
        float inv0 = 1.0f / la0, inv1 = 1.0f / la1;
        size_t cb0 = ((size_t)(b * S_ + ra)) * INNER + h * DK;
        size_t cb1 = cb0 + (size_t)8 * INNER;
        #pragma unroll
        for (int dt = 0; dt < 8; dt++) {
            uint32_t hh, ll;
            split2(o0[dt][0] * inv0, o0[dt][1] * inv0, hh, ll);
            *(uint32_t*)&g_ctxhi[cb0 + dt * 8 + 2 * tg] = hh;
            *(uint32_t*)&g_ctxlo[cb0 + dt * 8 + 2 * tg] = ll;
            split2(o0[dt][2] * inv1, o0[dt][3] * inv1, hh, ll);
            *(uint32_t*)&g_ctxhi[cb1 + dt * 8 + 2 * tg] = hh;
            *(uint32_t*)&g_ctxlo[cb1 + dt * 8 + 2 * tg] = ll;
        }
    }
    {
        float inv0 = 1.0f / lb0, inv1 = 1.0f / lb1;
        size_t cb0 = ((size_t)(b * S_ + rb)) * INNER + h * DK;
        size_t cb1 = cb0 + (size_t)8 * INNER;
        #pragma unroll
        for (int dt = 0; dt < 8; dt++) {
            uint32_t hh, ll;
            split2(o1[dt][0] * inv0, o1[dt][1] * inv0, hh, ll);
            *(uint32_t*)&g_ctxhi[cb0 + dt * 8 + 2 * tg] = hh;
            *(uint32_t*)&g_ctxlo[cb0 + dt * 8 + 2 * tg] = ll;
            split2(o1[dt][2] * inv1, o1[dt][3] * inv1, hh, ll);
            *(uint32_t*)&g_ctxhi[cb1 + dt * 8 + 2 * tg] = hh;
            *(uint32_t*)&g_ctxlo[cb1 + dt * 8 + 2 * tg] = ll;
        }
    }
}

// ---------------- launch ----------------
extern "C" void kernel_launch(void* const* d_in, const int* in_sizes, int n_in,
                              void* d_out, int out_size) {
    const float* hidden    = (const float*)d_in[0];
    const int*   positions = (const int*)d_in[1];
    const float* mask      = (const float*)d_in[2];
    const float* wq        = (const float*)d_in[3];
    const float* wk        = (const float*)d_in[4];
    const float* wv        = (const float*)d_in[5];
    const float* wo        = (const float*)d_in[6];
    const float* rel_bias  = (const float*)d_in[7];
    float* out = (float*)d_out;

    cudaFuncSetAttribute(proj_mma, cudaFuncAttributeMaxDynamicSharedMemorySize, GDSMEM);
    cudaFuncSetAttribute(outproj_mma, cudaFuncAttributeMaxDynamicSharedMemorySize, GDSMEM);
    cudaFuncSetAttribute(attn_mma, cudaFuncAttributeMaxDynamicSharedMemorySize, AT_DSMEM);

    lut_kernel<<<1, 256>>>();
    int nb4 = B_ * S_ * S_ / 4;
    bucket_kernel<<<(nb4 + 255) / 256, 256>>>(positions);

    {
        __nv_bfloat16 *hh, *hl, *qh_, *ql_, *kh, *kl, *vh, *vl, *oh, *ol;
        cudaGetSymbolAddress((void**)&hh, g_hidhi);
        cudaGetSymbolAddress((void**)&hl, g_hidlo);
        cudaGetSymbolAddress((void**)&qh_, g_wqhi);
        cudaGetSymbolAddress((void**)&ql_, g_wqlo);
        cudaGetSymbolAddress((void**)&kh, g_wkhi);
        cudaGetSymbolAddress((void**)&kl, g_wklo);
        cudaGetSymbolAddress((void**)&vh, g_wvhi);
        cudaGetSymbolAddress((void**)&vl, g_wvlo);
        cudaGetSymbolAddress((void**)&oh, g_wohi);
        cudaGetSymbolAddress((void**)&ol, g_wolo);
        int nh4 = B_ * S_ * DM / 4;
        presplit_kernel<<<(nh4 + 255) / 256, 256>>>((const float4*)hidden, (uint2*)hh, (uint2*)hl, nh4);
        int nw4 = DM * DM / 4;
        presplit_kernel<<<(nw4 + 255) / 256, 256>>>((const float4*)wq, (uint2*)qh_, (uint2*)ql_, nw4);
        presplit_kernel<<<(nw4 + 255) / 256, 256>>>((const float4*)wk, (uint2*)kh, (uint2*)kl, nw4);
        presplit_kernel<<<(nw4 + 255) / 256, 256>>>((const float4*)wv, (uint2*)vh, (uint2*)vl, nw4);
        presplit_kernel<<<(nw4 + 255) / 256, 256>>>((const float4*)wo, (uint2*)oh, (uint2*)ol, nw4);
    }

    dim3 gproj(24, 64);
    proj_mma<<<gproj, 128, GDSMEM>>>();

    dim3 gattn(S_ / 128, NH, B_);
    attn_mma<<<gattn, 128, AT_DSMEM>>>(rel_bias, mask);

    dim3 gout(8, 64);
    outproj_mma<<<gout, 128, GDSMEM>>>(out);
}